// round 1
// baseline (speedup 1.0000x reference)
#include <cuda_runtime.h>
#include <math.h>

// ---------------------------------------------------------------------------
// UnifiedZipAdapterF: fused SiLU-adapter + l2norm + class prototypes + cosine
// logits + softmax.
//   B=8192, N=100000, C=1000, D=768 (derived at launch from in_sizes/out_size)
// Round 1: fp32 SIMT baseline. Support keys are never materialized: the
// adapter kernel fuses GEMM + silu + residual + row-l2norm + segment-sum
// (global RED atomics into prototype sums).
// ---------------------------------------------------------------------------

#define DD   768
#define BM   32
#define KT   32
#define CMAX 1000

// device scratch (no allocations allowed)
__device__ float g_Wt[DD * DD];        // W transposed to k-major: g_Wt[k*DD+j] = W[j*DD+k]
__device__ float g_proto[CMAX * DD];   // prototype sums -> normalized prototypes
__device__ float g_cnt[CMAX];          // per-class counts

// ---------------------------------------------------------------------------
__global__ void zero_kernel() {
    int i = blockIdx.x * blockDim.x + threadIdx.x;
    if (i < CMAX * DD) g_proto[i] = 0.f;
    if (i < CMAX)      g_cnt[i]  = 0.f;
}

__global__ void count_kernel(const int* __restrict__ lab, int N) {
    int i = blockIdx.x * blockDim.x + threadIdx.x;
    if (i < N) atomicAdd(&g_cnt[lab[i]], 1.0f);
}

// W (DD x DD, row-major) -> g_Wt (k-major)
__global__ void transpose_kernel(const float* __restrict__ W) {
    __shared__ float t[32][33];
    int bx = blockIdx.x * 32, by = blockIdx.y * 32;
    int tx = threadIdx.x, ty = threadIdx.y;
#pragma unroll
    for (int i = 0; i < 32; i += 8)
        t[ty + i][tx] = W[(size_t)(by + ty + i) * DD + bx + tx];
    __syncthreads();
#pragma unroll
    for (int i = 0; i < 32; i += 8)
        g_Wt[(size_t)(bx + ty + i) * DD + by + tx] = t[tx][ty + i];
}

// ---------------------------------------------------------------------------
// adapter kernel: rows = l2norm( silu(X @ W^T + b) + X )
// WRITE_OUT=true : write rows to outRows (embeddings)
// WRITE_OUT=false: atomicAdd rows into g_proto[label]
// Block: 256 threads, BM=32 rows, full 768 cols in registers.
// Thread (rg = tid/64 in 0..3, cg = tid%64): 8 rows x 12 cols accumulators.
// ---------------------------------------------------------------------------
template <bool WRITE_OUT>
__global__ __launch_bounds__(256, 1)
void adapter_kernel(const float* __restrict__ X,
                    const float* __restrict__ bias,
                    const int* __restrict__ labels,
                    float* __restrict__ outRows,
                    int M)
{
    extern __shared__ float sm[];
    float* W_s     = sm;                          // KT * DD
    float* x_s     = W_s + KT * DD;               // BM * (KT+1)
    float* b_s     = x_s + BM * (KT + 1);         // DD
    float* row_sum = b_s + DD;                    // BM

    const int tid  = threadIdx.x;
    const int rg   = tid >> 6;     // 0..3  (8 rows each)
    const int cg   = tid & 63;     // 0..63 (12 cols each)
    const int row0 = blockIdx.x * BM;

    for (int i = tid; i < DD; i += 256) b_s[i] = bias[i];
    if (tid < BM) row_sum[tid] = 0.f;

    float acc[8][12];
#pragma unroll
    for (int i = 0; i < 8; i++)
#pragma unroll
        for (int j = 0; j < 12; j++) acc[i][j] = 0.f;

    for (int kb = 0; kb < DD; kb += KT) {
        __syncthreads();
        // load W tile (k-major): KT x DD
        {
            const float4* Wt4 = reinterpret_cast<const float4*>(g_Wt);
            for (int t = tid; t < KT * (DD / 4); t += 256) {
                int k  = t / (DD / 4);
                int j4 = t % (DD / 4);
                float4 v = Wt4[(size_t)(kb + k) * (DD / 4) + j4];
                float4* dst = reinterpret_cast<float4*>(&W_s[k * DD + j4 * 4]);
                *dst = v;
            }
        }
        // load x tile: BM x KT (padded rows of KT+1)
        {
            int r  = tid >> 3;           // 0..31
            int k4 = (tid & 7) * 4;      // 0..28
            float4 v = *reinterpret_cast<const float4*>(
                &X[(size_t)(row0 + r) * DD + kb + k4]);
            x_s[r * (KT + 1) + k4 + 0] = v.x;
            x_s[r * (KT + 1) + k4 + 1] = v.y;
            x_s[r * (KT + 1) + k4 + 2] = v.z;
            x_s[r * (KT + 1) + k4 + 3] = v.w;
        }
        __syncthreads();

#pragma unroll 4
        for (int k = 0; k < KT; k++) {
            float xv[8];
#pragma unroll
            for (int i = 0; i < 8; i++)
                xv[i] = x_s[(rg * 8 + i) * (KT + 1) + k];
            const float4* wrow =
                reinterpret_cast<const float4*>(&W_s[k * DD + cg * 12]);
            float4 w0 = wrow[0], w1 = wrow[1], w2 = wrow[2];
            float wv[12] = {w0.x, w0.y, w0.z, w0.w,
                            w1.x, w1.y, w1.z, w1.w,
                            w2.x, w2.y, w2.z, w2.w};
#pragma unroll
            for (int i = 0; i < 8; i++)
#pragma unroll
                for (int j = 0; j < 12; j++)
                    acc[i][j] = fmaf(xv[i], wv[j], acc[i][j]);
        }
    }

    // epilogue: bias + silu + residual, partial squared-norm
    float sq[8];
#pragma unroll
    for (int i = 0; i < 8; i++) sq[i] = 0.f;

#pragma unroll
    for (int i = 0; i < 8; i++) {
        int row = row0 + rg * 8 + i;
        const float* xr = &X[(size_t)row * DD + cg * 12];
#pragma unroll
        for (int j = 0; j < 12; j++) {
            float h = acc[i][j] + b_s[cg * 12 + j];
            float s = h / (1.f + expf(-h)) + xr[j];   // silu + residual
            acc[i][j] = s;
            sq[i] += s * s;
        }
    }
    // warp reduce (each warp covers one rg, 32 distinct cg)
#pragma unroll
    for (int off = 16; off; off >>= 1)
#pragma unroll
        for (int i = 0; i < 8; i++)
            sq[i] += __shfl_xor_sync(0xffffffffu, sq[i], off);
    if ((tid & 31) == 0)
#pragma unroll
        for (int i = 0; i < 8; i++)
            atomicAdd(&row_sum[rg * 8 + i], sq[i]);
    __syncthreads();

    float inv[8];
#pragma unroll
    for (int i = 0; i < 8; i++)
        inv[i] = 1.f / fmaxf(sqrtf(row_sum[rg * 8 + i]), 1e-12f);

    if (WRITE_OUT) {
#pragma unroll
        for (int i = 0; i < 8; i++) {
            int row = row0 + rg * 8 + i;
            float* o = &outRows[(size_t)row * DD + cg * 12];
            float4 v;
            v.x = acc[i][0] * inv[i];  v.y = acc[i][1] * inv[i];
            v.z = acc[i][2] * inv[i];  v.w = acc[i][3] * inv[i];
            *reinterpret_cast<float4*>(o + 0) = v;
            v.x = acc[i][4] * inv[i];  v.y = acc[i][5] * inv[i];
            v.z = acc[i][6] * inv[i];  v.w = acc[i][7] * inv[i];
            *reinterpret_cast<float4*>(o + 4) = v;
            v.x = acc[i][8] * inv[i];  v.y = acc[i][9] * inv[i];
            v.z = acc[i][10] * inv[i]; v.w = acc[i][11] * inv[i];
            *reinterpret_cast<float4*>(o + 8) = v;
        }
    } else {
#pragma unroll
        for (int i = 0; i < 8; i++) {
            int row = row0 + rg * 8 + i;
            int lb = labels[row];
            float* p = &g_proto[(size_t)lb * DD + cg * 12];
#pragma unroll
            for (int j = 0; j < 12; j++)
                atomicAdd(&p[j], acc[i][j] * inv[i]);
        }
    }
}

// ---------------------------------------------------------------------------
// normalize prototype sums in place: proto = (cnt>0) ? sums/max(||sums||,eps) : 0
__global__ void proto_norm_kernel(int Cn) {
    int c   = blockIdx.x;
    int tid = threadIdx.x;
    if (c >= Cn) return;
    float* row = &g_proto[(size_t)c * DD];
    float ss = 0.f;
    for (int i = tid; i < DD; i += 256) { float v = row[i]; ss += v * v; }
    __shared__ float red[8];
#pragma unroll
    for (int o = 16; o; o >>= 1) ss += __shfl_xor_sync(0xffffffffu, ss, o);
    if ((tid & 31) == 0) red[tid >> 5] = ss;
    __syncthreads();
    if (tid < 8) {
        ss = red[tid];
#pragma unroll
        for (int o = 4; o; o >>= 1) ss += __shfl_xor_sync(0xffu, ss, o);
        if (tid == 0) red[0] = ss;
    }
    __syncthreads();
    float total = red[0];
    float inv = (g_cnt[c] > 0.f) ? 1.f / fmaxf(sqrtf(total), 1e-12f) : 0.f;
    for (int i = tid; i < DD; i += 256) row[i] *= inv;
}

// ---------------------------------------------------------------------------
// logits = exp(32*(cos - 1)) / tau ;   cos = E (MxD) @ proto^T (CnxD)
// Tiles: BM=64 x BN=64, BK=16, 256 threads, 4x4 micro-tile.
__global__ __launch_bounds__(256)
void cos_logits_kernel(const float* __restrict__ E,
                       float* __restrict__ L, int M, int Cn)
{
    __shared__ float A_s[16][65];
    __shared__ float B_s[16][65];
    const int tid = threadIdx.x;
    const int tm  = tid & 15;      // 0..15
    const int tn  = tid >> 4;      // 0..15
    const int mB  = blockIdx.y * 64;
    const int nB  = blockIdx.x * 64;
    const int lm  = tid >> 2;        // 0..63 tile row for loading
    const int lk  = (tid & 3) * 4;   // 0,4,8,12

    float acc[4][4];
#pragma unroll
    for (int i = 0; i < 4; i++)
#pragma unroll
        for (int j = 0; j < 4; j++) acc[i][j] = 0.f;

    for (int kb = 0; kb < DD; kb += 16) {
        float4 av = *reinterpret_cast<const float4*>(
            &E[(size_t)(mB + lm) * DD + kb + lk]);
        float4 bv = make_float4(0.f, 0.f, 0.f, 0.f);
        if (nB + lm < Cn)
            bv = *reinterpret_cast<const float4*>(
                &g_proto[(size_t)(nB + lm) * DD + kb + lk]);
        __syncthreads();
        A_s[lk + 0][lm] = av.x; A_s[lk + 1][lm] = av.y;
        A_s[lk + 2][lm] = av.z; A_s[lk + 3][lm] = av.w;
        B_s[lk + 0][lm] = bv.x; B_s[lk + 1][lm] = bv.y;
        B_s[lk + 2][lm] = bv.z; B_s[lk + 3][lm] = bv.w;
        __syncthreads();
#pragma unroll
        for (int k = 0; k < 16; k++) {
            float a0 = A_s[k][tm * 4 + 0], a1 = A_s[k][tm * 4 + 1];
            float a2 = A_s[k][tm * 4 + 2], a3 = A_s[k][tm * 4 + 3];
            float b0 = B_s[k][tn * 4 + 0], b1 = B_s[k][tn * 4 + 1];
            float b2 = B_s[k][tn * 4 + 2], b3 = B_s[k][tn * 4 + 3];
            acc[0][0] = fmaf(a0, b0, acc[0][0]); acc[0][1] = fmaf(a0, b1, acc[0][1]);
            acc[0][2] = fmaf(a0, b2, acc[0][2]); acc[0][3] = fmaf(a0, b3, acc[0][3]);
            acc[1][0] = fmaf(a1, b0, acc[1][0]); acc[1][1] = fmaf(a1, b1, acc[1][1]);
            acc[1][2] = fmaf(a1, b2, acc[1][2]); acc[1][3] = fmaf(a1, b3, acc[1][3]);
            acc[2][0] = fmaf(a2, b0, acc[2][0]); acc[2][1] = fmaf(a2, b1, acc[2][1]);
            acc[2][2] = fmaf(a2, b2, acc[2][2]); acc[2][3] = fmaf(a2, b3, acc[2][3]);
            acc[3][0] = fmaf(a3, b0, acc[3][0]); acc[3][1] = fmaf(a3, b1, acc[3][1]);
            acc[3][2] = fmaf(a3, b2, acc[3][2]); acc[3][3] = fmaf(a3, b3, acc[3][3]);
        }
    }

    const float invtau = 1.0f / 0.11f;
#pragma unroll
    for (int i = 0; i < 4; i++) {
        int m = mB + tm * 4 + i;
#pragma unroll
        for (int j = 0; j < 4; j++) {
            int n = nB + tn * 4 + j;
            if (n < Cn)
                L[(size_t)m * Cn + n] = expf(32.f * acc[i][j] - 32.f) * invtau;
        }
    }
}

// ---------------------------------------------------------------------------
__global__ void softmax_kernel(const float* __restrict__ L,
                               float* __restrict__ P, int Cn)
{
    __shared__ float buf[1024];
    __shared__ float red[8];
    int row = blockIdx.x, tid = threadIdx.x;
    const float* lr = L + (size_t)row * Cn;

    float mx = -1e30f;
    for (int i = tid; i < Cn; i += 256) { float v = lr[i]; buf[i] = v; mx = fmaxf(mx, v); }
#pragma unroll
    for (int o = 16; o; o >>= 1) mx = fmaxf(mx, __shfl_xor_sync(0xffffffffu, mx, o));
    if ((tid & 31) == 0) red[tid >> 5] = mx;
    __syncthreads();
    if (tid < 8) {
        mx = red[tid];
#pragma unroll
        for (int o = 4; o; o >>= 1) mx = fmaxf(mx, __shfl_xor_sync(0xffu, mx, o));
        if (tid == 0) red[0] = mx;
    }
    __syncthreads();
    mx = red[0];
    __syncthreads();

    float sm = 0.f;
    for (int i = tid; i < Cn; i += 256) { float e = expf(buf[i] - mx); buf[i] = e; sm += e; }
#pragma unroll
    for (int o = 16; o; o >>= 1) sm += __shfl_xor_sync(0xffffffffu, sm, o);
    if ((tid & 31) == 0) red[tid >> 5] = sm;
    __syncthreads();
    if (tid < 8) {
        sm = red[tid];
#pragma unroll
        for (int o = 4; o; o >>= 1) sm += __shfl_xor_sync(0xffu, sm, o);
        if (tid == 0) red[0] = sm;
    }
    __syncthreads();
    float inv = 1.f / red[0];
    for (int i = tid; i < Cn; i += 256)
        P[(size_t)row * Cn + i] = buf[i] * inv;
}

// ---------------------------------------------------------------------------
extern "C" void kernel_launch(void* const* d_in, const int* in_sizes, int n_in,
                              void* d_out, int out_size)
{
    const float* x   = (const float*)d_in[0];
    const float* sf  = (const float*)d_in[1];
    const int*   lab = (const int*)d_in[2];
    const float* W   = (const float*)d_in[3];
    const float* b   = (const float*)d_in[4];

    const int D = in_sizes[4];               // 768
    const int B = in_sizes[0] / D;           // 8192
    const int N = in_sizes[2];               // 100000
    const long long C =
        ((long long)out_size - (long long)B * D) / (2LL * B);   // 1000
    (void)D; (void)n_in;

    float* predicts = (float*)d_out;
    float* logits   = predicts + (long long)B * C;
    float* emb      = logits + (long long)B * C;

    const int smem_adapter =
        (KT * DD + BM * (KT + 1) + DD + BM) * (int)sizeof(float);
    cudaFuncSetAttribute(adapter_kernel<true>,
                         cudaFuncAttributeMaxDynamicSharedMemorySize, smem_adapter);
    cudaFuncSetAttribute(adapter_kernel<false>,
                         cudaFuncAttributeMaxDynamicSharedMemorySize, smem_adapter);

    zero_kernel<<<(CMAX * DD + 255) / 256, 256>>>();
    transpose_kernel<<<dim3(DD / 32, DD / 32), dim3(32, 8)>>>(W);
    count_kernel<<<(N + 255) / 256, 256>>>(lab, N);

    adapter_kernel<true><<<B / BM, 256, smem_adapter>>>(x, b, nullptr, emb, B);
    adapter_kernel<false><<<N / BM, 256, smem_adapter>>>(sf, b, lab, nullptr, N);

    proto_norm_kernel<<<(int)C, 256>>>((int)C);

    dim3 cgrid(((int)C + 63) / 64, B / 64);
    cos_logits_kernel<<<cgrid, 256>>>(emb, logits, B, (int)C);

    softmax_kernel<<<B, 256>>>(logits, predicts, (int)C);
}

// round 4
// speedup vs baseline: 3.0486x; 3.0486x over previous
#include <cuda_runtime.h>
#include <cuda_bf16.h>
#include <math.h>
#include <stdint.h>

// ---------------------------------------------------------------------------
// UnifiedZipAdapterF round 4: mma.sync (HMMA) bf16 hi/lo-split GEMMs.
// Fix vs R3: B-operand ldmatrix must be NON-trans (B stored [n][k], k-contiguous).
//   H = X @ W^T + b ; U = silu(H) + X ; emb/proto = rownorm(U)
//   logits = exp(32*cos - 32)/tau ; predicts = softmax(logits)
// GEMM terms: Ah*Bh + Ah*Bl + Al*Bh  (fp32 accumulate)
// ---------------------------------------------------------------------------

#define DD        768
#define CMAX      1000
#define NPAD      1024
#define BMAX      8192
#define ROWS_PAD  108288      // 8192 + ceil(100000/128)*128

// ---- static device scratch (no allocations allowed) ----
__device__ __nv_bfloat16 g_Ahi[(size_t)ROWS_PAD * DD];
__device__ __nv_bfloat16 g_Alo[(size_t)ROWS_PAD * DD];
__device__ float         g_U[(size_t)ROWS_PAD * DD];
__device__ float         g_sq[ROWS_PAD];
__device__ __nv_bfloat16 g_Whi[DD * DD];
__device__ __nv_bfloat16 g_Wlo[DD * DD];
__device__ float         g_proto[CMAX * DD];
__device__ float         g_cnt[CMAX];
__device__ __nv_bfloat16 g_Ehi[(size_t)BMAX * DD];
__device__ __nv_bfloat16 g_Elo[(size_t)BMAX * DD];
__device__ __nv_bfloat16 g_Phi[(size_t)NPAD * DD];
__device__ __nv_bfloat16 g_Plo[(size_t)NPAD * DD];

// ---------------------------------------------------------------------------
__device__ __forceinline__ uint32_t s2u(const void* p) {
    uint32_t a;
    asm("{ .reg .u64 t; cvta.to.shared.u64 t, %1; cvt.u32.u64 %0, t; }"
        : "=r"(a) : "l"(p));
    return a;
}
__device__ __forceinline__ uint32_t pack2bf(float a, float b) {
    __nv_bfloat162 t = __floats2bfloat162_rn(a, b);
    return *reinterpret_cast<uint32_t*>(&t);
}
__device__ __forceinline__ void cp16(uint32_t d, const void* s) {
    asm volatile("cp.async.cg.shared.global [%0], [%1], 16;" :: "r"(d), "l"(s));
}

#define LDSM_X4(R0, R1, R2, R3, ADDR)                                          \
    asm volatile("ldmatrix.sync.aligned.m8n8.x4.shared.b16 {%0,%1,%2,%3}, [%4];" \
        : "=r"(R0), "=r"(R1), "=r"(R2), "=r"(R3) : "r"(ADDR))
#define MMA_BF16(D, A, B)                                                      \
    asm volatile("mma.sync.aligned.m16n8k16.row.col.f32.bf16.bf16.f32 "        \
        "{%0,%1,%2,%3}, {%4,%5,%6,%7}, {%8,%9}, {%0,%1,%2,%3};"                \
        : "+f"((D)[0]), "+f"((D)[1]), "+f"((D)[2]), "+f"((D)[3])               \
        : "r"((A)[0]), "r"((A)[1]), "r"((A)[2]), "r"((A)[3]),                  \
          "r"((B)[0]), "r"((B)[1]))

// ---------------------------------------------------------------------------
// prep kernels
// ---------------------------------------------------------------------------
__global__ void zero_kernel() {
    int i = blockIdx.x * blockDim.x + threadIdx.x;
    if (i < CMAX * DD) g_proto[i] = 0.f;
    if (i < NPAD * DD) {
        g_Phi[i] = __nv_bfloat16(0.f);
        g_Plo[i] = __nv_bfloat16(0.f);
    }
    if (i < CMAX)     g_cnt[i] = 0.f;
    if (i < ROWS_PAD) g_sq[i]  = 0.f;
}

__global__ void count_kernel(const int* __restrict__ lab, int N) {
    int i = blockIdx.x * blockDim.x + threadIdx.x;
    if (i < N) atomicAdd(&g_cnt[lab[i]], 1.0f);
}

__global__ void prep_w(const float* __restrict__ W) {
    int i = blockIdx.x * blockDim.x + threadIdx.x;
    if (i < DD * DD) {
        float v = W[i];
        __nv_bfloat16 h = __float2bfloat16(v);
        g_Whi[i] = h;
        g_Wlo[i] = __float2bfloat16(v - __bfloat162float(h));
    }
}

// [x ; sf ; zero-pad] rows -> g_Ahi/g_Alo  (4 floats per thread)
__global__ void prep_x(const float* __restrict__ x, const float* __restrict__ sf,
                       int Brows, int Nrows) {
    size_t i = ((size_t)blockIdx.x * blockDim.x + threadIdx.x) * 4;
    if (i >= (size_t)ROWS_PAD * DD) return;
    size_t r = i / DD;
    float4 v = make_float4(0.f, 0.f, 0.f, 0.f);
    if (r < (size_t)Brows)
        v = *reinterpret_cast<const float4*>(&x[i]);
    else if (r < (size_t)(Brows + Nrows))
        v = *reinterpret_cast<const float4*>(&sf[i - (size_t)Brows * DD]);
    float vv[4] = {v.x, v.y, v.z, v.w};
    uint32_t hi[2], lo[2];
#pragma unroll
    for (int j = 0; j < 2; ++j) {
        float a0 = vv[2 * j], a1 = vv[2 * j + 1];
        __nv_bfloat16 h0 = __float2bfloat16(a0);
        __nv_bfloat16 h1 = __float2bfloat16(a1);
        hi[j] = pack2bf(a0, a1);
        lo[j] = pack2bf(a0 - __bfloat162float(h0), a1 - __bfloat162float(h1));
    }
    *reinterpret_cast<uint2*>(&g_Ahi[i]) = make_uint2(hi[0], hi[1]);
    *reinterpret_cast<uint2*>(&g_Alo[i]) = make_uint2(lo[0], lo[1]);
}

// ---------------------------------------------------------------------------
// GEMM core: 128x128 tile, 8 warps (2x4), warp tile 64x32, BK=64, 2-stage cp.async
// smem per stage: Ahi 16K | Alo 16K | Bhi 16K | Blo 16K  (row = 128B, XOR swizzle)
// ---------------------------------------------------------------------------
#define STAGE_BYTES 65536
#define GEMM_SMEM   (2 * STAGE_BYTES)

__device__ __forceinline__ void fill_stage(
    const __nv_bfloat16* __restrict__ Ah, const __nv_bfloat16* __restrict__ Al,
    const __nv_bfloat16* __restrict__ Bh, const __nv_bfloat16* __restrict__ Bl,
    int arow0, int brow0, int kb, uint32_t sbase, int tid)
{
#pragma unroll
    for (int it = 0; it < 4; ++it) {
        int ch = tid + it * 256;       // 1024 chunks per 16KB tile
        int r = ch >> 3, c = ch & 7;
        uint32_t off = (uint32_t)(r * 128 + ((c ^ (r & 7)) << 4));
        size_t ai = (size_t)(arow0 + r) * DD + kb + c * 8;
        size_t bi = (size_t)(brow0 + r) * DD + kb + c * 8;
        cp16(sbase + off,         Ah + ai);
        cp16(sbase + 16384 + off, Al + ai);
        cp16(sbase + 32768 + off, Bh + bi);
        cp16(sbase + 49152 + off, Bl + bi);
    }
}

__device__ __forceinline__ void compute_stage(uint32_t sb, int wm, int wn, int lane,
                                              float (&acc)[4][4][4])
{
    const uint32_t aH = sb, aL = sb + 16384, bH = sb + 32768, bL = sb + 49152;
    const int t = lane >> 3, li = lane & 7;
#pragma unroll
    for (int kk = 0; kk < 64; kk += 16) {
        uint32_t ah[4][4], al[4][4], bh[4][2], bl[4][2];
#pragma unroll
        for (int mi = 0; mi < 4; ++mi) {
            int r  = wm * 64 + mi * 16 + ((t & 1) << 3) + li;
            int cc = (kk >> 3) + (t >> 1);
            uint32_t off = (uint32_t)(r * 128 + ((cc ^ (r & 7)) << 4));
            LDSM_X4(ah[mi][0], ah[mi][1], ah[mi][2], ah[mi][3], aH + off);
            LDSM_X4(al[mi][0], al[mi][1], al[mi][2], al[mi][3], aL + off);
        }
        // B stored [n][k] (k-contiguous) => NON-trans ldmatrix yields the
        // required col-major fragment (lane l: k = 2*(l%4)+{0,1}, n = l/4).
#pragma unroll
        for (int p = 0; p < 2; ++p) {
            int n  = wn * 32 + p * 16 + ((t >> 1) << 3) + li;
            int cc = (kk >> 3) + (t & 1);
            uint32_t off = (uint32_t)(n * 128 + ((cc ^ (n & 7)) << 4));
            LDSM_X4(bh[2 * p][0], bh[2 * p][1], bh[2 * p + 1][0], bh[2 * p + 1][1], bH + off);
            LDSM_X4(bl[2 * p][0], bl[2 * p][1], bl[2 * p + 1][0], bl[2 * p + 1][1], bL + off);
        }
#pragma unroll
        for (int mi = 0; mi < 4; ++mi)
#pragma unroll
            for (int nj = 0; nj < 4; ++nj) {
                MMA_BF16(acc[mi][nj], ah[mi], bh[nj]);
                MMA_BF16(acc[mi][nj], ah[mi], bl[nj]);
                MMA_BF16(acc[mi][nj], al[mi], bh[nj]);
            }
    }
}

// EPI 0: adapter (bias+silu+residual -> g_U, row-sq -> g_sq)
// EPI 1: cosine logits (exp(32c-32)/tau -> Lout)
template <int EPI>
__global__ __launch_bounds__(256, 1)
void gemm_kernel(const __nv_bfloat16* __restrict__ Ah, const __nv_bfloat16* __restrict__ Al,
                 const __nv_bfloat16* __restrict__ Bh, const __nv_bfloat16* __restrict__ Bl,
                 const float* __restrict__ Xres, const float* __restrict__ bias,
                 float* __restrict__ Lout,
                 int aRowBase0, int rowEnd, int inputBase, int Cn)
{
    extern __shared__ __align__(16) char smem[];
    const int tid  = threadIdx.x;
    const int lane = tid & 31, wid = tid >> 5;
    const int wm = wid >> 2, wn = wid & 3;
    const int nb0   = blockIdx.x * 128;
    const int arow0 = aRowBase0 + blockIdx.y * 128;
    const uint32_t sb = s2u(smem);

    float acc[4][4][4] = {};

    fill_stage(Ah, Al, Bh, Bl, arow0, nb0, 0, sb, tid);
    asm volatile("cp.async.commit_group;");
#pragma unroll 1
    for (int s = 0; s < 12; ++s) {
        if (s + 1 < 12) {
            fill_stage(Ah, Al, Bh, Bl, arow0, nb0, (s + 1) * 64,
                       sb + ((s + 1) & 1) * STAGE_BYTES, tid);
            asm volatile("cp.async.commit_group;");
            asm volatile("cp.async.wait_group 1;");
        } else {
            asm volatile("cp.async.wait_group 0;");
        }
        __syncthreads();
        compute_stage(sb + (s & 1) * STAGE_BYTES, wm, wn, lane, acc);
        __syncthreads();
    }

    // ---- stage accumulators through smem (reuse pipeline buffers) ----
    float* es = reinterpret_cast<float*>(smem);   // [128][132]
#pragma unroll
    for (int mi = 0; mi < 4; ++mi)
#pragma unroll
        for (int nj = 0; nj < 4; ++nj) {
            int r0 = wm * 64 + mi * 16 + (lane >> 2);
            int c0 = wn * 32 + nj * 8 + (lane & 3) * 2;
            es[r0 * 132 + c0]           = acc[mi][nj][0];
            es[r0 * 132 + c0 + 1]       = acc[mi][nj][1];
            es[(r0 + 8) * 132 + c0]     = acc[mi][nj][2];
            es[(r0 + 8) * 132 + c0 + 1] = acc[mi][nj][3];
        }
    __syncthreads();

    const int row  = tid >> 1;
    const int half = tid & 1;
    const int arow = arow0 + row;
    const bool valid = (arow < rowEnd);
    const float* er = es + row * 132 + half * 64;

    if (EPI == 0) {
        float sq = 0.f;
        if (valid) {
            const float* xr = Xres + (size_t)(arow - inputBase) * DD + nb0 + half * 64;
            float*       ur = g_U  + (size_t)arow * DD + nb0 + half * 64;
            const float* br = bias + nb0 + half * 64;
#pragma unroll
            for (int j = 0; j < 64; j += 4) {
                float4 v  = *reinterpret_cast<const float4*>(er + j);
                float4 bb = *reinterpret_cast<const float4*>(br + j);
                float4 xv = *reinterpret_cast<const float4*>(xr + j);
                float h0 = v.x + bb.x, h1 = v.y + bb.y;
                float h2 = v.z + bb.z, h3 = v.w + bb.w;
                float4 o;
                o.x = h0 / (1.f + expf(-h0)) + xv.x;
                o.y = h1 / (1.f + expf(-h1)) + xv.y;
                o.z = h2 / (1.f + expf(-h2)) + xv.z;
                o.w = h3 / (1.f + expf(-h3)) + xv.w;
                sq += o.x * o.x + o.y * o.y + o.z * o.z + o.w * o.w;
                *reinterpret_cast<float4*>(ur + j) = o;
            }
        }
        float tot = sq + __shfl_xor_sync(0xffffffffu, sq, 1);
        if (valid && half == 0) atomicAdd(&g_sq[arow], tot);
    } else {
        if (valid) {
            const float invtau = 1.0f / 0.11f;
            float* lr = Lout + (size_t)arow * Cn + nb0 + half * 64;
            int cbase = nb0 + half * 64;
            if (cbase + 64 <= Cn) {
#pragma unroll
                for (int j = 0; j < 64; j += 4) {
                    float4 v = *reinterpret_cast<const float4*>(er + j);
                    float4 o;
                    o.x = expf(32.f * v.x - 32.f) * invtau;
                    o.y = expf(32.f * v.y - 32.f) * invtau;
                    o.z = expf(32.f * v.z - 32.f) * invtau;
                    o.w = expf(32.f * v.w - 32.f) * invtau;
                    *reinterpret_cast<float4*>(lr + j) = o;
                }
            } else {
                for (int j = 0; j < 64; ++j) {
                    int c = cbase + j;
                    if (c < Cn) lr[j] = expf(32.f * er[j] - 32.f) * invtau;
                }
            }
        }
    }
}

// ---------------------------------------------------------------------------
// normalize rows 0..B-1 of g_U -> emb (fp32) + g_Ehi/g_Elo (bf16 hi/lo)
__global__ __launch_bounds__(256)
void norm_emb(float* __restrict__ emb, int M) {
    int row  = blockIdx.x * 8 + (threadIdx.x >> 5);
    int lane = threadIdx.x & 31;
    if (row >= M) return;
    float inv = 1.f / fmaxf(sqrtf(g_sq[row]), 1e-12f);
    const float4* u = reinterpret_cast<const float4*>(&g_U[(size_t)row * DD]);
    float4* o  = reinterpret_cast<float4*>(&emb[(size_t)row * DD]);
    uint2*  eh = reinterpret_cast<uint2*>(&g_Ehi[(size_t)row * DD]);
    uint2*  el = reinterpret_cast<uint2*>(&g_Elo[(size_t)row * DD]);
    for (int i = lane; i < DD / 4; i += 32) {
        float4 v = u[i];
        v.x *= inv; v.y *= inv; v.z *= inv; v.w *= inv;
        o[i] = v;
        __nv_bfloat16 h0 = __float2bfloat16(v.x), h1 = __float2bfloat16(v.y);
        __nv_bfloat16 h2 = __float2bfloat16(v.z), h3 = __float2bfloat16(v.w);
        eh[i] = make_uint2(pack2bf(v.x, v.y), pack2bf(v.z, v.w));
        el[i] = make_uint2(
            pack2bf(v.x - __bfloat162float(h0), v.y - __bfloat162float(h1)),
            pack2bf(v.z - __bfloat162float(h2), v.w - __bfloat162float(h3)));
    }
}

// normalize rows B..B+N-1 of g_U, scatter-add into g_proto[label] (vector red)
__global__ __launch_bounds__(256)
void norm_proto(const int* __restrict__ lab, int Brows, int N) {
    int row  = blockIdx.x * 8 + (threadIdx.x >> 5);
    int lane = threadIdx.x & 31;
    if (row >= N) return;
    int grow = Brows + row;
    float inv = 1.f / fmaxf(sqrtf(g_sq[grow]), 1e-12f);
    int lb = lab[row];
    const float4* u = reinterpret_cast<const float4*>(&g_U[(size_t)grow * DD]);
    float* dst = &g_proto[(size_t)lb * DD];
    for (int i = lane; i < DD / 4; i += 32) {
        float4 v = u[i];
        asm volatile("red.global.add.v4.f32 [%0], {%1,%2,%3,%4};"
                     :: "l"(dst + i * 4), "f"(v.x * inv), "f"(v.y * inv),
                        "f"(v.z * inv), "f"(v.w * inv) : "memory");
    }
}

// prototype sums -> normalized bf16 hi/lo (rows >= Cn remain zero)
__global__ void proto_norm_kernel(int Cn) {
    int c   = blockIdx.x;
    int tid = threadIdx.x;
    if (c >= Cn) return;
    const float* row = &g_proto[(size_t)c * DD];
    float ss = 0.f;
    for (int i = tid; i < DD; i += 256) { float v = row[i]; ss += v * v; }
    __shared__ float red[8];
#pragma unroll
    for (int o = 16; o; o >>= 1) ss += __shfl_xor_sync(0xffffffffu, ss, o);
    if ((tid & 31) == 0) red[tid >> 5] = ss;
    __syncthreads();
    if (tid < 8) {
        ss = red[tid];
#pragma unroll
        for (int o = 4; o; o >>= 1) ss += __shfl_xor_sync(0xffu, ss, o);
        if (tid == 0) red[0] = ss;
    }
    __syncthreads();
    float inv = (g_cnt[c] > 0.f) ? 1.f / fmaxf(sqrtf(red[0]), 1e-12f) : 0.f;
    for (int i = tid; i < DD; i += 256) {
        float v = row[i] * inv;
        __nv_bfloat16 h = __float2bfloat16(v);
        g_Phi[(size_t)c * DD + i] = h;
        g_Plo[(size_t)c * DD + i] = __float2bfloat16(v - __bfloat162float(h));
    }
}

// ---------------------------------------------------------------------------
__global__ void softmax_kernel(const float* __restrict__ L,
                               float* __restrict__ P, int Cn)
{
    __shared__ float buf[1024];
    __shared__ float red[8];
    int row = blockIdx.x, tid = threadIdx.x;
    const float* lr = L + (size_t)row * Cn;

    float mx = -1e30f;
    for (int i = tid; i < Cn; i += 256) { float v = lr[i]; buf[i] = v; mx = fmaxf(mx, v); }
#pragma unroll
    for (int o = 16; o; o >>= 1) mx = fmaxf(mx, __shfl_xor_sync(0xffffffffu, mx, o));
    if ((tid & 31) == 0) red[tid >> 5] = mx;
    __syncthreads();
    if (tid < 8) {
        mx = red[tid];
#pragma unroll
        for (int o = 4; o; o >>= 1) mx = fmaxf(mx, __shfl_xor_sync(0xffu, mx, o));
        if (tid == 0) red[0] = mx;
    }
    __syncthreads();
    mx = red[0];
    __syncthreads();

    float sm = 0.f;
    for (int i = tid; i < Cn; i += 256) { float e = expf(buf[i] - mx); buf[i] = e; sm += e; }
#pragma unroll
    for (int o = 16; o; o >>= 1) sm += __shfl_xor_sync(0xffffffffu, sm, o);
    if ((tid & 31) == 0) red[tid >> 5] = sm;
    __syncthreads();
    if (tid < 8) {
        sm = red[tid];
#pragma unroll
        for (int o = 4; o; o >>= 1) sm += __shfl_xor_sync(0xffu, sm, o);
        if (tid == 0) red[0] = sm;
    }
    __syncthreads();
    float inv = 1.f / red[0];
    for (int i = tid; i < Cn; i += 256)
        P[(size_t)row * Cn + i] = buf[i] * inv;
}

// ---------------------------------------------------------------------------
extern "C" void kernel_launch(void* const* d_in, const int* in_sizes, int n_in,
                              void* d_out, int out_size)
{
    const float* x   = (const float*)d_in[0];
    const float* sf  = (const float*)d_in[1];
    const int*   lab = (const int*)d_in[2];
    const float* W   = (const float*)d_in[3];
    const float* b   = (const float*)d_in[4];
    (void)n_in;

    const int D = in_sizes[4];               // 768
    const int B = in_sizes[0] / D;           // 8192
    const int N = in_sizes[2];               // 100000
    const long long C =
        ((long long)out_size - (long long)B * D) / (2LL * B);   // 1000

    float* predicts = (float*)d_out;
    float* logits   = predicts + (long long)B * C;
    float* emb      = logits + (long long)B * C;

    static __nv_bfloat16 *pAhi = nullptr, *pAlo = nullptr, *pWhi = nullptr, *pWlo = nullptr;
    static __nv_bfloat16 *pEhi = nullptr, *pElo = nullptr, *pPhi = nullptr, *pPlo = nullptr;
    static bool init = false;
    if (!init) {
        cudaGetSymbolAddress((void**)&pAhi, g_Ahi);
        cudaGetSymbolAddress((void**)&pAlo, g_Alo);
        cudaGetSymbolAddress((void**)&pWhi, g_Whi);
        cudaGetSymbolAddress((void**)&pWlo, g_Wlo);
        cudaGetSymbolAddress((void**)&pEhi, g_Ehi);
        cudaGetSymbolAddress((void**)&pElo, g_Elo);
        cudaGetSymbolAddress((void**)&pPhi, g_Phi);
        cudaGetSymbolAddress((void**)&pPlo, g_Plo);
        cudaFuncSetAttribute(gemm_kernel<0>,
                             cudaFuncAttributeMaxDynamicSharedMemorySize, GEMM_SMEM);
        cudaFuncSetAttribute(gemm_kernel<1>,
                             cudaFuncAttributeMaxDynamicSharedMemorySize, GEMM_SMEM);
        init = true;
    }

    zero_kernel<<<(NPAD * DD + 255) / 256, 256>>>();
    prep_w<<<(DD * DD + 255) / 256, 256>>>(W);
    {
        size_t tot = ((size_t)ROWS_PAD * DD) / 4;
        prep_x<<<(int)((tot + 255) / 256), 256>>>(x, sf, B, N);
    }
    count_kernel<<<(N + 255) / 256, 256>>>(lab, N);

    // adapter GEMM over x rows (0..B-1)
    {
        dim3 g(DD / 128, B / 128);
        gemm_kernel<0><<<g, 256, GEMM_SMEM>>>(pAhi, pAlo, pWhi, pWlo,
                                              x, b, nullptr, 0, B, 0, DD);
    }
    // adapter GEMM over support rows (B..B+N-1)
    {
        dim3 g(DD / 128, (N + 127) / 128);
        gemm_kernel<0><<<g, 256, GEMM_SMEM>>>(pAhi, pAlo, pWhi, pWlo,
                                              sf, b, nullptr, B, B + N, B, DD);
    }

    norm_emb<<<(B + 7) / 8, 256>>>(emb, B);
    norm_proto<<<(N + 7) / 8, 256>>>(lab, B, N);
    proto_norm_kernel<<<(int)C, 256>>>((int)C);

    // cosine logits GEMM: emb (hi/lo) x proto (hi/lo)
    {
        dim3 g(NPAD / 128, B / 128);
        gemm_kernel<1><<<g, 256, GEMM_SMEM>>>(pEhi, pElo, pPhi, pPlo,
                                              nullptr, nullptr, logits,
                                              0, B, 0, (int)C);
    }

    softmax_kernel<<<B, 256>>>(logits, predicts, (int)C);
}

// round 5
// speedup vs baseline: 3.6088x; 1.1838x over previous
#include <cuda_runtime.h>
#include <cuda_bf16.h>
#include <math.h>
#include <stdint.h>

// ---------------------------------------------------------------------------
// UnifiedZipAdapterF round 5: HMMA bf16 hi/lo-split GEMMs.
// vs R4: support adapter GEMM uses 2-term split Ah*(Bh+Bl) (row-specific
// truncation error averages out in class-mean prototypes), 3-stage cp.async
// pipeline for the 2-term path, and prep skips Alo for support rows.
//   H = X @ W^T + b ; U = silu(H) + X ; emb/proto = rownorm(U)
//   logits = exp(32*cos - 32)/tau ; predicts = softmax(logits)
// ---------------------------------------------------------------------------

#define DD        768
#define CMAX      1000
#define NPAD      1024
#define BMAX      8192
#define ROWS_PAD  108288      // 8192 + ceil(100000/128)*128

// ---- static device scratch (no allocations allowed) ----
__device__ __nv_bfloat16 g_Ahi[(size_t)ROWS_PAD * DD];
__device__ __nv_bfloat16 g_Alo[(size_t)BMAX * DD];      // only emb rows need lo
__device__ float         g_U[(size_t)ROWS_PAD * DD];
__device__ float         g_sq[ROWS_PAD];
__device__ __nv_bfloat16 g_Whi[DD * DD];
__device__ __nv_bfloat16 g_Wlo[DD * DD];
__device__ float         g_proto[CMAX * DD];
__device__ float         g_cnt[CMAX];
__device__ __nv_bfloat16 g_Ehi[(size_t)BMAX * DD];
__device__ __nv_bfloat16 g_Elo[(size_t)BMAX * DD];
__device__ __nv_bfloat16 g_Phi[(size_t)NPAD * DD];
__device__ __nv_bfloat16 g_Plo[(size_t)NPAD * DD];

// ---------------------------------------------------------------------------
__device__ __forceinline__ uint32_t s2u(const void* p) {
    uint32_t a;
    asm("{ .reg .u64 t; cvta.to.shared.u64 t, %1; cvt.u32.u64 %0, t; }"
        : "=r"(a) : "l"(p));
    return a;
}
__device__ __forceinline__ uint32_t pack2bf(float a, float b) {
    __nv_bfloat162 t = __floats2bfloat162_rn(a, b);
    return *reinterpret_cast<uint32_t*>(&t);
}
__device__ __forceinline__ void cp16(uint32_t d, const void* s) {
    asm volatile("cp.async.cg.shared.global [%0], [%1], 16;" :: "r"(d), "l"(s));
}

#define LDSM_X4(R0, R1, R2, R3, ADDR)                                          \
    asm volatile("ldmatrix.sync.aligned.m8n8.x4.shared.b16 {%0,%1,%2,%3}, [%4];" \
        : "=r"(R0), "=r"(R1), "=r"(R2), "=r"(R3) : "r"(ADDR))
#define MMA_BF16(D, A, B)                                                      \
    asm volatile("mma.sync.aligned.m16n8k16.row.col.f32.bf16.bf16.f32 "        \
        "{%0,%1,%2,%3}, {%4,%5,%6,%7}, {%8,%9}, {%0,%1,%2,%3};"                \
        : "+f"((D)[0]), "+f"((D)[1]), "+f"((D)[2]), "+f"((D)[3])               \
        : "r"((A)[0]), "r"((A)[1]), "r"((A)[2]), "r"((A)[3]),                  \
          "r"((B)[0]), "r"((B)[1]))

// ---------------------------------------------------------------------------
// prep kernels
// ---------------------------------------------------------------------------
__global__ void zero_kernel() {
    int i = blockIdx.x * blockDim.x + threadIdx.x;
    if (i < CMAX * DD) g_proto[i] = 0.f;
    if (i < NPAD * DD) {
        g_Phi[i] = __nv_bfloat16(0.f);
        g_Plo[i] = __nv_bfloat16(0.f);
    }
    if (i < CMAX)     g_cnt[i] = 0.f;
    if (i < ROWS_PAD) g_sq[i]  = 0.f;
}

__global__ void count_kernel(const int* __restrict__ lab, int N) {
    int i = blockIdx.x * blockDim.x + threadIdx.x;
    if (i < N) atomicAdd(&g_cnt[lab[i]], 1.0f);
}

__global__ void prep_w(const float* __restrict__ W) {
    int i = blockIdx.x * blockDim.x + threadIdx.x;
    if (i < DD * DD) {
        float v = W[i];
        __nv_bfloat16 h = __float2bfloat16(v);
        g_Whi[i] = h;
        g_Wlo[i] = __float2bfloat16(v - __bfloat162float(h));
    }
}

// [x ; sf ; zero-pad] rows -> g_Ahi (all) / g_Alo (emb rows only)
__global__ void prep_x(const float* __restrict__ x, const float* __restrict__ sf,
                       int Brows, int Nrows) {
    size_t i = ((size_t)blockIdx.x * blockDim.x + threadIdx.x) * 4;
    if (i >= (size_t)ROWS_PAD * DD) return;
    size_t r = i / DD;
    float4 v = make_float4(0.f, 0.f, 0.f, 0.f);
    if (r < (size_t)Brows)
        v = *reinterpret_cast<const float4*>(&x[i]);
    else if (r < (size_t)(Brows + Nrows))
        v = *reinterpret_cast<const float4*>(&sf[i - (size_t)Brows * DD]);
    float vv[4] = {v.x, v.y, v.z, v.w};
    uint32_t hi[2], lo[2];
#pragma unroll
    for (int j = 0; j < 2; ++j) {
        float a0 = vv[2 * j], a1 = vv[2 * j + 1];
        __nv_bfloat16 h0 = __float2bfloat16(a0);
        __nv_bfloat16 h1 = __float2bfloat16(a1);
        hi[j] = pack2bf(a0, a1);
        lo[j] = pack2bf(a0 - __bfloat162float(h0), a1 - __bfloat162float(h1));
    }
    *reinterpret_cast<uint2*>(&g_Ahi[i]) = make_uint2(hi[0], hi[1]);
    if (r < (size_t)Brows)
        *reinterpret_cast<uint2*>(&g_Alo[i]) = make_uint2(lo[0], lo[1]);
}

// ---------------------------------------------------------------------------
// GEMM core: 128x128 tile, 8 warps (2x4), warp tile 64x32, BK=64.
// TERMS==3: Ah*Bh + Ah*Bl + Al*Bh, 2-stage pipeline (stage 64KB).
// TERMS==2: Ah*Bh + Ah*Bl,         3-stage pipeline (stage 48KB).
// smem stage: Ahi 16K | [Alo 16K] | Bhi 16K | Blo 16K (row=128B, XOR swizzle)
// ---------------------------------------------------------------------------
template <int TERMS>
struct Cfg {
    static const int A_SZ  = (TERMS == 3) ? 32768 : 16384;
    static const int STAGE = A_SZ + 32768;
    static const int NS    = (TERMS == 3) ? 2 : 3;
    static const int SMEM  = NS * STAGE;
};

template <int TERMS>
__device__ __forceinline__ void fill_stage(
    const __nv_bfloat16* __restrict__ Ah, const __nv_bfloat16* __restrict__ Al,
    const __nv_bfloat16* __restrict__ Bh, const __nv_bfloat16* __restrict__ Bl,
    int arow0, int brow0, int kb, uint32_t sbase, int tid)
{
    const int A_SZ = Cfg<TERMS>::A_SZ;
#pragma unroll
    for (int it = 0; it < 4; ++it) {
        int ch = tid + it * 256;       // 1024 chunks per 16KB tile
        int r = ch >> 3, c = ch & 7;
        uint32_t off = (uint32_t)(r * 128 + ((c ^ (r & 7)) << 4));
        size_t ai = (size_t)(arow0 + r) * DD + kb + c * 8;
        size_t bi = (size_t)(brow0 + r) * DD + kb + c * 8;
        cp16(sbase + off, Ah + ai);
        if (TERMS == 3) cp16(sbase + 16384 + off, Al + ai);
        cp16(sbase + A_SZ + off,         Bh + bi);
        cp16(sbase + A_SZ + 16384 + off, Bl + bi);
    }
}

template <int TERMS>
__device__ __forceinline__ void compute_stage(uint32_t sb, int wm, int wn, int lane,
                                              float (&acc)[4][4][4])
{
    const uint32_t aH = sb, aL = sb + 16384;
    const uint32_t bH = sb + Cfg<TERMS>::A_SZ, bL = bH + 16384;
    const int t = lane >> 3, li = lane & 7;
#pragma unroll
    for (int kk = 0; kk < 64; kk += 16) {
        uint32_t ah[4][4], al[4][4], bh[4][2], bl[4][2];
#pragma unroll
        for (int mi = 0; mi < 4; ++mi) {
            int r  = wm * 64 + mi * 16 + ((t & 1) << 3) + li;
            int cc = (kk >> 3) + (t >> 1);
            uint32_t off = (uint32_t)(r * 128 + ((cc ^ (r & 7)) << 4));
            LDSM_X4(ah[mi][0], ah[mi][1], ah[mi][2], ah[mi][3], aH + off);
            if (TERMS == 3)
                LDSM_X4(al[mi][0], al[mi][1], al[mi][2], al[mi][3], aL + off);
        }
        // B stored [n][k] (k-contiguous) => NON-trans ldmatrix gives the
        // col-major fragment (lane l: k = 2*(l%4)+{0,1}, n = l/4).
#pragma unroll
        for (int p = 0; p < 2; ++p) {
            int n  = wn * 32 + p * 16 + ((t >> 1) << 3) + li;
            int cc = (kk >> 3) + (t & 1);
            uint32_t off = (uint32_t)(n * 128 + ((cc ^ (n & 7)) << 4));
            LDSM_X4(bh[2 * p][0], bh[2 * p][1], bh[2 * p + 1][0], bh[2 * p + 1][1], bH + off);
            LDSM_X4(bl[2 * p][0], bl[2 * p][1], bl[2 * p + 1][0], bl[2 * p + 1][1], bL + off);
        }
#pragma unroll
        for (int mi = 0; mi < 4; ++mi)
#pragma unroll
            for (int nj = 0; nj < 4; ++nj) {
                MMA_BF16(acc[mi][nj], ah[mi], bh[nj]);
                MMA_BF16(acc[mi][nj], ah[mi], bl[nj]);
                if (TERMS == 3) MMA_BF16(acc[mi][nj], al[mi], bh[nj]);
            }
    }
}

// EPI 0: adapter (bias+silu+residual -> g_U, row-sq -> g_sq)
// EPI 1: cosine logits (exp(32c-32)/tau -> Lout)
template <int EPI, int TERMS>
__global__ __launch_bounds__(256, 1)
void gemm_kernel(const __nv_bfloat16* __restrict__ Ah, const __nv_bfloat16* __restrict__ Al,
                 const __nv_bfloat16* __restrict__ Bh, const __nv_bfloat16* __restrict__ Bl,
                 const float* __restrict__ Xres, const float* __restrict__ bias,
                 float* __restrict__ Lout,
                 int aRowBase0, int rowEnd, int inputBase, int Cn)
{
    const int NS    = Cfg<TERMS>::NS;
    const int STAGE = Cfg<TERMS>::STAGE;
    extern __shared__ __align__(16) char smem[];
    const int tid  = threadIdx.x;
    const int lane = tid & 31, wid = tid >> 5;
    const int wm = wid >> 2, wn = wid & 3;
    const int nb0   = blockIdx.x * 128;
    const int arow0 = aRowBase0 + blockIdx.y * 128;
    const uint32_t sb = s2u(smem);

    float acc[4][4][4] = {};

#pragma unroll
    for (int s = 0; s < NS - 1; ++s) {
        fill_stage<TERMS>(Ah, Al, Bh, Bl, arow0, nb0, s * 64, sb + s * STAGE, tid);
        asm volatile("cp.async.commit_group;");
    }
#pragma unroll 1
    for (int s = 0; s < 12; ++s) {
        if (s + NS - 1 < 12) {
            fill_stage<TERMS>(Ah, Al, Bh, Bl, arow0, nb0, (s + NS - 1) * 64,
                              sb + ((s + NS - 1) % NS) * STAGE, tid);
            asm volatile("cp.async.commit_group;");
            asm volatile("cp.async.wait_group %0;" :: "n"(NS - 1));
        } else {
            asm volatile("cp.async.wait_group 0;");
        }
        __syncthreads();
        compute_stage<TERMS>(sb + (s % NS) * STAGE, wm, wn, lane, acc);
        __syncthreads();
    }

    // ---- stage accumulators through smem (reuse pipeline buffers) ----
    float* es = reinterpret_cast<float*>(smem);   // [128][132]
#pragma unroll
    for (int mi = 0; mi < 4; ++mi)
#pragma unroll
        for (int nj = 0; nj < 4; ++nj) {
            int r0 = wm * 64 + mi * 16 + (lane >> 2);
            int c0 = wn * 32 + nj * 8 + (lane & 3) * 2;
            es[r0 * 132 + c0]           = acc[mi][nj][0];
            es[r0 * 132 + c0 + 1]       = acc[mi][nj][1];
            es[(r0 + 8) * 132 + c0]     = acc[mi][nj][2];
            es[(r0 + 8) * 132 + c0 + 1] = acc[mi][nj][3];
        }
    __syncthreads();

    const int row  = tid >> 1;
    const int half = tid & 1;
    const int arow = arow0 + row;
    const bool valid = (arow < rowEnd);
    const float* er = es + row * 132 + half * 64;

    if (EPI == 0) {
        float sq = 0.f;
        if (valid) {
            const float* xr = Xres + (size_t)(arow - inputBase) * DD + nb0 + half * 64;
            float*       ur = g_U  + (size_t)arow * DD + nb0 + half * 64;
            const float* br = bias + nb0 + half * 64;
#pragma unroll
            for (int j = 0; j < 64; j += 4) {
                float4 v  = *reinterpret_cast<const float4*>(er + j);
                float4 bb = *reinterpret_cast<const float4*>(br + j);
                float4 xv = *reinterpret_cast<const float4*>(xr + j);
                float h0 = v.x + bb.x, h1 = v.y + bb.y;
                float h2 = v.z + bb.z, h3 = v.w + bb.w;
                float4 o;
                o.x = h0 / (1.f + expf(-h0)) + xv.x;
                o.y = h1 / (1.f + expf(-h1)) + xv.y;
                o.z = h2 / (1.f + expf(-h2)) + xv.z;
                o.w = h3 / (1.f + expf(-h3)) + xv.w;
                sq += o.x * o.x + o.y * o.y + o.z * o.z + o.w * o.w;
                *reinterpret_cast<float4*>(ur + j) = o;
            }
        }
        float tot = sq + __shfl_xor_sync(0xffffffffu, sq, 1);
        if (valid && half == 0) atomicAdd(&g_sq[arow], tot);
    } else {
        if (valid) {
            const float invtau = 1.0f / 0.11f;
            float* lr = Lout + (size_t)arow * Cn + nb0 + half * 64;
            int cbase = nb0 + half * 64;
            if (cbase + 64 <= Cn) {
#pragma unroll
                for (int j = 0; j < 64; j += 4) {
                    float4 v = *reinterpret_cast<const float4*>(er + j);
                    float4 o;
                    o.x = expf(32.f * v.x - 32.f) * invtau;
                    o.y = expf(32.f * v.y - 32.f) * invtau;
                    o.z = expf(32.f * v.z - 32.f) * invtau;
                    o.w = expf(32.f * v.w - 32.f) * invtau;
                    *reinterpret_cast<float4*>(lr + j) = o;
                }
            } else {
                for (int j = 0; j < 64; ++j) {
                    int c = cbase + j;
                    if (c < Cn) lr[j] = expf(32.f * er[j] - 32.f) * invtau;
                }
            }
        }
    }
}

// ---------------------------------------------------------------------------
// normalize rows 0..B-1 of g_U -> emb (fp32) + g_Ehi/g_Elo (bf16 hi/lo)
__global__ __launch_bounds__(256)
void norm_emb(float* __restrict__ emb, int M) {
    int row  = blockIdx.x * 8 + (threadIdx.x >> 5);
    int lane = threadIdx.x & 31;
    if (row >= M) return;
    float inv = 1.f / fmaxf(sqrtf(g_sq[row]), 1e-12f);
    const float4* u = reinterpret_cast<const float4*>(&g_U[(size_t)row * DD]);
    float4* o  = reinterpret_cast<float4*>(&emb[(size_t)row * DD]);
    uint2*  eh = reinterpret_cast<uint2*>(&g_Ehi[(size_t)row * DD]);
    uint2*  el = reinterpret_cast<uint2*>(&g_Elo[(size_t)row * DD]);
    for (int i = lane; i < DD / 4; i += 32) {
        float4 v = u[i];
        v.x *= inv; v.y *= inv; v.z *= inv; v.w *= inv;
        o[i] = v;
        __nv_bfloat16 h0 = __float2bfloat16(v.x), h1 = __float2bfloat16(v.y);
        __nv_bfloat16 h2 = __float2bfloat16(v.z), h3 = __float2bfloat16(v.w);
        eh[i] = make_uint2(pack2bf(v.x, v.y), pack2bf(v.z, v.w));
        el[i] = make_uint2(
            pack2bf(v.x - __bfloat162float(h0), v.y - __bfloat162float(h1)),
            pack2bf(v.z - __bfloat162float(h2), v.w - __bfloat162float(h3)));
    }
}

// normalize rows B..B+N-1 of g_U, scatter-add into g_proto[label] (vector red)
__global__ __launch_bounds__(256)
void norm_proto(const int* __restrict__ lab, int Brows, int N) {
    int row  = blockIdx.x * 8 + (threadIdx.x >> 5);
    int lane = threadIdx.x & 31;
    if (row >= N) return;
    int grow = Brows + row;
    float inv = 1.f / fmaxf(sqrtf(g_sq[grow]), 1e-12f);
    int lb = lab[row];
    const float4* u = reinterpret_cast<const float4*>(&g_U[(size_t)grow * DD]);
    float* dst = &g_proto[(size_t)lb * DD];
    for (int i = lane; i < DD / 4; i += 32) {
        float4 v = u[i];
        asm volatile("red.global.add.v4.f32 [%0], {%1,%2,%3,%4};"
                     :: "l"(dst + i * 4), "f"(v.x * inv), "f"(v.y * inv),
                        "f"(v.z * inv), "f"(v.w * inv) : "memory");
    }
}

// prototype sums -> normalized bf16 hi/lo (rows >= Cn remain zero)
__global__ void proto_norm_kernel(int Cn) {
    int c   = blockIdx.x;
    int tid = threadIdx.x;
    if (c >= Cn) return;
    const float* row = &g_proto[(size_t)c * DD];
    float ss = 0.f;
    for (int i = tid; i < DD; i += 256) { float v = row[i]; ss += v * v; }
    __shared__ float red[8];
#pragma unroll
    for (int o = 16; o; o >>= 1) ss += __shfl_xor_sync(0xffffffffu, ss, o);
    if ((tid & 31) == 0) red[tid >> 5] = ss;
    __syncthreads();
    if (tid < 8) {
        ss = red[tid];
#pragma unroll
        for (int o = 4; o; o >>= 1) ss += __shfl_xor_sync(0xffu, ss, o);
        if (tid == 0) red[0] = ss;
    }
    __syncthreads();
    float inv = (g_cnt[c] > 0.f) ? 1.f / fmaxf(sqrtf(red[0]), 1e-12f) : 0.f;
    for (int i = tid; i < DD; i += 256) {
        float v = row[i] * inv;
        __nv_bfloat16 h = __float2bfloat16(v);
        g_Phi[(size_t)c * DD + i] = h;
        g_Plo[(size_t)c * DD + i] = __float2bfloat16(v - __bfloat162float(h));
    }
}

// ---------------------------------------------------------------------------
__global__ void softmax_kernel(const float* __restrict__ L,
                               float* __restrict__ P, int Cn)
{
    __shared__ float buf[1024];
    __shared__ float red[8];
    int row = blockIdx.x, tid = threadIdx.x;
    const float* lr = L + (size_t)row * Cn;

    float mx = -1e30f;
    for (int i = tid; i < Cn; i += 256) { float v = lr[i]; buf[i] = v; mx = fmaxf(mx, v); }
#pragma unroll
    for (int o = 16; o; o >>= 1) mx = fmaxf(mx, __shfl_xor_sync(0xffffffffu, mx, o));
    if ((tid & 31) == 0) red[tid >> 5] = mx;
    __syncthreads();
    if (tid < 8) {
        mx = red[tid];
#pragma unroll
        for (int o = 4; o; o >>= 1) mx = fmaxf(mx, __shfl_xor_sync(0xffu, mx, o));
        if (tid == 0) red[0] = mx;
    }
    __syncthreads();
    mx = red[0];
    __syncthreads();

    float sm = 0.f;
    for (int i = tid; i < Cn; i += 256) { float e = expf(buf[i] - mx); buf[i] = e; sm += e; }
#pragma unroll
    for (int o = 16; o; o >>= 1) sm += __shfl_xor_sync(0xffffffffu, sm, o);
    if ((tid & 31) == 0) red[tid >> 5] = sm;
    __syncthreads();
    if (tid < 8) {
        sm = red[tid];
#pragma unroll
        for (int o = 4; o; o >>= 1) sm += __shfl_xor_sync(0xffu, sm, o);
        if (tid == 0) red[0] = sm;
    }
    __syncthreads();
    float inv = 1.f / red[0];
    for (int i = tid; i < Cn; i += 256)
        P[(size_t)row * Cn + i] = buf[i] * inv;
}

// ---------------------------------------------------------------------------
extern "C" void kernel_launch(void* const* d_in, const int* in_sizes, int n_in,
                              void* d_out, int out_size)
{
    const float* x   = (const float*)d_in[0];
    const float* sf  = (const float*)d_in[1];
    const int*   lab = (const int*)d_in[2];
    const float* W   = (const float*)d_in[3];
    const float* b   = (const float*)d_in[4];
    (void)n_in;

    const int D = in_sizes[4];               // 768
    const int B = in_sizes[0] / D;           // 8192
    const int N = in_sizes[2];               // 100000
    const long long C =
        ((long long)out_size - (long long)B * D) / (2LL * B);   // 1000

    float* predicts = (float*)d_out;
    float* logits   = predicts + (long long)B * C;
    float* emb      = logits + (long long)B * C;

    static __nv_bfloat16 *pAhi = nullptr, *pAlo = nullptr, *pWhi = nullptr, *pWlo = nullptr;
    static __nv_bfloat16 *pEhi = nullptr, *pElo = nullptr, *pPhi = nullptr, *pPlo = nullptr;
    static bool init = false;
    if (!init) {
        cudaGetSymbolAddress((void**)&pAhi, g_Ahi);
        cudaGetSymbolAddress((void**)&pAlo, g_Alo);
        cudaGetSymbolAddress((void**)&pWhi, g_Whi);
        cudaGetSymbolAddress((void**)&pWlo, g_Wlo);
        cudaGetSymbolAddress((void**)&pEhi, g_Ehi);
        cudaGetSymbolAddress((void**)&pElo, g_Elo);
        cudaGetSymbolAddress((void**)&pPhi, g_Phi);
        cudaGetSymbolAddress((void**)&pPlo, g_Plo);
        cudaFuncSetAttribute(gemm_kernel<0, 3>,
                             cudaFuncAttributeMaxDynamicSharedMemorySize, Cfg<3>::SMEM);
        cudaFuncSetAttribute(gemm_kernel<0, 2>,
                             cudaFuncAttributeMaxDynamicSharedMemorySize, Cfg<2>::SMEM);
        cudaFuncSetAttribute(gemm_kernel<1, 3>,
                             cudaFuncAttributeMaxDynamicSharedMemorySize, Cfg<3>::SMEM);
        init = true;
    }

    zero_kernel<<<(NPAD * DD + 255) / 256, 256>>>();
    prep_w<<<(DD * DD + 255) / 256, 256>>>(W);
    {
        size_t tot = ((size_t)ROWS_PAD * DD) / 4;
        prep_x<<<(int)((tot + 255) / 256), 256>>>(x, sf, B, N);
    }
    count_kernel<<<(N + 255) / 256, 256>>>(lab, N);

    // adapter GEMM over x rows (0..B-1): 3-term split (exact path for emb)
    {
        dim3 g(DD / 128, B / 128);
        gemm_kernel<0, 3><<<g, 256, Cfg<3>::SMEM>>>(pAhi, pAlo, pWhi, pWlo,
                                                    x, b, nullptr, 0, B, 0, DD);
    }
    // adapter GEMM over support rows (B..B+N-1): 2-term split (error averages
    // out in class-mean prototypes)
    {
        dim3 g(DD / 128, (N + 127) / 128);
        gemm_kernel<0, 2><<<g, 256, Cfg<2>::SMEM>>>(pAhi, nullptr, pWhi, pWlo,
                                                    sf, b, nullptr, B, B + N, B, DD);
    }

    norm_emb<<<(B + 7) / 8, 256>>>(emb, B);
    norm_proto<<<(N + 7) / 8, 256>>>(lab, B, N);
    proto_norm_kernel<<<(int)C, 256>>>((int)C);

    // cosine logits GEMM: emb (hi/lo) x proto (hi/lo), 3-term
    {
        dim3 g(NPAD / 128, B / 128);
        gemm_kernel<1, 3><<<g, 256, Cfg<3>::SMEM>>>(pEhi, pElo, pPhi, pPlo,
                                                    nullptr, nullptr, logits,
                                                    0, B, 0, (int)C);
    }

    softmax_kernel<<<B, 256>>>(logits, predicts, (int)C);
}

// round 6
// speedup vs baseline: 3.6594x; 1.0140x over previous
#include <cuda_runtime.h>
#include <cuda_bf16.h>
#include <math.h>
#include <stdint.h>

// ---------------------------------------------------------------------------
// UnifiedZipAdapterF round 6: HMMA bf16 hi/lo-split GEMMs.
// vs R5: single-barrier software pipeline (fills interleaved into compute
// after the stage barrier, empty commit groups keep wait_group uniform),
// deeper pipelines (3-term: 3 stages, 2-term: 4 stages; 192KB smem).
//   H = X @ W^T + b ; U = silu(H) + X ; emb/proto = rownorm(U)
//   logits = exp(32*cos - 32)/tau ; predicts = softmax(logits)
// ---------------------------------------------------------------------------

#define DD        768
#define CMAX      1000
#define NPAD      1024
#define BMAX      8192
#define ROWS_PAD  108288      // 8192 + ceil(100000/128)*128

// ---- static device scratch (no allocations allowed) ----
__device__ __nv_bfloat16 g_Ahi[(size_t)ROWS_PAD * DD];
__device__ __nv_bfloat16 g_Alo[(size_t)BMAX * DD];      // only emb rows need lo
__device__ float         g_U[(size_t)ROWS_PAD * DD];
__device__ float         g_sq[ROWS_PAD];
__device__ __nv_bfloat16 g_Whi[DD * DD];
__device__ __nv_bfloat16 g_Wlo[DD * DD];
__device__ float         g_proto[CMAX * DD];
__device__ float         g_cnt[CMAX];
__device__ __nv_bfloat16 g_Ehi[(size_t)BMAX * DD];
__device__ __nv_bfloat16 g_Elo[(size_t)BMAX * DD];
__device__ __nv_bfloat16 g_Phi[(size_t)NPAD * DD];
__device__ __nv_bfloat16 g_Plo[(size_t)NPAD * DD];

// ---------------------------------------------------------------------------
__device__ __forceinline__ uint32_t s2u(const void* p) {
    uint32_t a;
    asm("{ .reg .u64 t; cvta.to.shared.u64 t, %1; cvt.u32.u64 %0, t; }"
        : "=r"(a) : "l"(p));
    return a;
}
__device__ __forceinline__ uint32_t pack2bf(float a, float b) {
    __nv_bfloat162 t = __floats2bfloat162_rn(a, b);
    return *reinterpret_cast<uint32_t*>(&t);
}
__device__ __forceinline__ void cp16(uint32_t d, const void* s) {
    asm volatile("cp.async.cg.shared.global [%0], [%1], 16;" :: "r"(d), "l"(s));
}

#define LDSM_X4(R0, R1, R2, R3, ADDR)                                          \
    asm volatile("ldmatrix.sync.aligned.m8n8.x4.shared.b16 {%0,%1,%2,%3}, [%4];" \
        : "=r"(R0), "=r"(R1), "=r"(R2), "=r"(R3) : "r"(ADDR))
#define MMA_BF16(D, A, B)                                                      \
    asm volatile("mma.sync.aligned.m16n8k16.row.col.f32.bf16.bf16.f32 "        \
        "{%0,%1,%2,%3}, {%4,%5,%6,%7}, {%8,%9}, {%0,%1,%2,%3};"                \
        : "+f"((D)[0]), "+f"((D)[1]), "+f"((D)[2]), "+f"((D)[3])               \
        : "r"((A)[0]), "r"((A)[1]), "r"((A)[2]), "r"((A)[3]),                  \
          "r"((B)[0]), "r"((B)[1]))

// ---------------------------------------------------------------------------
// prep kernels
// ---------------------------------------------------------------------------
__global__ void zero_kernel() {
    int i = blockIdx.x * blockDim.x + threadIdx.x;
    if (i < CMAX * DD) g_proto[i] = 0.f;
    if (i < NPAD * DD) {
        g_Phi[i] = __nv_bfloat16(0.f);
        g_Plo[i] = __nv_bfloat16(0.f);
    }
    if (i < CMAX)     g_cnt[i] = 0.f;
    if (i < ROWS_PAD) g_sq[i]  = 0.f;
}

__global__ void count_kernel(const int* __restrict__ lab, int N) {
    int i = blockIdx.x * blockDim.x + threadIdx.x;
    if (i < N) atomicAdd(&g_cnt[lab[i]], 1.0f);
}

__global__ void prep_w(const float* __restrict__ W) {
    int i = blockIdx.x * blockDim.x + threadIdx.x;
    if (i < DD * DD) {
        float v = W[i];
        __nv_bfloat16 h = __float2bfloat16(v);
        g_Whi[i] = h;
        g_Wlo[i] = __float2bfloat16(v - __bfloat162float(h));
    }
}

// [x ; sf ; zero-pad] rows -> g_Ahi (all) / g_Alo (emb rows only)
__global__ void prep_x(const float* __restrict__ x, const float* __restrict__ sf,
                       int Brows, int Nrows) {
    size_t i = ((size_t)blockIdx.x * blockDim.x + threadIdx.x) * 4;
    if (i >= (size_t)ROWS_PAD * DD) return;
    size_t r = i / DD;
    float4 v = make_float4(0.f, 0.f, 0.f, 0.f);
    if (r < (size_t)Brows)
        v = *reinterpret_cast<const float4*>(&x[i]);
    else if (r < (size_t)(Brows + Nrows))
        v = *reinterpret_cast<const float4*>(&sf[i - (size_t)Brows * DD]);
    float vv[4] = {v.x, v.y, v.z, v.w};
    uint32_t hi[2], lo[2];
#pragma unroll
    for (int j = 0; j < 2; ++j) {
        float a0 = vv[2 * j], a1 = vv[2 * j + 1];
        __nv_bfloat16 h0 = __float2bfloat16(a0);
        __nv_bfloat16 h1 = __float2bfloat16(a1);
        hi[j] = pack2bf(a0, a1);
        lo[j] = pack2bf(a0 - __bfloat162float(h0), a1 - __bfloat162float(h1));
    }
    *reinterpret_cast<uint2*>(&g_Ahi[i]) = make_uint2(hi[0], hi[1]);
    if (r < (size_t)Brows)
        *reinterpret_cast<uint2*>(&g_Alo[i]) = make_uint2(lo[0], lo[1]);
}

// ---------------------------------------------------------------------------
// GEMM core: 128x128 tile, 8 warps (2x4), warp tile 64x32, BK=64.
// TERMS==3: Ah*Bh + Ah*Bl + Al*Bh, 3-stage pipeline (stage 64KB).
// TERMS==2: Ah*Bh + Ah*Bl,         4-stage pipeline (stage 48KB).
// smem stage: Ahi 16K | [Alo 16K] | Bhi 16K | Blo 16K (row=128B, XOR swizzle)
// Mainloop: ONE __syncthreads per stage; next-stage fills interleaved into
// the k-sub-iterations AFTER the barrier (stage being refilled was computed
// in the previous iteration, so all warps have drained it).
// ---------------------------------------------------------------------------
template <int TERMS>
struct Cfg {
    static const int A_SZ  = (TERMS == 3) ? 32768 : 16384;
    static const int STAGE = A_SZ + 32768;
    static const int NS    = (TERMS == 3) ? 3 : 4;
    static const int SMEM  = NS * STAGE;    // 192KB either way
};

// one quarter of a stage fill (part p in 0..3)
template <int TERMS>
__device__ __forceinline__ void fill_part(
    const __nv_bfloat16* __restrict__ Ah, const __nv_bfloat16* __restrict__ Al,
    const __nv_bfloat16* __restrict__ Bh, const __nv_bfloat16* __restrict__ Bl,
    int arow0, int brow0, int kb, uint32_t sbase, int tid, int p)
{
    const int A_SZ = Cfg<TERMS>::A_SZ;
    int ch = tid + p * 256;        // 1024 chunks per 16KB tile
    int r = ch >> 3, c = ch & 7;
    uint32_t off = (uint32_t)(r * 128 + ((c ^ (r & 7)) << 4));
    size_t ai = (size_t)(arow0 + r) * DD + kb + c * 8;
    size_t bi = (size_t)(brow0 + r) * DD + kb + c * 8;
    cp16(sbase + off, Ah + ai);
    if (TERMS == 3) cp16(sbase + 16384 + off, Al + ai);
    cp16(sbase + A_SZ + off,         Bh + bi);
    cp16(sbase + A_SZ + 16384 + off, Bl + bi);
}

// one k16 sub-iteration of compute (kk in 0..3 => k offset kk*16)
template <int TERMS>
__device__ __forceinline__ void compute_k16(uint32_t sb, int kk, int wm, int wn,
                                            int lane, float (&acc)[4][4][4])
{
    const uint32_t aH = sb, aL = sb + 16384;
    const uint32_t bH = sb + Cfg<TERMS>::A_SZ, bL = bH + 16384;
    const int t = lane >> 3, li = lane & 7;
    uint32_t ah[4][4], al[4][4], bh[4][2], bl[4][2];
#pragma unroll
    for (int mi = 0; mi < 4; ++mi) {
        int r  = wm * 64 + mi * 16 + ((t & 1) << 3) + li;
        int cc = (kk << 1) + (t >> 1);
        uint32_t off = (uint32_t)(r * 128 + ((cc ^ (r & 7)) << 4));
        LDSM_X4(ah[mi][0], ah[mi][1], ah[mi][2], ah[mi][3], aH + off);
        if (TERMS == 3)
            LDSM_X4(al[mi][0], al[mi][1], al[mi][2], al[mi][3], aL + off);
    }
    // B stored [n][k] (k-contiguous) => NON-trans ldmatrix gives the
    // col-major fragment (lane l: k = 2*(l%4)+{0,1}, n = l/4).
#pragma unroll
    for (int p = 0; p < 2; ++p) {
        int n  = wn * 32 + p * 16 + ((t >> 1) << 3) + li;
        int cc = (kk << 1) + (t & 1);
        uint32_t off = (uint32_t)(n * 128 + ((cc ^ (n & 7)) << 4));
        LDSM_X4(bh[2 * p][0], bh[2 * p][1], bh[2 * p + 1][0], bh[2 * p + 1][1], bH + off);
        LDSM_X4(bl[2 * p][0], bl[2 * p][1], bl[2 * p + 1][0], bl[2 * p + 1][1], bL + off);
    }
#pragma unroll
    for (int mi = 0; mi < 4; ++mi)
#pragma unroll
        for (int nj = 0; nj < 4; ++nj) {
            MMA_BF16(acc[mi][nj], ah[mi], bh[nj]);
            MMA_BF16(acc[mi][nj], ah[mi], bl[nj]);
            if (TERMS == 3) MMA_BF16(acc[mi][nj], al[mi], bh[nj]);
        }
}

// EPI 0: adapter (bias+silu+residual -> g_U, row-sq -> g_sq)
// EPI 1: cosine logits (exp(32c-32)/tau -> Lout)
template <int EPI, int TERMS>
__global__ __launch_bounds__(256, 1)
void gemm_kernel(const __nv_bfloat16* __restrict__ Ah, const __nv_bfloat16* __restrict__ Al,
                 const __nv_bfloat16* __restrict__ Bh, const __nv_bfloat16* __restrict__ Bl,
                 const float* __restrict__ Xres, const float* __restrict__ bias,
                 float* __restrict__ Lout,
                 int aRowBase0, int rowEnd, int inputBase, int Cn)
{
    const int NS    = Cfg<TERMS>::NS;
    const int STAGE = Cfg<TERMS>::STAGE;
    extern __shared__ __align__(16) char smem[];
    const int tid  = threadIdx.x;
    const int lane = tid & 31, wid = tid >> 5;
    const int wm = wid >> 2, wn = wid & 3;
    const int nb0   = blockIdx.x * 128;
    const int arow0 = aRowBase0 + blockIdx.y * 128;
    const uint32_t sb = s2u(smem);

    float acc[4][4][4] = {};

    // prologue: fill stages 0..NS-2
#pragma unroll
    for (int s = 0; s < NS - 1; ++s) {
#pragma unroll
        for (int p = 0; p < 4; ++p)
            fill_part<TERMS>(Ah, Al, Bh, Bl, arow0, nb0, s * 64, sb + s * STAGE, tid, p);
        asm volatile("cp.async.commit_group;");
    }

#pragma unroll 1
    for (int s = 0; s < 12; ++s) {
        asm volatile("cp.async.wait_group %0;" :: "n"(Cfg<TERMS>::NS - 2));
        __syncthreads();
        const uint32_t cs = sb + (s % NS) * STAGE;
        const uint32_t fs = sb + ((s + NS - 1) % NS) * STAGE;
        const int fkb = (s + NS - 1) * 64;
        const bool df = (s + NS - 1) < 12;
#pragma unroll
        for (int kk = 0; kk < 4; ++kk) {
            if (df) fill_part<TERMS>(Ah, Al, Bh, Bl, arow0, nb0, fkb, fs, tid, kk);
            compute_k16<TERMS>(cs, kk, wm, wn, lane, acc);
        }
        asm volatile("cp.async.commit_group;");   // empty group when !df
    }
    __syncthreads();

    // ---- stage accumulators through smem (reuse pipeline buffers) ----
    float* es = reinterpret_cast<float*>(smem);   // [128][132]
#pragma unroll
    for (int mi = 0; mi < 4; ++mi)
#pragma unroll
        for (int nj = 0; nj < 4; ++nj) {
            int r0 = wm * 64 + mi * 16 + (lane >> 2);
            int c0 = wn * 32 + nj * 8 + (lane & 3) * 2;
            es[r0 * 132 + c0]           = acc[mi][nj][0];
            es[r0 * 132 + c0 + 1]       = acc[mi][nj][1];
            es[(r0 + 8) * 132 + c0]     = acc[mi][nj][2];
            es[(r0 + 8) * 132 + c0 + 1] = acc[mi][nj][3];
        }
    __syncthreads();

    const int row  = tid >> 1;
    const int half = tid & 1;
    const int arow = arow0 + row;
    const bool valid = (arow < rowEnd);
    const float* er = es + row * 132 + half * 64;

    if (EPI == 0) {
        float sq = 0.f;
        if (valid) {
            const float* xr = Xres + (size_t)(arow - inputBase) * DD + nb0 + half * 64;
            float*       ur = g_U  + (size_t)arow * DD + nb0 + half * 64;
            const float* br = bias + nb0 + half * 64;
#pragma unroll
            for (int j = 0; j < 64; j += 4) {
                float4 v  = *reinterpret_cast<const float4*>(er + j);
                float4 bb = *reinterpret_cast<const float4*>(br + j);
                float4 xv = *reinterpret_cast<const float4*>(xr + j);
                float h0 = v.x + bb.x, h1 = v.y + bb.y;
                float h2 = v.z + bb.z, h3 = v.w + bb.w;
                float4 o;
                o.x = h0 / (1.f + expf(-h0)) + xv.x;
                o.y = h1 / (1.f + expf(-h1)) + xv.y;
                o.z = h2 / (1.f + expf(-h2)) + xv.z;
                o.w = h3 / (1.f + expf(-h3)) + xv.w;
                sq += o.x * o.x + o.y * o.y + o.z * o.z + o.w * o.w;
                *reinterpret_cast<float4*>(ur + j) = o;
            }
        }
        float tot = sq + __shfl_xor_sync(0xffffffffu, sq, 1);
        if (valid && half == 0) atomicAdd(&g_sq[arow], tot);
    } else {
        if (valid) {
            const float invtau = 1.0f / 0.11f;
            float* lr = Lout + (size_t)arow * Cn + nb0 + half * 64;
            int cbase = nb0 + half * 64;
            if (cbase + 64 <= Cn) {
#pragma unroll
                for (int j = 0; j < 64; j += 4) {
                    float4 v = *reinterpret_cast<const float4*>(er + j);
                    float4 o;
                    o.x = expf(32.f * v.x - 32.f) * invtau;
                    o.y = expf(32.f * v.y - 32.f) * invtau;
                    o.z = expf(32.f * v.z - 32.f) * invtau;
                    o.w = expf(32.f * v.w - 32.f) * invtau;
                    *reinterpret_cast<float4*>(lr + j) = o;
                }
            } else {
                for (int j = 0; j < 64; ++j) {
                    int c = cbase + j;
                    if (c < Cn) lr[j] = expf(32.f * er[j] - 32.f) * invtau;
                }
            }
        }
    }
}

// ---------------------------------------------------------------------------
// normalize rows 0..B-1 of g_U -> emb (fp32) + g_Ehi/g_Elo (bf16 hi/lo)
__global__ __launch_bounds__(256)
void norm_emb(float* __restrict__ emb, int M) {
    int row  = blockIdx.x * 8 + (threadIdx.x >> 5);
    int lane = threadIdx.x & 31;
    if (row >= M) return;
    float inv = 1.f / fmaxf(sqrtf(g_sq[row]), 1e-12f);
    const float4* u = reinterpret_cast<const float4*>(&g_U[(size_t)row * DD]);
    float4* o  = reinterpret_cast<float4*>(&emb[(size_t)row * DD]);
    uint2*  eh = reinterpret_cast<uint2*>(&g_Ehi[(size_t)row * DD]);
    uint2*  el = reinterpret_cast<uint2*>(&g_Elo[(size_t)row * DD]);
    for (int i = lane; i < DD / 4; i += 32) {
        float4 v = u[i];
        v.x *= inv; v.y *= inv; v.z *= inv; v.w *= inv;
        o[i] = v;
        __nv_bfloat16 h0 = __float2bfloat16(v.x), h1 = __float2bfloat16(v.y);
        __nv_bfloat16 h2 = __float2bfloat16(v.z), h3 = __float2bfloat16(v.w);
        eh[i] = make_uint2(pack2bf(v.x, v.y), pack2bf(v.z, v.w));
        el[i] = make_uint2(
            pack2bf(v.x - __bfloat162float(h0), v.y - __bfloat162float(h1)),
            pack2bf(v.z - __bfloat162float(h2), v.w - __bfloat162float(h3)));
    }
}

// normalize rows B..B+N-1 of g_U, scatter-add into g_proto[label] (vector red)
__global__ __launch_bounds__(256)
void norm_proto(const int* __restrict__ lab, int Brows, int N) {
    int row  = blockIdx.x * 8 + (threadIdx.x >> 5);
    int lane = threadIdx.x & 31;
    if (row >= N) return;
    int grow = Brows + row;
    float inv = 1.f / fmaxf(sqrtf(g_sq[grow]), 1e-12f);
    int lb = lab[row];
    const float4* u = reinterpret_cast<const float4*>(&g_U[(size_t)grow * DD]);
    float* dst = &g_proto[(size_t)lb * DD];
    for (int i = lane; i < DD / 4; i += 32) {
        float4 v = u[i];
        asm volatile("red.global.add.v4.f32 [%0], {%1,%2,%3,%4};"
                     :: "l"(dst + i * 4), "f"(v.x * inv), "f"(v.y * inv),
                        "f"(v.z * inv), "f"(v.w * inv) : "memory");
    }
}

// prototype sums -> normalized bf16 hi/lo (rows >= Cn remain zero)
__global__ void proto_norm_kernel(int Cn) {
    int c   = blockIdx.x;
    int tid = threadIdx.x;
    if (c >= Cn) return;
    const float* row = &g_proto[(size_t)c * DD];
    float ss = 0.f;
    for (int i = tid; i < DD; i += 256) { float v = row[i]; ss += v * v; }
    __shared__ float red[8];
#pragma unroll
    for (int o = 16; o; o >>= 1) ss += __shfl_xor_sync(0xffffffffu, ss, o);
    if ((tid & 31) == 0) red[tid >> 5] = ss;
    __syncthreads();
    if (tid < 8) {
        ss = red[tid];
#pragma unroll
        for (int o = 4; o; o >>= 1) ss += __shfl_xor_sync(0xffu, ss, o);
        if (tid == 0) red[0] = ss;
    }
    __syncthreads();
    float inv = (g_cnt[c] > 0.f) ? 1.f / fmaxf(sqrtf(red[0]), 1e-12f) : 0.f;
    for (int i = tid; i < DD; i += 256) {
        float v = row[i] * inv;
        __nv_bfloat16 h = __float2bfloat16(v);
        g_Phi[(size_t)c * DD + i] = h;
        g_Plo[(size_t)c * DD + i] = __float2bfloat16(v - __bfloat162float(h));
    }
}

// ---------------------------------------------------------------------------
__global__ void softmax_kernel(const float* __restrict__ L,
                               float* __restrict__ P, int Cn)
{
    __shared__ float buf[1024];
    __shared__ float red[8];
    int row = blockIdx.x, tid = threadIdx.x;
    const float* lr = L + (size_t)row * Cn;

    float mx = -1e30f;
    for (int i = tid; i < Cn; i += 256) { float v = lr[i]; buf[i] = v; mx = fmaxf(mx, v); }
#pragma unroll
    for (int o = 16; o; o >>= 1) mx = fmaxf(mx, __shfl_xor_sync(0xffffffffu, mx, o));
    if ((tid & 31) == 0) red[tid >> 5] = mx;
    __syncthreads();
    if (tid < 8) {
        mx = red[tid];
#pragma unroll
        for (int o = 4; o; o >>= 1) mx = fmaxf(mx, __shfl_xor_sync(0xffu, mx, o));
        if (tid == 0) red[0] = mx;
    }
    __syncthreads();
    mx = red[0];
    __syncthreads();

    float sm = 0.f;
    for (int i = tid; i < Cn; i += 256) { float e = expf(buf[i] - mx); buf[i] = e; sm += e; }
#pragma unroll
    for (int o = 16; o; o >>= 1) sm += __shfl_xor_sync(0xffffffffu, sm, o);
    if ((tid & 31) == 0) red[tid >> 5] = sm;
    __syncthreads();
    if (tid < 8) {
        sm = red[tid];
#pragma unroll
        for (int o = 4; o; o >>= 1) sm += __shfl_xor_sync(0xffu, sm, o);
        if (tid == 0) red[0] = sm;
    }
    __syncthreads();
    float inv = 1.f / red[0];
    for (int i = tid; i < Cn; i += 256)
        P[(size_t)row * Cn + i] = buf[i] * inv;
}

// ---------------------------------------------------------------------------
extern "C" void kernel_launch(void* const* d_in, const int* in_sizes, int n_in,
                              void* d_out, int out_size)
{
    const float* x   = (const float*)d_in[0];
    const float* sf  = (const float*)d_in[1];
    const int*   lab = (const int*)d_in[2];
    const float* W   = (const float*)d_in[3];
    const float* b   = (const float*)d_in[4];
    (void)n_in;

    const int D = in_sizes[4];               // 768
    const int B = in_sizes[0] / D;           // 8192
    const int N = in_sizes[2];               // 100000
    const long long C =
        ((long long)out_size - (long long)B * D) / (2LL * B);   // 1000

    float* predicts = (float*)d_out;
    float* logits   = predicts + (long long)B * C;
    float* emb      = logits + (long long)B * C;

    static __nv_bfloat16 *pAhi = nullptr, *pAlo = nullptr, *pWhi = nullptr, *pWlo = nullptr;
    static __nv_bfloat16 *pEhi = nullptr, *pElo = nullptr, *pPhi = nullptr, *pPlo = nullptr;
    static bool init = false;
    if (!init) {
        cudaGetSymbolAddress((void**)&pAhi, g_Ahi);
        cudaGetSymbolAddress((void**)&pAlo, g_Alo);
        cudaGetSymbolAddress((void**)&pWhi, g_Whi);
        cudaGetSymbolAddress((void**)&pWlo, g_Wlo);
        cudaGetSymbolAddress((void**)&pEhi, g_Ehi);
        cudaGetSymbolAddress((void**)&pElo, g_Elo);
        cudaGetSymbolAddress((void**)&pPhi, g_Phi);
        cudaGetSymbolAddress((void**)&pPlo, g_Plo);
        cudaFuncSetAttribute(gemm_kernel<0, 3>,
                             cudaFuncAttributeMaxDynamicSharedMemorySize, Cfg<3>::SMEM);
        cudaFuncSetAttribute(gemm_kernel<0, 2>,
                             cudaFuncAttributeMaxDynamicSharedMemorySize, Cfg<2>::SMEM);
        cudaFuncSetAttribute(gemm_kernel<1, 3>,
                             cudaFuncAttributeMaxDynamicSharedMemorySize, Cfg<3>::SMEM);
        init = true;
    }

    zero_kernel<<<(NPAD * DD + 255) / 256, 256>>>();
    prep_w<<<(DD * DD + 255) / 256, 256>>>(W);
    {
        size_t tot = ((size_t)ROWS_PAD * DD) / 4;
        prep_x<<<(int)((tot + 255) / 256), 256>>>(x, sf, B, N);
    }
    count_kernel<<<(N + 255) / 256, 256>>>(lab, N);

    // adapter GEMM over x rows (0..B-1): 3-term split (exact path for emb)
    {
        dim3 g(DD / 128, B / 128);
        gemm_kernel<0, 3><<<g, 256, Cfg<3>::SMEM>>>(pAhi, pAlo, pWhi, pWlo,
                                                    x, b, nullptr, 0, B, 0, DD);
    }
    // adapter GEMM over support rows (B..B+N-1): 2-term split (error averages
    // out in class-mean prototypes)
    {
        dim3 g(DD / 128, (N + 127) / 128);
        gemm_kernel<0, 2><<<g, 256, Cfg<2>::SMEM>>>(pAhi, nullptr, pWhi, pWlo,
                                                    sf, b, nullptr, B, B + N, B, DD);
    }

    norm_emb<<<(B + 7) / 8, 256>>>(emb, B);
    norm_proto<<<(N + 7) / 8, 256>>>(lab, B, N);
    proto_norm_kernel<<<(int)C, 256>>>((int)C);

    // cosine logits GEMM: emb (hi/lo) x proto (hi/lo), 3-term
    {
        dim3 g(NPAD / 128, B / 128);
        gemm_kernel<1, 3><<<g, 256, Cfg<3>::SMEM>>>(pEhi, pElo, pPhi, pPlo,
                                                    nullptr, nullptr, logits,
                                                    0, B, 0, (int)C);
    }

    softmax_kernel<<<B, 256>>>(logits, predicts, (int)C);
}

// round 8
// speedup vs baseline: 3.6716x; 1.0033x over previous
#include <cuda_runtime.h>
#include <cuda_bf16.h>
#include <cuda_fp16.h>
#include <math.h>
#include <stdint.h>

// ---------------------------------------------------------------------------
// UnifiedZipAdapterF round 8: R7 with the __floats2half2_rn signature fixed.
// bf16 hi/lo-split HMMA GEMMs (cores at the HMMA issue floor). Overhead cuts:
//   - support-row U stored fp16 (halves U traffic)
//   - row-sq computed in norm kernels (epilogue atomics + g_sq removed)
//   - smem-aggregated label count
//   - launch order puts the big GEMM at the ncu capture slot
// ---------------------------------------------------------------------------

#define DD        768
#define CMAX      1000
#define NPAD      1024
#define BMAX      8192
#define NSUP_PAD  100096     // ceil(100000/128)*128
#define ROWS_PAD  (BMAX + NSUP_PAD)

// ---- static device scratch (no allocations allowed) ----
__device__ __nv_bfloat16 g_Ahi[(size_t)ROWS_PAD * DD];
__device__ __nv_bfloat16 g_Alo[(size_t)BMAX * DD];      // only emb rows need lo
__device__ float         g_U[(size_t)BMAX * DD];        // emb-row adapter out (fp32)
__device__ __half        g_Uh[(size_t)NSUP_PAD * DD];   // support-row adapter out (fp16)
__device__ __nv_bfloat16 g_Whi[DD * DD];
__device__ __nv_bfloat16 g_Wlo[DD * DD];
__device__ float         g_proto[CMAX * DD];
__device__ float         g_cnt[CMAX];
__device__ __nv_bfloat16 g_Ehi[(size_t)BMAX * DD];
__device__ __nv_bfloat16 g_Elo[(size_t)BMAX * DD];
__device__ __nv_bfloat16 g_Phi[(size_t)NPAD * DD];      // pad rows stay zero-init
__device__ __nv_bfloat16 g_Plo[(size_t)NPAD * DD];

// ---------------------------------------------------------------------------
__device__ __forceinline__ uint32_t s2u(const void* p) {
    uint32_t a;
    asm("{ .reg .u64 t; cvta.to.shared.u64 t, %1; cvt.u32.u64 %0, t; }"
        : "=r"(a) : "l"(p));
    return a;
}
__device__ __forceinline__ uint32_t pack2bf(float a, float b) {
    __nv_bfloat162 t = __floats2bfloat162_rn(a, b);
    return *reinterpret_cast<uint32_t*>(&t);
}
__device__ __forceinline__ uint32_t pack2h(float a, float b) {
    __half2 t = __floats2half2_rn(a, b);
    return *reinterpret_cast<uint32_t*>(&t);
}
__device__ __forceinline__ void cp16(uint32_t d, const void* s) {
    asm volatile("cp.async.cg.shared.global [%0], [%1], 16;" :: "r"(d), "l"(s));
}

#define LDSM_X4(R0, R1, R2, R3, ADDR)                                          \
    asm volatile("ldmatrix.sync.aligned.m8n8.x4.shared.b16 {%0,%1,%2,%3}, [%4];" \
        : "=r"(R0), "=r"(R1), "=r"(R2), "=r"(R3) : "r"(ADDR))
#define MMA_BF16(D, A, B)                                                      \
    asm volatile("mma.sync.aligned.m16n8k16.row.col.f32.bf16.bf16.f32 "        \
        "{%0,%1,%2,%3}, {%4,%5,%6,%7}, {%8,%9}, {%0,%1,%2,%3};"                \
        : "+f"((D)[0]), "+f"((D)[1]), "+f"((D)[2]), "+f"((D)[3])               \
        : "r"((A)[0]), "r"((A)[1]), "r"((A)[2]), "r"((A)[3]),                  \
          "r"((B)[0]), "r"((B)[1]))

// ---------------------------------------------------------------------------
// prep kernels
// ---------------------------------------------------------------------------
__global__ void zero_kernel() {
    int i = blockIdx.x * blockDim.x + threadIdx.x;
    if (i < CMAX * DD) g_proto[i] = 0.f;
    if (i < CMAX)      g_cnt[i]   = 0.f;
}

__global__ void count_kernel(const int* __restrict__ lab, int N) {
    __shared__ int c[CMAX];
    int tid = threadIdx.x;
    for (int i = tid; i < CMAX; i += 256) c[i] = 0;
    __syncthreads();
    for (int i = blockIdx.x * 256 + tid; i < N; i += gridDim.x * 256)
        atomicAdd(&c[lab[i]], 1);
    __syncthreads();
    for (int i = tid; i < CMAX; i += 256)
        if (c[i]) atomicAdd(&g_cnt[i], (float)c[i]);
}

__global__ void prep_w(const float* __restrict__ W) {
    int i = blockIdx.x * blockDim.x + threadIdx.x;
    if (i < DD * DD) {
        float v = W[i];
        __nv_bfloat16 h = __float2bfloat16(v);
        g_Whi[i] = h;
        g_Wlo[i] = __float2bfloat16(v - __bfloat162float(h));
    }
}

// [x ; sf ; zero-pad] rows -> g_Ahi (all) / g_Alo (emb rows only)
__global__ void prep_x(const float* __restrict__ x, const float* __restrict__ sf,
                       int Brows, int Nrows) {
    size_t i = ((size_t)blockIdx.x * blockDim.x + threadIdx.x) * 4;
    if (i >= (size_t)ROWS_PAD * DD) return;
    size_t r = i / DD;
    float4 v = make_float4(0.f, 0.f, 0.f, 0.f);
    if (r < (size_t)Brows)
        v = *reinterpret_cast<const float4*>(&x[i]);
    else if (r < (size_t)(Brows + Nrows))
        v = *reinterpret_cast<const float4*>(&sf[i - (size_t)Brows * DD]);
    float vv[4] = {v.x, v.y, v.z, v.w};
    uint32_t hi[2], lo[2];
#pragma unroll
    for (int j = 0; j < 2; ++j) {
        float a0 = vv[2 * j], a1 = vv[2 * j + 1];
        __nv_bfloat16 h0 = __float2bfloat16(a0);
        __nv_bfloat16 h1 = __float2bfloat16(a1);
        hi[j] = pack2bf(a0, a1);
        lo[j] = pack2bf(a0 - __bfloat162float(h0), a1 - __bfloat162float(h1));
    }
    *reinterpret_cast<uint2*>(&g_Ahi[i]) = make_uint2(hi[0], hi[1]);
    if (r < (size_t)Brows)
        *reinterpret_cast<uint2*>(&g_Alo[i]) = make_uint2(lo[0], lo[1]);
}

// ---------------------------------------------------------------------------
// GEMM core (unchanged from R6): 128x128 tile, 8 warps, warp tile 64x32, BK=64
// ---------------------------------------------------------------------------
template <int TERMS>
struct Cfg {
    static const int A_SZ  = (TERMS == 3) ? 32768 : 16384;
    static const int STAGE = A_SZ + 32768;
    static const int NS    = (TERMS == 3) ? 3 : 4;
    static const int SMEM  = NS * STAGE;    // 192KB either way
};

template <int TERMS>
__device__ __forceinline__ void fill_part(
    const __nv_bfloat16* __restrict__ Ah, const __nv_bfloat16* __restrict__ Al,
    const __nv_bfloat16* __restrict__ Bh, const __nv_bfloat16* __restrict__ Bl,
    int arow0, int brow0, int kb, uint32_t sbase, int tid, int p)
{
    const int A_SZ = Cfg<TERMS>::A_SZ;
    int ch = tid + p * 256;
    int r = ch >> 3, c = ch & 7;
    uint32_t off = (uint32_t)(r * 128 + ((c ^ (r & 7)) << 4));
    size_t ai = (size_t)(arow0 + r) * DD + kb + c * 8;
    size_t bi = (size_t)(brow0 + r) * DD + kb + c * 8;
    cp16(sbase + off, Ah + ai);
    if (TERMS == 3) cp16(sbase + 16384 + off, Al + ai);
    cp16(sbase + A_SZ + off,         Bh + bi);
    cp16(sbase + A_SZ + 16384 + off, Bl + bi);
}

template <int TERMS>
__device__ __forceinline__ void compute_k16(uint32_t sb, int kk, int wm, int wn,
                                            int lane, float (&acc)[4][4][4])
{
    const uint32_t aH = sb, aL = sb + 16384;
    const uint32_t bH = sb + Cfg<TERMS>::A_SZ, bL = bH + 16384;
    const int t = lane >> 3, li = lane & 7;
    uint32_t ah[4][4], al[4][4], bh[4][2], bl[4][2];
#pragma unroll
    for (int mi = 0; mi < 4; ++mi) {
        int r  = wm * 64 + mi * 16 + ((t & 1) << 3) + li;
        int cc = (kk << 1) + (t >> 1);
        uint32_t off = (uint32_t)(r * 128 + ((cc ^ (r & 7)) << 4));
        LDSM_X4(ah[mi][0], ah[mi][1], ah[mi][2], ah[mi][3], aH + off);
        if (TERMS == 3)
            LDSM_X4(al[mi][0], al[mi][1], al[mi][2], al[mi][3], aL + off);
    }
#pragma unroll
    for (int p = 0; p < 2; ++p) {
        int n  = wn * 32 + p * 16 + ((t >> 1) << 3) + li;
        int cc = (kk << 1) + (t & 1);
        uint32_t off = (uint32_t)(n * 128 + ((cc ^ (n & 7)) << 4));
        LDSM_X4(bh[2 * p][0], bh[2 * p][1], bh[2 * p + 1][0], bh[2 * p + 1][1], bH + off);
        LDSM_X4(bl[2 * p][0], bl[2 * p][1], bl[2 * p + 1][0], bl[2 * p + 1][1], bL + off);
    }
#pragma unroll
    for (int mi = 0; mi < 4; ++mi)
#pragma unroll
        for (int nj = 0; nj < 4; ++nj) {
            MMA_BF16(acc[mi][nj], ah[mi], bh[nj]);
            MMA_BF16(acc[mi][nj], ah[mi], bl[nj]);
            if (TERMS == 3) MMA_BF16(acc[mi][nj], al[mi], bh[nj]);
        }
}

// EPI 0: adapter (bias+silu+residual -> U fp32 or fp16)
// EPI 1: cosine logits (exp(32c-32)/tau -> Lout)
template <int EPI, int TERMS, bool HALF_U>
__global__ __launch_bounds__(256, 1)
void gemm_kernel(const __nv_bfloat16* __restrict__ Ah, const __nv_bfloat16* __restrict__ Al,
                 const __nv_bfloat16* __restrict__ Bh, const __nv_bfloat16* __restrict__ Bl,
                 const float* __restrict__ Xres, const float* __restrict__ bias,
                 float* __restrict__ Lout,
                 int aRowBase0, int rowEnd, int inputBase, int Cn)
{
    const int NS    = Cfg<TERMS>::NS;
    const int STAGE = Cfg<TERMS>::STAGE;
    extern __shared__ __align__(16) char smem[];
    const int tid  = threadIdx.x;
    const int lane = tid & 31, wid = tid >> 5;
    const int wm = wid >> 2, wn = wid & 3;
    const int nb0   = blockIdx.x * 128;
    const int arow0 = aRowBase0 + blockIdx.y * 128;
    const uint32_t sb = s2u(smem);

    float acc[4][4][4] = {};

#pragma unroll
    for (int s = 0; s < NS - 1; ++s) {
#pragma unroll
        for (int p = 0; p < 4; ++p)
            fill_part<TERMS>(Ah, Al, Bh, Bl, arow0, nb0, s * 64, sb + s * STAGE, tid, p);
        asm volatile("cp.async.commit_group;");
    }

#pragma unroll 1
    for (int s = 0; s < 12; ++s) {
        asm volatile("cp.async.wait_group %0;" :: "n"(Cfg<TERMS>::NS - 2));
        __syncthreads();
        const uint32_t cs = sb + (s % NS) * STAGE;
        const uint32_t fs = sb + ((s + NS - 1) % NS) * STAGE;
        const int fkb = (s + NS - 1) * 64;
        const bool df = (s + NS - 1) < 12;
#pragma unroll
        for (int kk = 0; kk < 4; ++kk) {
            if (df) fill_part<TERMS>(Ah, Al, Bh, Bl, arow0, nb0, fkb, fs, tid, kk);
            compute_k16<TERMS>(cs, kk, wm, wn, lane, acc);
        }
        asm volatile("cp.async.commit_group;");   // empty group when !df
    }
    __syncthreads();

    // ---- stage accumulators through smem ----
    float* es = reinterpret_cast<float*>(smem);   // [128][132]
#pragma unroll
    for (int mi = 0; mi < 4; ++mi)
#pragma unroll
        for (int nj = 0; nj < 4; ++nj) {
            int r0 = wm * 64 + mi * 16 + (lane >> 2);
            int c0 = wn * 32 + nj * 8 + (lane & 3) * 2;
            es[r0 * 132 + c0]           = acc[mi][nj][0];
            es[r0 * 132 + c0 + 1]       = acc[mi][nj][1];
            es[(r0 + 8) * 132 + c0]     = acc[mi][nj][2];
            es[(r0 + 8) * 132 + c0 + 1] = acc[mi][nj][3];
        }
    __syncthreads();

    const int row  = tid >> 1;
    const int half = tid & 1;
    const int arow = arow0 + row;
    const bool valid = (arow < rowEnd);
    const float* er = es + row * 132 + half * 64;

    if (EPI == 0) {
        if (valid) {
            const int lrow = arow - inputBase;
            const float* xr = Xres + (size_t)lrow * DD + nb0 + half * 64;
            const float* br = bias + nb0 + half * 64;
            float*  urf = HALF_U ? nullptr
                                 : (g_U + (size_t)lrow * DD + nb0 + half * 64);
            __half* urh = HALF_U ? (g_Uh + (size_t)lrow * DD + nb0 + half * 64)
                                 : nullptr;
#pragma unroll
            for (int j = 0; j < 64; j += 4) {
                float4 v  = *reinterpret_cast<const float4*>(er + j);
                float4 bb = *reinterpret_cast<const float4*>(br + j);
                float4 xv = *reinterpret_cast<const float4*>(xr + j);
                float h0 = v.x + bb.x, h1 = v.y + bb.y;
                float h2 = v.z + bb.z, h3 = v.w + bb.w;
                float4 o;
                o.x = h0 / (1.f + expf(-h0)) + xv.x;
                o.y = h1 / (1.f + expf(-h1)) + xv.y;
                o.z = h2 / (1.f + expf(-h2)) + xv.z;
                o.w = h3 / (1.f + expf(-h3)) + xv.w;
                if (HALF_U) {
                    uint2 pk = make_uint2(pack2h(o.x, o.y), pack2h(o.z, o.w));
                    *reinterpret_cast<uint2*>(urh + j) = pk;
                } else {
                    *reinterpret_cast<float4*>(urf + j) = o;
                }
            }
        }
    } else {
        if (valid) {
            const float invtau = 1.0f / 0.11f;
            float* lr = Lout + (size_t)arow * Cn + nb0 + half * 64;
            int cbase = nb0 + half * 64;
            if (cbase + 64 <= Cn) {
#pragma unroll
                for (int j = 0; j < 64; j += 4) {
                    float4 v = *reinterpret_cast<const float4*>(er + j);
                    float4 o;
                    o.x = expf(32.f * v.x - 32.f) * invtau;
                    o.y = expf(32.f * v.y - 32.f) * invtau;
                    o.z = expf(32.f * v.z - 32.f) * invtau;
                    o.w = expf(32.f * v.w - 32.f) * invtau;
                    *reinterpret_cast<float4*>(lr + j) = o;
                }
            } else {
                for (int j = 0; j < 64; ++j) {
                    int c = cbase + j;
                    if (c < Cn) lr[j] = expf(32.f * er[j] - 32.f) * invtau;
                }
            }
        }
    }
}

// ---------------------------------------------------------------------------
// normalize emb rows of g_U -> emb (fp32) + g_Ehi/g_Elo; sq computed here.
__global__ __launch_bounds__(256)
void norm_emb(float* __restrict__ emb, int M) {
    int row  = blockIdx.x * 8 + (threadIdx.x >> 5);
    int lane = threadIdx.x & 31;
    if (row >= M) return;
    const float4* u = reinterpret_cast<const float4*>(&g_U[(size_t)row * DD]);
    float4 v[6];
    float sq = 0.f;
#pragma unroll
    for (int i = 0; i < 6; ++i) {
        v[i] = u[lane + 32 * i];
        sq += v[i].x * v[i].x + v[i].y * v[i].y + v[i].z * v[i].z + v[i].w * v[i].w;
    }
#pragma unroll
    for (int o = 16; o; o >>= 1) sq += __shfl_xor_sync(0xffffffffu, sq, o);
    float inv = 1.f / fmaxf(sqrtf(sq), 1e-12f);
    float4* of = reinterpret_cast<float4*>(&emb[(size_t)row * DD]);
    uint2*  eh = reinterpret_cast<uint2*>(&g_Ehi[(size_t)row * DD]);
    uint2*  el = reinterpret_cast<uint2*>(&g_Elo[(size_t)row * DD]);
#pragma unroll
    for (int i = 0; i < 6; ++i) {
        float4 w = v[i];
        w.x *= inv; w.y *= inv; w.z *= inv; w.w *= inv;
        of[lane + 32 * i] = w;
        __nv_bfloat16 h0 = __float2bfloat16(w.x), h1 = __float2bfloat16(w.y);
        __nv_bfloat16 h2 = __float2bfloat16(w.z), h3 = __float2bfloat16(w.w);
        eh[lane + 32 * i] = make_uint2(pack2bf(w.x, w.y), pack2bf(w.z, w.w));
        el[lane + 32 * i] = make_uint2(
            pack2bf(w.x - __bfloat162float(h0), w.y - __bfloat162float(h1)),
            pack2bf(w.z - __bfloat162float(h2), w.w - __bfloat162float(h3)));
    }
}

// normalize support rows of g_Uh (fp16), scatter-add into g_proto[label]
__global__ __launch_bounds__(256)
void norm_proto(const int* __restrict__ lab, int N) {
    int row  = blockIdx.x * 8 + (threadIdx.x >> 5);
    int lane = threadIdx.x & 31;
    if (row >= N) return;
    const uint4* u = reinterpret_cast<const uint4*>(&g_Uh[(size_t)row * DD]);
    float vv[24];
    float sq = 0.f;
#pragma unroll
    for (int i = 0; i < 3; ++i) {
        uint4 q = u[lane + 32 * i];              // 8 halves
        const uint32_t w[4] = {q.x, q.y, q.z, q.w};
#pragma unroll
        for (int j = 0; j < 4; ++j) {
            float2 f = __half22float2(*reinterpret_cast<const __half2*>(&w[j]));
            vv[i * 8 + 2 * j]     = f.x;
            vv[i * 8 + 2 * j + 1] = f.y;
            sq += f.x * f.x + f.y * f.y;
        }
    }
#pragma unroll
    for (int o = 16; o; o >>= 1) sq += __shfl_xor_sync(0xffffffffu, sq, o);
    float inv = 1.f / fmaxf(sqrtf(sq), 1e-12f);
    int lb = lab[row];
    float* dst = &g_proto[(size_t)lb * DD];
#pragma unroll
    for (int i = 0; i < 3; ++i) {
        int col = (lane + 32 * i) * 8;
#pragma unroll
        for (int t = 0; t < 2; ++t) {
            float a = vv[i * 8 + 4 * t]     * inv;
            float b = vv[i * 8 + 4 * t + 1] * inv;
            float c = vv[i * 8 + 4 * t + 2] * inv;
            float d = vv[i * 8 + 4 * t + 3] * inv;
            asm volatile("red.global.add.v4.f32 [%0], {%1,%2,%3,%4};"
                         :: "l"(dst + col + 4 * t), "f"(a), "f"(b), "f"(c), "f"(d)
                         : "memory");
        }
    }
}

// prototype sums -> normalized bf16 hi/lo (rows >= Cn stay zero-init)
__global__ void proto_norm_kernel(int Cn) {
    int c   = blockIdx.x;
    int tid = threadIdx.x;
    if (c >= Cn) return;
    const float* row = &g_proto[(size_t)c * DD];
    float ss = 0.f;
    for (int i = tid; i < DD; i += 256) { float v = row[i]; ss += v * v; }
    __shared__ float red[8];
#pragma unroll
    for (int o = 16; o; o >>= 1) ss += __shfl_xor_sync(0xffffffffu, ss, o);
    if ((tid & 31) == 0) red[tid >> 5] = ss;
    __syncthreads();
    if (tid < 8) {
        ss = red[tid];
#pragma unroll
        for (int o = 4; o; o >>= 1) ss += __shfl_xor_sync(0xffu, ss, o);
        if (tid == 0) red[0] = ss;
    }
    __syncthreads();
    float inv = (g_cnt[c] > 0.f) ? 1.f / fmaxf(sqrtf(red[0]), 1e-12f) : 0.f;
    for (int i = tid; i < DD; i += 256) {
        float v = row[i] * inv;
        __nv_bfloat16 h = __float2bfloat16(v);
        g_Phi[(size_t)c * DD + i] = h;
        g_Plo[(size_t)c * DD + i] = __float2bfloat16(v - __bfloat162float(h));
    }
}

// ---------------------------------------------------------------------------
__global__ void softmax_kernel(const float* __restrict__ L,
                               float* __restrict__ P, int Cn)
{
    __shared__ float buf[1024];
    __shared__ float red[8];
    int row = blockIdx.x, tid = threadIdx.x;
    const float* lr = L + (size_t)row * Cn;

    float mx = -1e30f;
    for (int i = tid; i < Cn; i += 256) { float v = lr[i]; buf[i] = v; mx = fmaxf(mx, v); }
#pragma unroll
    for (int o = 16; o; o >>= 1) mx = fmaxf(mx, __shfl_xor_sync(0xffffffffu, mx, o));
    if ((tid & 31) == 0) red[tid >> 5] = mx;
    __syncthreads();
    if (tid < 8) {
        mx = red[tid];
#pragma unroll
        for (int o = 4; o; o >>= 1) mx = fmaxf(mx, __shfl_xor_sync(0xffu, mx, o));
        if (tid == 0) red[0] = mx;
    }
    __syncthreads();
    mx = red[0];
    __syncthreads();

    float sm = 0.f;
    for (int i = tid; i < Cn; i += 256) { float e = expf(buf[i] - mx); buf[i] = e; sm += e; }
#pragma unroll
    for (int o = 16; o; o >>= 1) sm += __shfl_xor_sync(0xffffffffu, sm, o);
    if ((tid & 31) == 0) red[tid >> 5] = sm;
    __syncthreads();
    if (tid < 8) {
        sm = red[tid];
#pragma unroll
        for (int o = 4; o; o >>= 1) sm += __shfl_xor_sync(0xffu, sm, o);
        if (tid == 0) red[0] = sm;
    }
    __syncthreads();
    float inv = 1.f / red[0];
    for (int i = tid; i < Cn; i += 256)
        P[(size_t)row * Cn + i] = buf[i] * inv;
}

// ---------------------------------------------------------------------------
extern "C" void kernel_launch(void* const* d_in, const int* in_sizes, int n_in,
                              void* d_out, int out_size)
{
    const float* x   = (const float*)d_in[0];
    const float* sf  = (const float*)d_in[1];
    const int*   lab = (const int*)d_in[2];
    const float* W   = (const float*)d_in[3];
    const float* b   = (const float*)d_in[4];
    (void)n_in;

    const int D = in_sizes[4];               // 768
    const int B = in_sizes[0] / D;           // 8192
    const int N = in_sizes[2];               // 100000
    const long long C =
        ((long long)out_size - (long long)B * D) / (2LL * B);   // 1000

    float* predicts = (float*)d_out;
    float* logits   = predicts + (long long)B * C;
    float* emb      = logits + (long long)B * C;

    static __nv_bfloat16 *pAhi = nullptr, *pAlo = nullptr, *pWhi = nullptr, *pWlo = nullptr;
    static __nv_bfloat16 *pEhi = nullptr, *pElo = nullptr, *pPhi = nullptr, *pPlo = nullptr;
    static bool init = false;
    if (!init) {
        cudaGetSymbolAddress((void**)&pAhi, g_Ahi);
        cudaGetSymbolAddress((void**)&pAlo, g_Alo);
        cudaGetSymbolAddress((void**)&pWhi, g_Whi);
        cudaGetSymbolAddress((void**)&pWlo, g_Wlo);
        cudaGetSymbolAddress((void**)&pEhi, g_Ehi);
        cudaGetSymbolAddress((void**)&pElo, g_Elo);
        cudaGetSymbolAddress((void**)&pPhi, g_Phi);
        cudaGetSymbolAddress((void**)&pPlo, g_Plo);
        cudaFuncSetAttribute((const void*)gemm_kernel<0, 3, false>,
                             cudaFuncAttributeMaxDynamicSharedMemorySize, Cfg<3>::SMEM);
        cudaFuncSetAttribute((const void*)gemm_kernel<0, 2, true>,
                             cudaFuncAttributeMaxDynamicSharedMemorySize, Cfg<2>::SMEM);
        cudaFuncSetAttribute((const void*)gemm_kernel<1, 3, false>,
                             cudaFuncAttributeMaxDynamicSharedMemorySize, Cfg<3>::SMEM);
        init = true;
    }

    // launch order chosen so the big support GEMM sits at the ncu capture slot
    zero_kernel<<<(CMAX * DD + 255) / 256, 256>>>();                    // 0
    prep_w<<<(DD * DD + 255) / 256, 256>>>(W);                          // 1
    {
        size_t tot = ((size_t)ROWS_PAD * DD) / 4;
        prep_x<<<(int)((tot + 255) / 256), 256>>>(x, sf, B, N);         // 2
    }
    // support adapter GEMM (rows B..B+N-1): 2-term split, fp16 U        // 3
    {
        dim3 g(DD / 128, (N + 127) / 128);
        gemm_kernel<0, 2, true><<<g, 256, Cfg<2>::SMEM>>>(
            pAhi, nullptr, pWhi, pWlo, sf, b, nullptr, B, B + N, B, DD);
    }
    // emb adapter GEMM (rows 0..B-1): 3-term split, fp32 U              // 4
    {
        dim3 g(DD / 128, B / 128);
        gemm_kernel<0, 3, false><<<g, 256, Cfg<3>::SMEM>>>(
            pAhi, pAlo, pWhi, pWlo, x, b, nullptr, 0, B, 0, DD);
    }
    count_kernel<<<200, 256>>>(lab, N);                                 // 5
    norm_emb<<<(B + 7) / 8, 256>>>(emb, B);                             // 6
    norm_proto<<<(N + 7) / 8, 256>>>(lab, N);                           // 7
    proto_norm_kernel<<<(int)C, 256>>>((int)C);                         // 8
    // cosine logits GEMM: emb (hi/lo) x proto (hi/lo), 3-term           // 9
    {
        dim3 g(NPAD / 128, B / 128);
        gemm_kernel<1, 3, false><<<g, 256, Cfg<3>::SMEM>>>(
            pEhi, pElo, pPhi, pPlo, nullptr, nullptr, logits, 0, B, 0, (int)C);
    }
    softmax_kernel<<<B, 256>>>(logits, predicts, (int)C);               // 10
}

// round 9
// speedup vs baseline: 4.3233x; 1.1775x over previous
#include <cuda_runtime.h>
#include <cuda_bf16.h>
#include <cuda_fp16.h>
#include <math.h>
#include <stdint.h>

// ---------------------------------------------------------------------------
// UnifiedZipAdapterF round 9: raise HMMA issue density (tensor was 48.3%).
//   - term-outer MMA ordering (breaks same-accumulator back-to-back RAW)
//   - 2-term support GEMM: 2 stages x 48KB smem + __launch_bounds__(256,2)
//     => 2 CTAs/SM, 4 warps/SMSP
// ---------------------------------------------------------------------------

#define DD        768
#define CMAX      1000
#define NPAD      1024
#define BMAX      8192
#define NSUP_PAD  100096     // ceil(100000/128)*128
#define ROWS_PAD  (BMAX + NSUP_PAD)

// ---- static device scratch (no allocations allowed) ----
__device__ __nv_bfloat16 g_Ahi[(size_t)ROWS_PAD * DD];
__device__ __nv_bfloat16 g_Alo[(size_t)BMAX * DD];      // only emb rows need lo
__device__ float         g_U[(size_t)BMAX * DD];        // emb-row adapter out (fp32)
__device__ __half        g_Uh[(size_t)NSUP_PAD * DD];   // support-row adapter out (fp16)
__device__ __nv_bfloat16 g_Whi[DD * DD];
__device__ __nv_bfloat16 g_Wlo[DD * DD];
__device__ float         g_proto[CMAX * DD];
__device__ float         g_cnt[CMAX];
__device__ __nv_bfloat16 g_Ehi[(size_t)BMAX * DD];
__device__ __nv_bfloat16 g_Elo[(size_t)BMAX * DD];
__device__ __nv_bfloat16 g_Phi[(size_t)NPAD * DD];      // pad rows stay zero-init
__device__ __nv_bfloat16 g_Plo[(size_t)NPAD * DD];

// ---------------------------------------------------------------------------
__device__ __forceinline__ uint32_t s2u(const void* p) {
    uint32_t a;
    asm("{ .reg .u64 t; cvta.to.shared.u64 t, %1; cvt.u32.u64 %0, t; }"
        : "=r"(a) : "l"(p));
    return a;
}
__device__ __forceinline__ uint32_t pack2bf(float a, float b) {
    __nv_bfloat162 t = __floats2bfloat162_rn(a, b);
    return *reinterpret_cast<uint32_t*>(&t);
}
__device__ __forceinline__ uint32_t pack2h(float a, float b) {
    __half2 t = __floats2half2_rn(a, b);
    return *reinterpret_cast<uint32_t*>(&t);
}
__device__ __forceinline__ void cp16(uint32_t d, const void* s) {
    asm volatile("cp.async.cg.shared.global [%0], [%1], 16;" :: "r"(d), "l"(s));
}

#define LDSM_X4(R0, R1, R2, R3, ADDR)                                          \
    asm volatile("ldmatrix.sync.aligned.m8n8.x4.shared.b16 {%0,%1,%2,%3}, [%4];" \
        : "=r"(R0), "=r"(R1), "=r"(R2), "=r"(R3) : "r"(ADDR))
#define MMA_BF16(D, A, B)                                                      \
    asm volatile("mma.sync.aligned.m16n8k16.row.col.f32.bf16.bf16.f32 "        \
        "{%0,%1,%2,%3}, {%4,%5,%6,%7}, {%8,%9}, {%0,%1,%2,%3};"                \
        : "+f"((D)[0]), "+f"((D)[1]), "+f"((D)[2]), "+f"((D)[3])               \
        : "r"((A)[0]), "r"((A)[1]), "r"((A)[2]), "r"((A)[3]),                  \
          "r"((B)[0]), "r"((B)[1]))

// ---------------------------------------------------------------------------
// prep kernels
// ---------------------------------------------------------------------------
__global__ void zero_kernel() {
    int i = blockIdx.x * blockDim.x + threadIdx.x;
    if (i < CMAX * DD) g_proto[i] = 0.f;
    if (i < CMAX)      g_cnt[i]   = 0.f;
}

__global__ void count_kernel(const int* __restrict__ lab, int N) {
    __shared__ int c[CMAX];
    int tid = threadIdx.x;
    for (int i = tid; i < CMAX; i += 256) c[i] = 0;
    __syncthreads();
    for (int i = blockIdx.x * 256 + tid; i < N; i += gridDim.x * 256)
        atomicAdd(&c[lab[i]], 1);
    __syncthreads();
    for (int i = tid; i < CMAX; i += 256)
        if (c[i]) atomicAdd(&g_cnt[i], (float)c[i]);
}

__global__ void prep_w(const float* __restrict__ W) {
    int i = blockIdx.x * blockDim.x + threadIdx.x;
    if (i < DD * DD) {
        float v = W[i];
        __nv_bfloat16 h = __float2bfloat16(v);
        g_Whi[i] = h;
        g_Wlo[i] = __float2bfloat16(v - __bfloat162float(h));
    }
}

// [x ; sf ; zero-pad] rows -> g_Ahi (all) / g_Alo (emb rows only)
__global__ void prep_x(const float* __restrict__ x, const float* __restrict__ sf,
                       int Brows, int Nrows) {
    size_t i = ((size_t)blockIdx.x * blockDim.x + threadIdx.x) * 4;
    if (i >= (size_t)ROWS_PAD * DD) return;
    size_t r = i / DD;
    float4 v = make_float4(0.f, 0.f, 0.f, 0.f);
    if (r < (size_t)Brows)
        v = *reinterpret_cast<const float4*>(&x[i]);
    else if (r < (size_t)(Brows + Nrows))
        v = *reinterpret_cast<const float4*>(&sf[i - (size_t)Brows * DD]);
    float vv[4] = {v.x, v.y, v.z, v.w};
    uint32_t hi[2], lo[2];
#pragma unroll
    for (int j = 0; j < 2; ++j) {
        float a0 = vv[2 * j], a1 = vv[2 * j + 1];
        __nv_bfloat16 h0 = __float2bfloat16(a0);
        __nv_bfloat16 h1 = __float2bfloat16(a1);
        hi[j] = pack2bf(a0, a1);
        lo[j] = pack2bf(a0 - __bfloat162float(h0), a1 - __bfloat162float(h1));
    }
    *reinterpret_cast<uint2*>(&g_Ahi[i]) = make_uint2(hi[0], hi[1]);
    if (r < (size_t)Brows)
        *reinterpret_cast<uint2*>(&g_Alo[i]) = make_uint2(lo[0], lo[1]);
}

// ---------------------------------------------------------------------------
// GEMM core: 128x128 tile, 8 warps, warp tile 64x32, BK=64.
// TERMS==3: 3 stages x 64KB (1 CTA/SM).  TERMS==2: 2 stages x 48KB (2 CTA/SM).
// ---------------------------------------------------------------------------
template <int TERMS>
struct Cfg {
    static const int A_SZ  = (TERMS == 3) ? 32768 : 16384;
    static const int STAGE = A_SZ + 32768;
    static const int NS    = (TERMS == 3) ? 3 : 2;
    static const int SMEM  = NS * STAGE;    // 3-term: 192KB, 2-term: 96KB
    static const int MINB  = (TERMS == 3) ? 1 : 2;
};

template <int TERMS>
__device__ __forceinline__ void fill_part(
    const __nv_bfloat16* __restrict__ Ah, const __nv_bfloat16* __restrict__ Al,
    const __nv_bfloat16* __restrict__ Bh, const __nv_bfloat16* __restrict__ Bl,
    int arow0, int brow0, int kb, uint32_t sbase, int tid, int p)
{
    const int A_SZ = Cfg<TERMS>::A_SZ;
    int ch = tid + p * 256;
    int r = ch >> 3, c = ch & 7;
    uint32_t off = (uint32_t)(r * 128 + ((c ^ (r & 7)) << 4));
    size_t ai = (size_t)(arow0 + r) * DD + kb + c * 8;
    size_t bi = (size_t)(brow0 + r) * DD + kb + c * 8;
    cp16(sbase + off, Ah + ai);
    if (TERMS == 3) cp16(sbase + 16384 + off, Al + ai);
    cp16(sbase + A_SZ + off,         Bh + bi);
    cp16(sbase + A_SZ + 16384 + off, Bl + bi);
}

template <int TERMS>
__device__ __forceinline__ void compute_k16(uint32_t sb, int kk, int wm, int wn,
                                            int lane, float (&acc)[4][4][4])
{
    const uint32_t aH = sb, aL = sb + 16384;
    const uint32_t bH = sb + Cfg<TERMS>::A_SZ, bL = bH + 16384;
    const int t = lane >> 3, li = lane & 7;
    uint32_t ah[4][4], al[4][4], bh[4][2], bl[4][2];
#pragma unroll
    for (int mi = 0; mi < 4; ++mi) {
        int r  = wm * 64 + mi * 16 + ((t & 1) << 3) + li;
        int cc = (kk << 1) + (t >> 1);
        uint32_t off = (uint32_t)(r * 128 + ((cc ^ (r & 7)) << 4));
        LDSM_X4(ah[mi][0], ah[mi][1], ah[mi][2], ah[mi][3], aH + off);
        if (TERMS == 3)
            LDSM_X4(al[mi][0], al[mi][1], al[mi][2], al[mi][3], aL + off);
    }
#pragma unroll
    for (int p = 0; p < 2; ++p) {
        int n  = wn * 32 + p * 16 + ((t >> 1) << 3) + li;
        int cc = (kk << 1) + (t & 1);
        uint32_t off = (uint32_t)(n * 128 + ((cc ^ (n & 7)) << 4));
        LDSM_X4(bh[2 * p][0], bh[2 * p][1], bh[2 * p + 1][0], bh[2 * p + 1][1], bH + off);
        LDSM_X4(bl[2 * p][0], bl[2 * p][1], bl[2 * p + 1][0], bl[2 * p + 1][1], bL + off);
    }
    // term-outer ordering: 16 independent accumulators between dependent MMAs
#pragma unroll
    for (int mi = 0; mi < 4; ++mi)
#pragma unroll
        for (int nj = 0; nj < 4; ++nj)
            MMA_BF16(acc[mi][nj], ah[mi], bh[nj]);
#pragma unroll
    for (int mi = 0; mi < 4; ++mi)
#pragma unroll
        for (int nj = 0; nj < 4; ++nj)
            MMA_BF16(acc[mi][nj], ah[mi], bl[nj]);
    if (TERMS == 3) {
#pragma unroll
        for (int mi = 0; mi < 4; ++mi)
#pragma unroll
            for (int nj = 0; nj < 4; ++nj)
                MMA_BF16(acc[mi][nj], al[mi], bh[nj]);
    }
}

// EPI 0: adapter (bias+silu+residual -> U fp32 or fp16)
// EPI 1: cosine logits (exp(32c-32)/tau -> Lout)
template <int EPI, int TERMS, bool HALF_U>
__global__ __launch_bounds__(256, Cfg<TERMS>::MINB)
void gemm_kernel(const __nv_bfloat16* __restrict__ Ah, const __nv_bfloat16* __restrict__ Al,
                 const __nv_bfloat16* __restrict__ Bh, const __nv_bfloat16* __restrict__ Bl,
                 const float* __restrict__ Xres, const float* __restrict__ bias,
                 float* __restrict__ Lout,
                 int aRowBase0, int rowEnd, int inputBase, int Cn)
{
    const int NS    = Cfg<TERMS>::NS;
    const int STAGE = Cfg<TERMS>::STAGE;
    extern __shared__ __align__(16) char smem[];
    const int tid  = threadIdx.x;
    const int lane = tid & 31, wid = tid >> 5;
    const int wm = wid >> 2, wn = wid & 3;
    const int nb0   = blockIdx.x * 128;
    const int arow0 = aRowBase0 + blockIdx.y * 128;
    const uint32_t sb = s2u(smem);

    float acc[4][4][4] = {};

#pragma unroll
    for (int s = 0; s < NS - 1; ++s) {
#pragma unroll
        for (int p = 0; p < 4; ++p)
            fill_part<TERMS>(Ah, Al, Bh, Bl, arow0, nb0, s * 64, sb + s * STAGE, tid, p);
        asm volatile("cp.async.commit_group;");
    }

#pragma unroll 1
    for (int s = 0; s < 12; ++s) {
        asm volatile("cp.async.wait_group %0;" :: "n"(Cfg<TERMS>::NS - 2));
        __syncthreads();
        const uint32_t cs = sb + (s % NS) * STAGE;
        const uint32_t fs = sb + ((s + NS - 1) % NS) * STAGE;
        const int fkb = (s + NS - 1) * 64;
        const bool df = (s + NS - 1) < 12;
#pragma unroll
        for (int kk = 0; kk < 4; ++kk) {
            if (df) fill_part<TERMS>(Ah, Al, Bh, Bl, arow0, nb0, fkb, fs, tid, kk);
            compute_k16<TERMS>(cs, kk, wm, wn, lane, acc);
        }
        asm volatile("cp.async.commit_group;");   // empty group when !df
    }
    __syncthreads();

    // ---- stage accumulators through smem ----
    float* es = reinterpret_cast<float*>(smem);   // [128][132]
#pragma unroll
    for (int mi = 0; mi < 4; ++mi)
#pragma unroll
        for (int nj = 0; nj < 4; ++nj) {
            int r0 = wm * 64 + mi * 16 + (lane >> 2);
            int c0 = wn * 32 + nj * 8 + (lane & 3) * 2;
            es[r0 * 132 + c0]           = acc[mi][nj][0];
            es[r0 * 132 + c0 + 1]       = acc[mi][nj][1];
            es[(r0 + 8) * 132 + c0]     = acc[mi][nj][2];
            es[(r0 + 8) * 132 + c0 + 1] = acc[mi][nj][3];
        }
    __syncthreads();

    const int row  = tid >> 1;
    const int half = tid & 1;
    const int arow = arow0 + row;
    const bool valid = (arow < rowEnd);
    const float* er = es + row * 132 + half * 64;

    if (EPI == 0) {
        if (valid) {
            const int lrow = arow - inputBase;
            const float* xr = Xres + (size_t)lrow * DD + nb0 + half * 64;
            const float* br = bias + nb0 + half * 64;
            float*  urf = HALF_U ? nullptr
                                 : (g_U + (size_t)lrow * DD + nb0 + half * 64);
            __half* urh = HALF_U ? (g_Uh + (size_t)lrow * DD + nb0 + half * 64)
                                 : nullptr;
#pragma unroll
            for (int j = 0; j < 64; j += 4) {
                float4 v  = *reinterpret_cast<const float4*>(er + j);
                float4 bb = *reinterpret_cast<const float4*>(br + j);
                float4 xv = *reinterpret_cast<const float4*>(xr + j);
                float h0 = v.x + bb.x, h1 = v.y + bb.y;
                float h2 = v.z + bb.z, h3 = v.w + bb.w;
                float4 o;
                o.x = h0 / (1.f + expf(-h0)) + xv.x;
                o.y = h1 / (1.f + expf(-h1)) + xv.y;
                o.z = h2 / (1.f + expf(-h2)) + xv.z;
                o.w = h3 / (1.f + expf(-h3)) + xv.w;
                if (HALF_U) {
                    uint2 pk = make_uint2(pack2h(o.x, o.y), pack2h(o.z, o.w));
                    *reinterpret_cast<uint2*>(urh + j) = pk;
                } else {
                    *reinterpret_cast<float4*>(urf + j) = o;
                }
            }
        }
    } else {
        if (valid) {
            const float invtau = 1.0f / 0.11f;
            float* lr = Lout + (size_t)arow * Cn + nb0 + half * 64;
            int cbase = nb0 + half * 64;
            if (cbase + 64 <= Cn) {
#pragma unroll
                for (int j = 0; j < 64; j += 4) {
                    float4 v = *reinterpret_cast<const float4*>(er + j);
                    float4 o;
                    o.x = expf(32.f * v.x - 32.f) * invtau;
                    o.y = expf(32.f * v.y - 32.f) * invtau;
                    o.z = expf(32.f * v.z - 32.f) * invtau;
                    o.w = expf(32.f * v.w - 32.f) * invtau;
                    *reinterpret_cast<float4*>(lr + j) = o;
                }
            } else {
                for (int j = 0; j < 64; ++j) {
                    int c = cbase + j;
                    if (c < Cn) lr[j] = expf(32.f * er[j] - 32.f) * invtau;
                }
            }
        }
    }
}

// ---------------------------------------------------------------------------
// normalize emb rows of g_U -> emb (fp32) + g_Ehi/g_Elo; sq computed here.
__global__ __launch_bounds__(256)
void norm_emb(float* __restrict__ emb, int M) {
    int row  = blockIdx.x * 8 + (threadIdx.x >> 5);
    int lane = threadIdx.x & 31;
    if (row >= M) return;
    const float4* u = reinterpret_cast<const float4*>(&g_U[(size_t)row * DD]);
    float4 v[6];
    float sq = 0.f;
#pragma unroll
    for (int i = 0; i < 6; ++i) {
        v[i] = u[lane + 32 * i];
        sq += v[i].x * v[i].x + v[i].y * v[i].y + v[i].z * v[i].z + v[i].w * v[i].w;
    }
#pragma unroll
    for (int o = 16; o; o >>= 1) sq += __shfl_xor_sync(0xffffffffu, sq, o);
    float inv = 1.f / fmaxf(sqrtf(sq), 1e-12f);
    float4* of = reinterpret_cast<float4*>(&emb[(size_t)row * DD]);
    uint2*  eh = reinterpret_cast<uint2*>(&g_Ehi[(size_t)row * DD]);
    uint2*  el = reinterpret_cast<uint2*>(&g_Elo[(size_t)row * DD]);
#pragma unroll
    for (int i = 0; i < 6; ++i) {
        float4 w = v[i];
        w.x *= inv; w.y *= inv; w.z *= inv; w.w *= inv;
        of[lane + 32 * i] = w;
        __nv_bfloat16 h0 = __float2bfloat16(w.x), h1 = __float2bfloat16(w.y);
        __nv_bfloat16 h2 = __float2bfloat16(w.z), h3 = __float2bfloat16(w.w);
        eh[lane + 32 * i] = make_uint2(pack2bf(w.x, w.y), pack2bf(w.z, w.w));
        el[lane + 32 * i] = make_uint2(
            pack2bf(w.x - __bfloat162float(h0), w.y - __bfloat162float(h1)),
            pack2bf(w.z - __bfloat162float(h2), w.w - __bfloat162float(h3)));
    }
}

// normalize support rows of g_Uh (fp16), scatter-add into g_proto[label]
__global__ __launch_bounds__(256)
void norm_proto(const int* __restrict__ lab, int N) {
    int row  = blockIdx.x * 8 + (threadIdx.x >> 5);
    int lane = threadIdx.x & 31;
    if (row >= N) return;
    const uint4* u = reinterpret_cast<const uint4*>(&g_Uh[(size_t)row * DD]);
    float vv[24];
    float sq = 0.f;
#pragma unroll
    for (int i = 0; i < 3; ++i) {
        uint4 q = u[lane + 32 * i];              // 8 halves
        const uint32_t w[4] = {q.x, q.y, q.z, q.w};
#pragma unroll
        for (int j = 0; j < 4; ++j) {
            float2 f = __half22float2(*reinterpret_cast<const __half2*>(&w[j]));
            vv[i * 8 + 2 * j]     = f.x;
            vv[i * 8 + 2 * j + 1] = f.y;
            sq += f.x * f.x + f.y * f.y;
        }
    }
#pragma unroll
    for (int o = 16; o; o >>= 1) sq += __shfl_xor_sync(0xffffffffu, sq, o);
    float inv = 1.f / fmaxf(sqrtf(sq), 1e-12f);
    int lb = lab[row];
    float* dst = &g_proto[(size_t)lb * DD];
#pragma unroll
    for (int i = 0; i < 3; ++i) {
        int col = (lane + 32 * i) * 8;
#pragma unroll
        for (int t = 0; t < 2; ++t) {
            float a = vv[i * 8 + 4 * t]     * inv;
            float b = vv[i * 8 + 4 * t + 1] * inv;
            float c = vv[i * 8 + 4 * t + 2] * inv;
            float d = vv[i * 8 + 4 * t + 3] * inv;
            asm volatile("red.global.add.v4.f32 [%0], {%1,%2,%3,%4};"
                         :: "l"(dst + col + 4 * t), "f"(a), "f"(b), "f"(c), "f"(d)
                         : "memory");
        }
    }
}

// prototype sums -> normalized bf16 hi/lo (rows >= Cn stay zero-init)
__global__ void proto_norm_kernel(int Cn) {
    int c   = blockIdx.x;
    int tid = threadIdx.x;
    if (c >= Cn) return;
    const float* row = &g_proto[(size_t)c * DD];
    float ss = 0.f;
    for (int i = tid; i < DD; i += 256) { float v = row[i]; ss += v * v; }
    __shared__ float red[8];
#pragma unroll
    for (int o = 16; o; o >>= 1) ss += __shfl_xor_sync(0xffffffffu, ss, o);
    if ((tid & 31) == 0) red[tid >> 5] = ss;
    __syncthreads();
    if (tid < 8) {
        ss = red[tid];
#pragma unroll
        for (int o = 4; o; o >>= 1) ss += __shfl_xor_sync(0xffu, ss, o);
        if (tid == 0) red[0] = ss;
    }
    __syncthreads();
    float inv = (g_cnt[c] > 0.f) ? 1.f / fmaxf(sqrtf(red[0]), 1e-12f) : 0.f;
    for (int i = tid; i < DD; i += 256) {
        float v = row[i] * inv;
        __nv_bfloat16 h = __float2bfloat16(v);
        g_Phi[(size_t)c * DD + i] = h;
        g_Plo[(size_t)c * DD + i] = __float2bfloat16(v - __bfloat162float(h));
    }
}

// ---------------------------------------------------------------------------
__global__ void softmax_kernel(const float* __restrict__ L,
                               float* __restrict__ P, int Cn)
{
    __shared__ float buf[1024];
    __shared__ float red[8];
    int row = blockIdx.x, tid = threadIdx.x;
    const float* lr = L + (size_t)row * Cn;

    float mx = -1e30f;
    for (int i = tid; i < Cn; i += 256) { float v = lr[i]; buf[i] = v; mx = fmaxf(mx, v); }
#pragma unroll
    for (int o = 16; o; o >>= 1) mx = fmaxf(mx, __shfl_xor_sync(0xffffffffu, mx, o));
    if ((tid & 31) == 0) red[tid >> 5] = mx;
    __syncthreads();
    if (tid < 8) {
        mx = red[tid];
#pragma unroll
        for (int o = 4; o; o >>= 1) mx = fmaxf(mx, __shfl_xor_sync(0xffu, mx, o));
        if (tid == 0) red[0] = mx;
    }
    __syncthreads();
    mx = red[0];
    __syncthreads();

    float sm = 0.f;
    for (int i = tid; i < Cn; i += 256) { float e = expf(buf[i] - mx); buf[i] = e; sm += e; }
#pragma unroll
    for (int o = 16; o; o >>= 1) sm += __shfl_xor_sync(0xffffffffu, sm, o);
    if ((tid & 31) == 0) red[tid >> 5] = sm;
    __syncthreads();
    if (tid < 8) {
        sm = red[tid];
#pragma unroll
        for (int o = 4; o; o >>= 1) sm += __shfl_xor_sync(0xffu, sm, o);
        if (tid == 0) red[0] = sm;
    }
    __syncthreads();
    float inv = 1.f / red[0];
    for (int i = tid; i < Cn; i += 256)
        P[(size_t)row * Cn + i] = buf[i] * inv;
}

// ---------------------------------------------------------------------------
extern "C" void kernel_launch(void* const* d_in, const int* in_sizes, int n_in,
                              void* d_out, int out_size)
{
    const float* x   = (const float*)d_in[0];
    const float* sf  = (const float*)d_in[1];
    const int*   lab = (const int*)d_in[2];
    const float* W   = (const float*)d_in[3];
    const float* b   = (const float*)d_in[4];
    (void)n_in;

    const int D = in_sizes[4];               // 768
    const int B = in_sizes[0] / D;           // 8192
    const int N = in_sizes[2];               // 100000
    const long long C =
        ((long long)out_size - (long long)B * D) / (2LL * B);   // 1000

    float* predicts = (float*)d_out;
    float* logits   = predicts + (long long)B * C;
    float* emb      = logits + (long long)B * C;

    static __nv_bfloat16 *pAhi = nullptr, *pAlo = nullptr, *pWhi = nullptr, *pWlo = nullptr;
    static __nv_bfloat16 *pEhi = nullptr, *pElo = nullptr, *pPhi = nullptr, *pPlo = nullptr;
    static bool init = false;
    if (!init) {
        cudaGetSymbolAddress((void**)&pAhi, g_Ahi);
        cudaGetSymbolAddress((void**)&pAlo, g_Alo);
        cudaGetSymbolAddress((void**)&pWhi, g_Whi);
        cudaGetSymbolAddress((void**)&pWlo, g_Wlo);
        cudaGetSymbolAddress((void**)&pEhi, g_Ehi);
        cudaGetSymbolAddress((void**)&pElo, g_Elo);
        cudaGetSymbolAddress((void**)&pPhi, g_Phi);
        cudaGetSymbolAddress((void**)&pPlo, g_Plo);
        cudaFuncSetAttribute((const void*)gemm_kernel<0, 3, false>,
                             cudaFuncAttributeMaxDynamicSharedMemorySize, Cfg<3>::SMEM);
        cudaFuncSetAttribute((const void*)gemm_kernel<0, 2, true>,
                             cudaFuncAttributeMaxDynamicSharedMemorySize, Cfg<2>::SMEM);
        cudaFuncSetAttribute((const void*)gemm_kernel<1, 3, false>,
                             cudaFuncAttributeMaxDynamicSharedMemorySize, Cfg<3>::SMEM);
        init = true;
    }

    zero_kernel<<<(CMAX * DD + 255) / 256, 256>>>();                    // 0
    prep_w<<<(DD * DD + 255) / 256, 256>>>(W);                          // 1
    {
        size_t tot = ((size_t)ROWS_PAD * DD) / 4;
        prep_x<<<(int)((tot + 255) / 256), 256>>>(x, sf, B, N);         // 2
    }
    // support adapter GEMM (rows B..B+N-1): 2-term split, fp16 U, 2 CTA/SM
    {
        dim3 g(DD / 128, (N + 127) / 128);
        gemm_kernel<0, 2, true><<<g, 256, Cfg<2>::SMEM>>>(
            pAhi, nullptr, pWhi, pWlo, sf, b, nullptr, B, B + N, B, DD);
    }
    // emb adapter GEMM (rows 0..B-1): 3-term split, fp32 U
    {
        dim3 g(DD / 128, B / 128);
        gemm_kernel<0, 3, false><<<g, 256, Cfg<3>::SMEM>>>(
            pAhi, pAlo, pWhi, pWlo, x, b, nullptr, 0, B, 0, DD);
    }
    count_kernel<<<200, 256>>>(lab, N);
    norm_emb<<<(B + 7) / 8, 256>>>(emb, B);
    norm_proto<<<(N + 7) / 8, 256>>>(lab, N);
    proto_norm_kernel<<<(int)C, 256>>>((int)C);
    // cosine logits GEMM: emb (hi/lo) x proto (hi/lo), 3-term
    {
        dim3 g(NPAD / 128, B / 128);
        gemm_kernel<1, 3, false><<<g, 256, Cfg<3>::SMEM>>>(
            pEhi, pElo, pPhi, pPlo, nullptr, nullptr, logits, 0, B, 0, (int)C);
    }
    softmax_kernel<<<B, 256>>>(logits, predicts, (int)C);
}

// round 10
// speedup vs baseline: 5.1775x; 1.1976x over previous
#include <cuda_runtime.h>
#include <cuda_bf16.h>
#include <cuda_fp16.h>
#include <math.h>
#include <stdint.h>

// ---------------------------------------------------------------------------
// UnifiedZipAdapterF round 10: support adapter GEMM in single-term fp16
// (fewer MMAs than bf16-2-term AND smaller error: 2^-10.4 vs 2^-9 dropped
// term, class-averaged x0.23). Emb/cos GEMMs stay bf16 3-term.
// ---------------------------------------------------------------------------

#define DD        768
#define CMAX      1000
#define NPAD      1024
#define BMAX      8192
#define NSUP_PAD  100096     // ceil(100000/128)*128
#define ROWS_PAD  (BMAX + NSUP_PAD)

// ---- static device scratch (no allocations allowed) ----
__device__ __nv_bfloat16 g_Ahi[(size_t)BMAX * DD];      // emb rows bf16-hi
__device__ __nv_bfloat16 g_Alo[(size_t)BMAX * DD];      // emb rows bf16-lo
__device__ __half        g_Ah16[(size_t)NSUP_PAD * DD]; // support rows fp16
__device__ float         g_U[(size_t)BMAX * DD];        // emb-row adapter out (fp32)
__device__ __half        g_Uh[(size_t)NSUP_PAD * DD];   // support-row adapter out (fp16)
__device__ __nv_bfloat16 g_Whi[DD * DD];
__device__ __nv_bfloat16 g_Wlo[DD * DD];
__device__ __half        g_Wh16[DD * DD];
__device__ float         g_proto[CMAX * DD];
__device__ float         g_cnt[CMAX];
__device__ __nv_bfloat16 g_Ehi[(size_t)BMAX * DD];
__device__ __nv_bfloat16 g_Elo[(size_t)BMAX * DD];
__device__ __nv_bfloat16 g_Phi[(size_t)NPAD * DD];      // pad rows stay zero-init
__device__ __nv_bfloat16 g_Plo[(size_t)NPAD * DD];

// ---------------------------------------------------------------------------
__device__ __forceinline__ uint32_t s2u(const void* p) {
    uint32_t a;
    asm("{ .reg .u64 t; cvta.to.shared.u64 t, %1; cvt.u32.u64 %0, t; }"
        : "=r"(a) : "l"(p));
    return a;
}
__device__ __forceinline__ uint32_t pack2bf(float a, float b) {
    __nv_bfloat162 t = __floats2bfloat162_rn(a, b);
    return *reinterpret_cast<uint32_t*>(&t);
}
__device__ __forceinline__ uint32_t pack2h(float a, float b) {
    __half2 t = __floats2half2_rn(a, b);
    return *reinterpret_cast<uint32_t*>(&t);
}
__device__ __forceinline__ void cp16(uint32_t d, const void* s) {
    asm volatile("cp.async.cg.shared.global [%0], [%1], 16;" :: "r"(d), "l"(s));
}

#define LDSM_X4(R0, R1, R2, R3, ADDR)                                          \
    asm volatile("ldmatrix.sync.aligned.m8n8.x4.shared.b16 {%0,%1,%2,%3}, [%4];" \
        : "=r"(R0), "=r"(R1), "=r"(R2), "=r"(R3) : "r"(ADDR))
#define MMA_BF16(D, A, B)                                                      \
    asm volatile("mma.sync.aligned.m16n8k16.row.col.f32.bf16.bf16.f32 "        \
        "{%0,%1,%2,%3}, {%4,%5,%6,%7}, {%8,%9}, {%0,%1,%2,%3};"                \
        : "+f"((D)[0]), "+f"((D)[1]), "+f"((D)[2]), "+f"((D)[3])               \
        : "r"((A)[0]), "r"((A)[1]), "r"((A)[2]), "r"((A)[3]),                  \
          "r"((B)[0]), "r"((B)[1]))
#define MMA_F16(D, A, B)                                                       \
    asm volatile("mma.sync.aligned.m16n8k16.row.col.f32.f16.f16.f32 "          \
        "{%0,%1,%2,%3}, {%4,%5,%6,%7}, {%8,%9}, {%0,%1,%2,%3};"                \
        : "+f"((D)[0]), "+f"((D)[1]), "+f"((D)[2]), "+f"((D)[3])               \
        : "r"((A)[0]), "r"((A)[1]), "r"((A)[2]), "r"((A)[3]),                  \
          "r"((B)[0]), "r"((B)[1]))

// ---------------------------------------------------------------------------
// prep kernels
// ---------------------------------------------------------------------------
__global__ void zero_kernel() {
    int i = blockIdx.x * blockDim.x + threadIdx.x;
    if (i < CMAX * DD) g_proto[i] = 0.f;
    if (i < CMAX)      g_cnt[i]   = 0.f;
}

__global__ void count_kernel(const int* __restrict__ lab, int N) {
    __shared__ int c[CMAX];
    int tid = threadIdx.x;
    for (int i = tid; i < CMAX; i += 256) c[i] = 0;
    __syncthreads();
    for (int i = blockIdx.x * 256 + tid; i < N; i += gridDim.x * 256)
        atomicAdd(&c[lab[i]], 1);
    __syncthreads();
    for (int i = tid; i < CMAX; i += 256)
        if (c[i]) atomicAdd(&g_cnt[i], (float)c[i]);
}

__global__ void prep_w(const float* __restrict__ W) {
    int i = blockIdx.x * blockDim.x + threadIdx.x;
    if (i < DD * DD) {
        float v = W[i];
        __nv_bfloat16 h = __float2bfloat16(v);
        g_Whi[i]  = h;
        g_Wlo[i]  = __float2bfloat16(v - __bfloat162float(h));
        g_Wh16[i] = __float2half(v);
    }
}

// emb rows -> g_Ahi/g_Alo (bf16 hi/lo); support rows (+pad) -> g_Ah16 (fp16)
__global__ void prep_x(const float* __restrict__ x, const float* __restrict__ sf,
                       int Brows, int Nrows) {
    size_t i = ((size_t)blockIdx.x * blockDim.x + threadIdx.x) * 4;
    if (i >= (size_t)ROWS_PAD * DD) return;
    size_t r = i / DD;
    if (r < (size_t)Brows) {
        float4 v = *reinterpret_cast<const float4*>(&x[i]);
        float vv[4] = {v.x, v.y, v.z, v.w};
        uint32_t hi[2], lo[2];
#pragma unroll
        for (int j = 0; j < 2; ++j) {
            float a0 = vv[2 * j], a1 = vv[2 * j + 1];
            __nv_bfloat16 h0 = __float2bfloat16(a0);
            __nv_bfloat16 h1 = __float2bfloat16(a1);
            hi[j] = pack2bf(a0, a1);
            lo[j] = pack2bf(a0 - __bfloat162float(h0), a1 - __bfloat162float(h1));
        }
        *reinterpret_cast<uint2*>(&g_Ahi[i]) = make_uint2(hi[0], hi[1]);
        *reinterpret_cast<uint2*>(&g_Alo[i]) = make_uint2(lo[0], lo[1]);
    } else {
        float4 v = make_float4(0.f, 0.f, 0.f, 0.f);
        if (r < (size_t)(Brows + Nrows))
            v = *reinterpret_cast<const float4*>(&sf[i - (size_t)Brows * DD]);
        size_t si = i - (size_t)Brows * DD;
        *reinterpret_cast<uint2*>(&g_Ah16[si]) =
            make_uint2(pack2h(v.x, v.y), pack2h(v.z, v.w));
    }
}

// ---------------------------------------------------------------------------
// GEMM core: 128x128 tile, 8 warps, warp tile 64x32, BK=64.
// TERMS==3: bf16 AhBh+AhBl+AlBh, 3 stages x 64KB, 1 CTA/SM.
// TERMS==1: fp16 single term,     3 stages x 32KB, 2 CTA/SM.
// ---------------------------------------------------------------------------
template <int TERMS>
struct Cfg {
    static const int A_SZ  = (TERMS == 3) ? 32768 : 16384;
    static const int B_SZ  = (TERMS == 1) ? 16384 : 32768;
    static const int STAGE = A_SZ + B_SZ;   // 3: 64KB, 1: 32KB
    static const int NS    = 3;
    static const int SMEM  = NS * STAGE;    // 3: 192KB, 1: 96KB
    static const int MINB  = (TERMS == 3) ? 1 : 2;
};

template <int TERMS>
__device__ __forceinline__ void fill_part(
    const __nv_bfloat16* __restrict__ Ah, const __nv_bfloat16* __restrict__ Al,
    const __nv_bfloat16* __restrict__ Bh, const __nv_bfloat16* __restrict__ Bl,
    int arow0, int brow0, int kb, uint32_t sbase, int tid, int p)
{
    const int A_SZ = Cfg<TERMS>::A_SZ;
    int ch = tid + p * 256;
    int r = ch >> 3, c = ch & 7;
    uint32_t off = (uint32_t)(r * 128 + ((c ^ (r & 7)) << 4));
    size_t ai = (size_t)(arow0 + r) * DD + kb + c * 8;
    size_t bi = (size_t)(brow0 + r) * DD + kb + c * 8;
    cp16(sbase + off, Ah + ai);
    if (TERMS == 3) cp16(sbase + 16384 + off, Al + ai);
    cp16(sbase + A_SZ + off, Bh + bi);
    if (TERMS >= 2) cp16(sbase + A_SZ + 16384 + off, Bl + bi);
}

template <int TERMS>
__device__ __forceinline__ void compute_k16(uint32_t sb, int kk, int wm, int wn,
                                            int lane, float (&acc)[4][4][4])
{
    const uint32_t aH = sb, aL = sb + 16384;
    const uint32_t bH = sb + Cfg<TERMS>::A_SZ, bL = bH + 16384;
    const int t = lane >> 3, li = lane & 7;
    uint32_t ah[4][4], al[4][4], bh[4][2], bl[4][2];
#pragma unroll
    for (int mi = 0; mi < 4; ++mi) {
        int r  = wm * 64 + mi * 16 + ((t & 1) << 3) + li;
        int cc = (kk << 1) + (t >> 1);
        uint32_t off = (uint32_t)(r * 128 + ((cc ^ (r & 7)) << 4));
        LDSM_X4(ah[mi][0], ah[mi][1], ah[mi][2], ah[mi][3], aH + off);
        if (TERMS == 3)
            LDSM_X4(al[mi][0], al[mi][1], al[mi][2], al[mi][3], aL + off);
    }
#pragma unroll
    for (int p = 0; p < 2; ++p) {
        int n  = wn * 32 + p * 16 + ((t >> 1) << 3) + li;
        int cc = (kk << 1) + (t & 1);
        uint32_t off = (uint32_t)(n * 128 + ((cc ^ (n & 7)) << 4));
        LDSM_X4(bh[2 * p][0], bh[2 * p][1], bh[2 * p + 1][0], bh[2 * p + 1][1], bH + off);
        if (TERMS >= 2)
            LDSM_X4(bl[2 * p][0], bl[2 * p][1], bl[2 * p + 1][0], bl[2 * p + 1][1], bL + off);
    }
    if (TERMS == 1) {
#pragma unroll
        for (int mi = 0; mi < 4; ++mi)
#pragma unroll
            for (int nj = 0; nj < 4; ++nj)
                MMA_F16(acc[mi][nj], ah[mi], bh[nj]);
        return;
    }
    // term-outer ordering: 16 independent accumulators between dependent MMAs
#pragma unroll
    for (int mi = 0; mi < 4; ++mi)
#pragma unroll
        for (int nj = 0; nj < 4; ++nj)
            MMA_BF16(acc[mi][nj], ah[mi], bh[nj]);
#pragma unroll
    for (int mi = 0; mi < 4; ++mi)
#pragma unroll
        for (int nj = 0; nj < 4; ++nj)
            MMA_BF16(acc[mi][nj], ah[mi], bl[nj]);
    if (TERMS == 3) {
#pragma unroll
        for (int mi = 0; mi < 4; ++mi)
#pragma unroll
            for (int nj = 0; nj < 4; ++nj)
                MMA_BF16(acc[mi][nj], al[mi], bh[nj]);
    }
}

// EPI 0: adapter (bias+silu+residual -> U fp32 or fp16)
// EPI 1: cosine logits (exp(32c-32)/tau -> Lout)
template <int EPI, int TERMS, bool HALF_U>
__global__ __launch_bounds__(256, Cfg<TERMS>::MINB)
void gemm_kernel(const __nv_bfloat16* __restrict__ Ah, const __nv_bfloat16* __restrict__ Al,
                 const __nv_bfloat16* __restrict__ Bh, const __nv_bfloat16* __restrict__ Bl,
                 const float* __restrict__ Xres, const float* __restrict__ bias,
                 float* __restrict__ Lout,
                 int aRowBase0, int rowEnd, int inputBase, int Cn)
{
    const int NS    = Cfg<TERMS>::NS;
    const int STAGE = Cfg<TERMS>::STAGE;
    extern __shared__ __align__(16) char smem[];
    const int tid  = threadIdx.x;
    const int lane = tid & 31, wid = tid >> 5;
    const int wm = wid >> 2, wn = wid & 3;
    const int nb0   = blockIdx.x * 128;
    const int arow0 = aRowBase0 + blockIdx.y * 128;
    const uint32_t sb = s2u(smem);

    float acc[4][4][4] = {};

#pragma unroll
    for (int s = 0; s < NS - 1; ++s) {
#pragma unroll
        for (int p = 0; p < 4; ++p)
            fill_part<TERMS>(Ah, Al, Bh, Bl, arow0, nb0, s * 64, sb + s * STAGE, tid, p);
        asm volatile("cp.async.commit_group;");
    }

#pragma unroll 1
    for (int s = 0; s < 12; ++s) {
        asm volatile("cp.async.wait_group %0;" :: "n"(Cfg<TERMS>::NS - 2));
        __syncthreads();
        const uint32_t cs = sb + (s % NS) * STAGE;
        const uint32_t fs = sb + ((s + NS - 1) % NS) * STAGE;
        const int fkb = (s + NS - 1) * 64;
        const bool df = (s + NS - 1) < 12;
#pragma unroll
        for (int kk = 0; kk < 4; ++kk) {
            if (df) fill_part<TERMS>(Ah, Al, Bh, Bl, arow0, nb0, fkb, fs, tid, kk);
            compute_k16<TERMS>(cs, kk, wm, wn, lane, acc);
        }
        asm volatile("cp.async.commit_group;");   // empty group when !df
    }
    __syncthreads();

    // ---- stage accumulators through smem ----
    float* es = reinterpret_cast<float*>(smem);   // [128][132]
#pragma unroll
    for (int mi = 0; mi < 4; ++mi)
#pragma unroll
        for (int nj = 0; nj < 4; ++nj) {
            int r0 = wm * 64 + mi * 16 + (lane >> 2);
            int c0 = wn * 32 + nj * 8 + (lane & 3) * 2;
            es[r0 * 132 + c0]           = acc[mi][nj][0];
            es[r0 * 132 + c0 + 1]       = acc[mi][nj][1];
            es[(r0 + 8) * 132 + c0]     = acc[mi][nj][2];
            es[(r0 + 8) * 132 + c0 + 1] = acc[mi][nj][3];
        }
    __syncthreads();

    const int row  = tid >> 1;
    const int half = tid & 1;
    const int arow = arow0 + row;
    const bool valid = (arow < rowEnd);
    const float* er = es + row * 132 + half * 64;

    if (EPI == 0) {
        if (valid) {
            const int lrow = arow - inputBase;
            const float* xr = Xres + (size_t)lrow * DD + nb0 + half * 64;
            const float* br = bias + nb0 + half * 64;
            float*  urf = HALF_U ? nullptr
                                 : (g_U + (size_t)lrow * DD + nb0 + half * 64);
            __half* urh = HALF_U ? (g_Uh + (size_t)lrow * DD + nb0 + half * 64)
                                 : nullptr;
#pragma unroll
            for (int j = 0; j < 64; j += 4) {
                float4 v  = *reinterpret_cast<const float4*>(er + j);
                float4 bb = *reinterpret_cast<const float4*>(br + j);
                float4 xv = *reinterpret_cast<const float4*>(xr + j);
                float h0 = v.x + bb.x, h1 = v.y + bb.y;
                float h2 = v.z + bb.z, h3 = v.w + bb.w;
                float4 o;
                o.x = h0 / (1.f + expf(-h0)) + xv.x;
                o.y = h1 / (1.f + expf(-h1)) + xv.y;
                o.z = h2 / (1.f + expf(-h2)) + xv.z;
                o.w = h3 / (1.f + expf(-h3)) + xv.w;
                if (HALF_U) {
                    uint2 pk = make_uint2(pack2h(o.x, o.y), pack2h(o.z, o.w));
                    *reinterpret_cast<uint2*>(urh + j) = pk;
                } else {
                    *reinterpret_cast<float4*>(urf + j) = o;
                }
            }
        }
    } else {
        if (valid) {
            const float invtau = 1.0f / 0.11f;
            float* lr = Lout + (size_t)arow * Cn + nb0 + half * 64;
            int cbase = nb0 + half * 64;
            if (cbase + 64 <= Cn) {
#pragma unroll
                for (int j = 0; j < 64; j += 4) {
                    float4 v = *reinterpret_cast<const float4*>(er + j);
                    float4 o;
                    o.x = expf(32.f * v.x - 32.f) * invtau;
                    o.y = expf(32.f * v.y - 32.f) * invtau;
                    o.z = expf(32.f * v.z - 32.f) * invtau;
                    o.w = expf(32.f * v.w - 32.f) * invtau;
                    *reinterpret_cast<float4*>(lr + j) = o;
                }
            } else {
                for (int j = 0; j < 64; ++j) {
                    int c = cbase + j;
                    if (c < Cn) lr[j] = expf(32.f * er[j] - 32.f) * invtau;
                }
            }
        }
    }
}

// ---------------------------------------------------------------------------
// normalize emb rows of g_U -> emb (fp32) + g_Ehi/g_Elo; sq computed here.
__global__ __launch_bounds__(256)
void norm_emb(float* __restrict__ emb, int M) {
    int row  = blockIdx.x * 8 + (threadIdx.x >> 5);
    int lane = threadIdx.x & 31;
    if (row >= M) return;
    const float4* u = reinterpret_cast<const float4*>(&g_U[(size_t)row * DD]);
    float4 v[6];
    float sq = 0.f;
#pragma unroll
    for (int i = 0; i < 6; ++i) {
        v[i] = u[lane + 32 * i];
        sq += v[i].x * v[i].x + v[i].y * v[i].y + v[i].z * v[i].z + v[i].w * v[i].w;
    }
#pragma unroll
    for (int o = 16; o; o >>= 1) sq += __shfl_xor_sync(0xffffffffu, sq, o);
    float inv = 1.f / fmaxf(sqrtf(sq), 1e-12f);
    float4* of = reinterpret_cast<float4*>(&emb[(size_t)row * DD]);
    uint2*  eh = reinterpret_cast<uint2*>(&g_Ehi[(size_t)row * DD]);
    uint2*  el = reinterpret_cast<uint2*>(&g_Elo[(size_t)row * DD]);
#pragma unroll
    for (int i = 0; i < 6; ++i) {
        float4 w = v[i];
        w.x *= inv; w.y *= inv; w.z *= inv; w.w *= inv;
        of[lane + 32 * i] = w;
        __nv_bfloat16 h0 = __float2bfloat16(w.x), h1 = __float2bfloat16(w.y);
        __nv_bfloat16 h2 = __float2bfloat16(w.z), h3 = __float2bfloat16(w.w);
        eh[lane + 32 * i] = make_uint2(pack2bf(w.x, w.y), pack2bf(w.z, w.w));
        el[lane + 32 * i] = make_uint2(
            pack2bf(w.x - __bfloat162float(h0), w.y - __bfloat162float(h1)),
            pack2bf(w.z - __bfloat162float(h2), w.w - __bfloat162float(h3)));
    }
}

// normalize support rows of g_Uh (fp16), scatter-add into g_proto[label]
__global__ __launch_bounds__(256)
void norm_proto(const int* __restrict__ lab, int N) {
    int row  = blockIdx.x * 8 + (threadIdx.x >> 5);
    int lane = threadIdx.x & 31;
    if (row >= N) return;
    const uint4* u = reinterpret_cast<const uint4*>(&g_Uh[(size_t)row * DD]);
    float vv[24];
    float sq = 0.f;
#pragma unroll
    for (int i = 0; i < 3; ++i) {
        uint4 q = u[lane + 32 * i];              // 8 halves
        const uint32_t w[4] = {q.x, q.y, q.z, q.w};
#pragma unroll
        for (int j = 0; j < 4; ++j) {
            float2 f = __half22float2(*reinterpret_cast<const __half2*>(&w[j]));
            vv[i * 8 + 2 * j]     = f.x;
            vv[i * 8 + 2 * j + 1] = f.y;
            sq += f.x * f.x + f.y * f.y;
        }
    }
#pragma unroll
    for (int o = 16; o; o >>= 1) sq += __shfl_xor_sync(0xffffffffu, sq, o);
    float inv = 1.f / fmaxf(sqrtf(sq), 1e-12f);
    int lb = lab[row];
    float* dst = &g_proto[(size_t)lb * DD];
#pragma unroll
    for (int i = 0; i < 3; ++i) {
        int col = (lane + 32 * i) * 8;
#pragma unroll
        for (int t = 0; t < 2; ++t) {
            float a = vv[i * 8 + 4 * t]     * inv;
            float b = vv[i * 8 + 4 * t + 1] * inv;
            float c = vv[i * 8 + 4 * t + 2] * inv;
            float d = vv[i * 8 + 4 * t + 3] * inv;
            asm volatile("red.global.add.v4.f32 [%0], {%1,%2,%3,%4};"
                         :: "l"(dst + col + 4 * t), "f"(a), "f"(b), "f"(c), "f"(d)
                         : "memory");
        }
    }
}

// prototype sums -> normalized bf16 hi/lo (rows >= Cn stay zero-init)
__global__ void proto_norm_kernel(int Cn) {
    int c   = blockIdx.x;
    int tid = threadIdx.x;
    if (c >= Cn) return;
    const float* row = &g_proto[(size_t)c * DD];
    float ss = 0.f;
    for (int i = tid; i < DD; i += 256) { float v = row[i]; ss += v * v; }
    __shared__ float red[8];
#pragma unroll
    for (int o = 16; o; o >>= 1) ss += __shfl_xor_sync(0xffffffffu, ss, o);
    if ((tid & 31) == 0) red[tid >> 5] = ss;
    __syncthreads();
    if (tid < 8) {
        ss = red[tid];
#pragma unroll
        for (int o = 4; o; o >>= 1) ss += __shfl_xor_sync(0xffu, ss, o);
        if (tid == 0) red[0] = ss;
    }
    __syncthreads();
    float inv = (g_cnt[c] > 0.f) ? 1.f / fmaxf(sqrtf(red[0]), 1e-12f) : 0.f;
    for (int i = tid; i < DD; i += 256) {
        float v = row[i] * inv;
        __nv_bfloat16 h = __float2bfloat16(v);
        g_Phi[(size_t)c * DD + i] = h;
        g_Plo[(size_t)c * DD + i] = __float2bfloat16(v - __bfloat162float(h));
    }
}

// ---------------------------------------------------------------------------
__global__ void softmax_kernel(const float* __restrict__ L,
                               float* __restrict__ P, int Cn)
{
    __shared__ float buf[1024];
    __shared__ float red[8];
    int row = blockIdx.x, tid = threadIdx.x;
    const float* lr = L + (size_t)row * Cn;

    float mx = -1e30f;
    for (int i = tid; i < Cn; i += 256) { float v = lr[i]; buf[i] = v; mx = fmaxf(mx, v); }
#pragma unroll
    for (int o = 16; o; o >>= 1) mx = fmaxf(mx, __shfl_xor_sync(0xffffffffu, mx, o));
    if ((tid & 31) == 0) red[tid >> 5] = mx;
    __syncthreads();
    if (tid < 8) {
        mx = red[tid];
#pragma unroll
        for (int o = 4; o; o >>= 1) mx = fmaxf(mx, __shfl_xor_sync(0xffu, mx, o));
        if (tid == 0) red[0] = mx;
    }
    __syncthreads();
    mx = red[0];
    __syncthreads();

    float sm = 0.f;
    for (int i = tid; i < Cn; i += 256) { float e = expf(buf[i] - mx); buf[i] = e; sm += e; }
#pragma unroll
    for (int o = 16; o; o >>= 1) sm += __shfl_xor_sync(0xffffffffu, sm, o);
    if ((tid & 31) == 0) red[tid >> 5] = sm;
    __syncthreads();
    if (tid < 8) {
        sm = red[tid];
#pragma unroll
        for (int o = 4; o; o >>= 1) sm += __shfl_xor_sync(0xffu, sm, o);
        if (tid == 0) red[0] = sm;
    }
    __syncthreads();
    float inv = 1.f / red[0];
    for (int i = tid; i < Cn; i += 256)
        P[(size_t)row * Cn + i] = buf[i] * inv;
}

// ---------------------------------------------------------------------------
extern "C" void kernel_launch(void* const* d_in, const int* in_sizes, int n_in,
                              void* d_out, int out_size)
{
    const float* x   = (const float*)d_in[0];
    const float* sf  = (const float*)d_in[1];
    const int*   lab = (const int*)d_in[2];
    const float* W   = (const float*)d_in[3];
    const float* b   = (const float*)d_in[4];
    (void)n_in;

    const int D = in_sizes[4];               // 768
    const int B = in_sizes[0] / D;           // 8192
    const int N = in_sizes[2];               // 100000
    const long long C =
        ((long long)out_size - (long long)B * D) / (2LL * B);   // 1000

    float* predicts = (float*)d_out;
    float* logits   = predicts + (long long)B * C;
    float* emb      = logits + (long long)B * C;

    static __nv_bfloat16 *pAhi = nullptr, *pAlo = nullptr, *pWhi = nullptr, *pWlo = nullptr;
    static __nv_bfloat16 *pEhi = nullptr, *pElo = nullptr, *pPhi = nullptr, *pPlo = nullptr;
    static __nv_bfloat16 *pAh16 = nullptr, *pWh16 = nullptr;
    static bool init = false;
    if (!init) {
        cudaGetSymbolAddress((void**)&pAhi,  g_Ahi);
        cudaGetSymbolAddress((void**)&pAlo,  g_Alo);
        cudaGetSymbolAddress((void**)&pWhi,  g_Whi);
        cudaGetSymbolAddress((void**)&pWlo,  g_Wlo);
        cudaGetSymbolAddress((void**)&pEhi,  g_Ehi);
        cudaGetSymbolAddress((void**)&pElo,  g_Elo);
        cudaGetSymbolAddress((void**)&pPhi,  g_Phi);
        cudaGetSymbolAddress((void**)&pPlo,  g_Plo);
        cudaGetSymbolAddress((void**)&pAh16, g_Ah16);   // fp16 bits, bf16* type
        cudaGetSymbolAddress((void**)&pWh16, g_Wh16);
        cudaFuncSetAttribute((const void*)gemm_kernel<0, 3, false>,
                             cudaFuncAttributeMaxDynamicSharedMemorySize, Cfg<3>::SMEM);
        cudaFuncSetAttribute((const void*)gemm_kernel<0, 1, true>,
                             cudaFuncAttributeMaxDynamicSharedMemorySize, Cfg<1>::SMEM);
        cudaFuncSetAttribute((const void*)gemm_kernel<1, 3, false>,
                             cudaFuncAttributeMaxDynamicSharedMemorySize, Cfg<3>::SMEM);
        init = true;
    }

    zero_kernel<<<(CMAX * DD + 255) / 256, 256>>>();
    prep_w<<<(DD * DD + 255) / 256, 256>>>(W);
    {
        size_t tot = ((size_t)ROWS_PAD * DD) / 4;
        prep_x<<<(int)((tot + 255) / 256), 256>>>(x, sf, B, N);
    }
    // support adapter GEMM (rows 0..N-1 of g_Ah16): fp16 1-term, fp16 U, 2 CTA/SM
    {
        dim3 g(DD / 128, (N + 127) / 128);
        gemm_kernel<0, 1, true><<<g, 256, Cfg<1>::SMEM>>>(
            pAh16, nullptr, pWh16, nullptr, sf, b, nullptr, 0, N, 0, DD);
    }
    // emb adapter GEMM (rows 0..B-1): bf16 3-term, fp32 U
    {
        dim3 g(DD / 128, B / 128);
        gemm_kernel<0, 3, false><<<g, 256, Cfg<3>::SMEM>>>(
            pAhi, pAlo, pWhi, pWlo, x, b, nullptr, 0, B, 0, DD);
    }
    count_kernel<<<200, 256>>>(lab, N);
    norm_emb<<<(B + 7) / 8, 256>>>(emb, B);
    norm_proto<<<(N + 7) / 8, 256>>>(lab, N);
    proto_norm_kernel<<<(int)C, 256>>>((int)C);
    // cosine logits GEMM: emb (hi/lo) x proto (hi/lo), bf16 3-term
    {
        dim3 g(NPAD / 128, B / 128);
        gemm_kernel<1, 3, false><<<g, 256, Cfg<3>::SMEM>>>(
            pEhi, pElo, pPhi, pPlo, nullptr, nullptr, logits, 0, B, 0, (int)C);
    }
    softmax_kernel<<<B, 256>>>(logits, predicts, (int)C);
}

// round 12
// speedup vs baseline: 5.3328x; 1.0300x over previous
#include <cuda_runtime.h>
#include <cuda_bf16.h>
#include <cuda_fp16.h>
#include <math.h>
#include <stdint.h>

// ---------------------------------------------------------------------------
// UnifiedZipAdapterF round 12: R11 with the fill_part<1> B-tile bug fixed
// (each (tid,p) slot now issues BOTH its A chunk and its B chunk, as in R10).
//   - 3-term bf16 GEMMs (emb, cos): M=64 / warp 32x32 / 2 stages x 48KB
//     => 2 CTAs/SM
//   - softmax replaced by fused row exp-sum in cos epilogue + predicts pass
//   - support GEMM (fp16 1-term) identical to R10
// ---------------------------------------------------------------------------

#define DD        768
#define CMAX      1000
#define NPAD      1024
#define BMAX      8192
#define NSUP_PAD  100096     // ceil(100000/128)*128
#define ROWS_PAD  (BMAX + NSUP_PAD)

// ---- static device scratch (no allocations allowed) ----
__device__ __nv_bfloat16 g_Ahi[(size_t)BMAX * DD];      // emb rows bf16-hi
__device__ __nv_bfloat16 g_Alo[(size_t)BMAX * DD];      // emb rows bf16-lo
__device__ __half        g_Ah16[(size_t)NSUP_PAD * DD]; // support rows fp16
__device__ float         g_U[(size_t)BMAX * DD];        // emb-row adapter out (fp32)
__device__ __half        g_Uh[(size_t)NSUP_PAD * DD];   // support-row adapter out (fp16)
__device__ __nv_bfloat16 g_Whi[DD * DD];
__device__ __nv_bfloat16 g_Wlo[DD * DD];
__device__ __half        g_Wh16[DD * DD];
__device__ float         g_proto[CMAX * DD];
__device__ float         g_cnt[CMAX];
__device__ float         g_rowsum[BMAX];                // sum of exp(logit) per row
__device__ __nv_bfloat16 g_Ehi[(size_t)BMAX * DD];
__device__ __nv_bfloat16 g_Elo[(size_t)BMAX * DD];
__device__ __nv_bfloat16 g_Phi[(size_t)NPAD * DD];      // pad rows stay zero-init
__device__ __nv_bfloat16 g_Plo[(size_t)NPAD * DD];

// ---------------------------------------------------------------------------
__device__ __forceinline__ uint32_t s2u(const void* p) {
    uint32_t a;
    asm("{ .reg .u64 t; cvta.to.shared.u64 t, %1; cvt.u32.u64 %0, t; }"
        : "=r"(a) : "l"(p));
    return a;
}
__device__ __forceinline__ uint32_t pack2bf(float a, float b) {
    __nv_bfloat162 t = __floats2bfloat162_rn(a, b);
    return *reinterpret_cast<uint32_t*>(&t);
}
__device__ __forceinline__ uint32_t pack2h(float a, float b) {
    __half2 t = __floats2half2_rn(a, b);
    return *reinterpret_cast<uint32_t*>(&t);
}
__device__ __forceinline__ void cp16(uint32_t d, const void* s) {
    asm volatile("cp.async.cg.shared.global [%0], [%1], 16;" :: "r"(d), "l"(s));
}

#define LDSM_X4(R0, R1, R2, R3, ADDR)                                          \
    asm volatile("ldmatrix.sync.aligned.m8n8.x4.shared.b16 {%0,%1,%2,%3}, [%4];" \
        : "=r"(R0), "=r"(R1), "=r"(R2), "=r"(R3) : "r"(ADDR))
#define MMA_BF16(D, A, B)                                                      \
    asm volatile("mma.sync.aligned.m16n8k16.row.col.f32.bf16.bf16.f32 "        \
        "{%0,%1,%2,%3}, {%4,%5,%6,%7}, {%8,%9}, {%0,%1,%2,%3};"                \
        : "+f"((D)[0]), "+f"((D)[1]), "+f"((D)[2]), "+f"((D)[3])               \
        : "r"((A)[0]), "r"((A)[1]), "r"((A)[2]), "r"((A)[3]),                  \
          "r"((B)[0]), "r"((B)[1]))
#define MMA_F16(D, A, B)                                                       \
    asm volatile("mma.sync.aligned.m16n8k16.row.col.f32.f16.f16.f32 "          \
        "{%0,%1,%2,%3}, {%4,%5,%6,%7}, {%8,%9}, {%0,%1,%2,%3};"                \
        : "+f"((D)[0]), "+f"((D)[1]), "+f"((D)[2]), "+f"((D)[3])               \
        : "r"((A)[0]), "r"((A)[1]), "r"((A)[2]), "r"((A)[3]),                  \
          "r"((B)[0]), "r"((B)[1]))

// ---------------------------------------------------------------------------
// prep kernels
// ---------------------------------------------------------------------------
__global__ void zero_kernel() {
    int i = blockIdx.x * blockDim.x + threadIdx.x;
    if (i < CMAX * DD) g_proto[i] = 0.f;
    if (i < CMAX)      g_cnt[i]   = 0.f;
    if (i < BMAX)      g_rowsum[i] = 0.f;
}

__global__ void count_kernel(const int* __restrict__ lab, int N) {
    __shared__ int c[CMAX];
    int tid = threadIdx.x;
    for (int i = tid; i < CMAX; i += 256) c[i] = 0;
    __syncthreads();
    for (int i = blockIdx.x * 256 + tid; i < N; i += gridDim.x * 256)
        atomicAdd(&c[lab[i]], 1);
    __syncthreads();
    for (int i = tid; i < CMAX; i += 256)
        if (c[i]) atomicAdd(&g_cnt[i], (float)c[i]);
}

__global__ void prep_w(const float* __restrict__ W) {
    int i = blockIdx.x * blockDim.x + threadIdx.x;
    if (i < DD * DD) {
        float v = W[i];
        __nv_bfloat16 h = __float2bfloat16(v);
        g_Whi[i]  = h;
        g_Wlo[i]  = __float2bfloat16(v - __bfloat162float(h));
        g_Wh16[i] = __float2half(v);
    }
}

// emb rows -> g_Ahi/g_Alo (bf16 hi/lo); support rows (+pad) -> g_Ah16 (fp16)
__global__ void prep_x(const float* __restrict__ x, const float* __restrict__ sf,
                       int Brows, int Nrows) {
    size_t i = ((size_t)blockIdx.x * blockDim.x + threadIdx.x) * 4;
    if (i >= (size_t)ROWS_PAD * DD) return;
    size_t r = i / DD;
    if (r < (size_t)Brows) {
        float4 v = *reinterpret_cast<const float4*>(&x[i]);
        float vv[4] = {v.x, v.y, v.z, v.w};
        uint32_t hi[2], lo[2];
#pragma unroll
        for (int j = 0; j < 2; ++j) {
            float a0 = vv[2 * j], a1 = vv[2 * j + 1];
            __nv_bfloat16 h0 = __float2bfloat16(a0);
            __nv_bfloat16 h1 = __float2bfloat16(a1);
            hi[j] = pack2bf(a0, a1);
            lo[j] = pack2bf(a0 - __bfloat162float(h0), a1 - __bfloat162float(h1));
        }
        *reinterpret_cast<uint2*>(&g_Ahi[i]) = make_uint2(hi[0], hi[1]);
        *reinterpret_cast<uint2*>(&g_Alo[i]) = make_uint2(lo[0], lo[1]);
    } else {
        float4 v = make_float4(0.f, 0.f, 0.f, 0.f);
        if (r < (size_t)(Brows + Nrows))
            v = *reinterpret_cast<const float4*>(&sf[i - (size_t)Brows * DD]);
        size_t si = i - (size_t)Brows * DD;
        *reinterpret_cast<uint2*>(&g_Ah16[si]) =
            make_uint2(pack2h(v.x, v.y), pack2h(v.z, v.w));
    }
}

// ---------------------------------------------------------------------------
// GEMM cores.
// TERMS==1 (support, fp16): CTA 128x128, warp 64x32, 3 stages x 32KB, 2 CTA/SM.
// TERMS==3 (bf16 hi/lo):    CTA  64x128, warp 32x32, 2 stages x 48KB, 2 CTA/SM.
// ---------------------------------------------------------------------------
template <int TERMS>
struct Cfg {
    static const int MT    = (TERMS == 1) ? 128 : 64;
    static const int STAGE = (TERMS == 1) ? 32768 : 49152;
    static const int NS    = (TERMS == 1) ? 3 : 2;
    static const int SMEM  = NS * STAGE;                    // 96KB both
    static const int MINB  = 2;
};

template <int TERMS>
__device__ __forceinline__ void fill_part(
    const __nv_bfloat16* __restrict__ Ah, const __nv_bfloat16* __restrict__ Al,
    const __nv_bfloat16* __restrict__ Bh, const __nv_bfloat16* __restrict__ Bl,
    int arow0, int brow0, int kb, uint32_t sbase, int tid, int p)
{
    if (TERMS == 1) {
        // 1024 (tid,p) slots; each issues its A chunk AND its B chunk (R10 style)
        int ch = tid + p * 256;          // 0..1023
        int r = ch >> 3, c = ch & 7;
        uint32_t off = (uint32_t)(r * 128 + ((c ^ (r & 7)) << 4));
        cp16(sbase + off,          Ah + (size_t)(arow0 + r) * DD + kb + c * 8);
        cp16(sbase + 16384 + off,  Bh + (size_t)(brow0 + r) * DD + kb + c * 8);
    } else {
        // 3072 chunks: [Ahi 512][Alo 512][Bhi 1024][Blo 1024]; 3 per thread/part
#pragma unroll
        for (int k = 0; k < 3; ++k) {
            int id = p * 768 + k * 256 + tid;
            if (id < 1024) {
                int a = id & 511;
                int r = a >> 3, c = a & 7;
                uint32_t off = (uint32_t)(r * 128 + ((c ^ (r & 7)) << 4));
                const __nv_bfloat16* src = (id < 512) ? Ah : Al;
                uint32_t dst = sbase + (id < 512 ? 0u : 8192u) + off;
                cp16(dst, src + (size_t)(arow0 + r) * DD + kb + c * 8);
            } else {
                int bidx = id - 1024;
                int bsel = bidx >> 10;               // 0: Bhi, 1: Blo
                int bloc = bidx & 1023;
                int r = bloc >> 3, c = bloc & 7;
                uint32_t off = (uint32_t)(r * 128 + ((c ^ (r & 7)) << 4));
                const __nv_bfloat16* src = bsel ? Bl : Bh;
                uint32_t dst = sbase + 16384u + (bsel ? 16384u : 0u) + off;
                cp16(dst, src + (size_t)(brow0 + r) * DD + kb + c * 8);
            }
        }
    }
}

template <int TERMS>
__device__ __forceinline__ void compute_k16(uint32_t sb, int kk, int wm, int wn,
                                            int lane, float (&acc)[4][4][4])
{
    const int t = lane >> 3, li = lane & 7;
    if (TERMS == 1) {
        const uint32_t aH = sb, bH = sb + 16384;
        uint32_t ah[4][4], bh[4][2];
#pragma unroll
        for (int mi = 0; mi < 4; ++mi) {
            int r  = wm * 64 + mi * 16 + ((t & 1) << 3) + li;
            int cc = (kk << 1) + (t >> 1);
            uint32_t off = (uint32_t)(r * 128 + ((cc ^ (r & 7)) << 4));
            LDSM_X4(ah[mi][0], ah[mi][1], ah[mi][2], ah[mi][3], aH + off);
        }
#pragma unroll
        for (int p = 0; p < 2; ++p) {
            int n  = wn * 32 + p * 16 + ((t >> 1) << 3) + li;
            int cc = (kk << 1) + (t & 1);
            uint32_t off = (uint32_t)(n * 128 + ((cc ^ (n & 7)) << 4));
            LDSM_X4(bh[2 * p][0], bh[2 * p][1], bh[2 * p + 1][0], bh[2 * p + 1][1], bH + off);
        }
#pragma unroll
        for (int mi = 0; mi < 4; ++mi)
#pragma unroll
            for (int nj = 0; nj < 4; ++nj)
                MMA_F16(acc[mi][nj], ah[mi], bh[nj]);
    } else {
        const uint32_t aH = sb, aL = sb + 8192, bH = sb + 16384, bL = sb + 32768;
        uint32_t ah[2][4], al[2][4], bh[4][2], bl[4][2];
#pragma unroll
        for (int mi = 0; mi < 2; ++mi) {
            int r  = wm * 32 + mi * 16 + ((t & 1) << 3) + li;
            int cc = (kk << 1) + (t >> 1);
            uint32_t off = (uint32_t)(r * 128 + ((cc ^ (r & 7)) << 4));
            LDSM_X4(ah[mi][0], ah[mi][1], ah[mi][2], ah[mi][3], aH + off);
            LDSM_X4(al[mi][0], al[mi][1], al[mi][2], al[mi][3], aL + off);
        }
#pragma unroll
        for (int p = 0; p < 2; ++p) {
            int n  = wn * 32 + p * 16 + ((t >> 1) << 3) + li;
            int cc = (kk << 1) + (t & 1);
            uint32_t off = (uint32_t)(n * 128 + ((cc ^ (n & 7)) << 4));
            LDSM_X4(bh[2 * p][0], bh[2 * p][1], bh[2 * p + 1][0], bh[2 * p + 1][1], bH + off);
            LDSM_X4(bl[2 * p][0], bl[2 * p][1], bl[2 * p + 1][0], bl[2 * p + 1][1], bL + off);
        }
#pragma unroll
        for (int mi = 0; mi < 2; ++mi)
#pragma unroll
            for (int nj = 0; nj < 4; ++nj)
                MMA_BF16(acc[mi][nj], ah[mi], bh[nj]);
#pragma unroll
        for (int mi = 0; mi < 2; ++mi)
#pragma unroll
            for (int nj = 0; nj < 4; ++nj)
                MMA_BF16(acc[mi][nj], ah[mi], bl[nj]);
#pragma unroll
        for (int mi = 0; mi < 2; ++mi)
#pragma unroll
            for (int nj = 0; nj < 4; ++nj)
                MMA_BF16(acc[mi][nj], al[mi], bh[nj]);
    }
}

// EPI 0: adapter (bias+silu+residual -> U fp32 or fp16)
// EPI 1: cosine logits (exp(32c-32)/tau -> Lout, + row exp-sum atomics)
template <int EPI, int TERMS, bool HALF_U>
__global__ __launch_bounds__(256, Cfg<TERMS>::MINB)
void gemm_kernel(const __nv_bfloat16* __restrict__ Ah, const __nv_bfloat16* __restrict__ Al,
                 const __nv_bfloat16* __restrict__ Bh, const __nv_bfloat16* __restrict__ Bl,
                 const float* __restrict__ Xres, const float* __restrict__ bias,
                 float* __restrict__ Lout,
                 int rowEnd, int Cn)
{
    const int NS    = Cfg<TERMS>::NS;
    const int STAGE = Cfg<TERMS>::STAGE;
    const int MT    = Cfg<TERMS>::MT;
    extern __shared__ __align__(16) char smem[];
    const int tid  = threadIdx.x;
    const int lane = tid & 31, wid = tid >> 5;
    const int wm = wid >> 2, wn = wid & 3;
    const int nb0   = blockIdx.x * 128;
    const int arow0 = blockIdx.y * MT;
    const uint32_t sb = s2u(smem);

    float acc[4][4][4] = {};

#pragma unroll
    for (int s = 0; s < NS - 1; ++s) {
#pragma unroll
        for (int p = 0; p < 4; ++p)
            fill_part<TERMS>(Ah, Al, Bh, Bl, arow0, nb0, s * 64, sb + s * STAGE, tid, p);
        asm volatile("cp.async.commit_group;");
    }

#pragma unroll 1
    for (int s = 0; s < 12; ++s) {
        asm volatile("cp.async.wait_group %0;" :: "n"(Cfg<TERMS>::NS - 2));
        __syncthreads();
        const uint32_t cs = sb + (s % NS) * STAGE;
        const uint32_t fs = sb + ((s + NS - 1) % NS) * STAGE;
        const int fkb = (s + NS - 1) * 64;
        const bool df = (s + NS - 1) < 12;
#pragma unroll
        for (int kk = 0; kk < 4; ++kk) {
            if (df) fill_part<TERMS>(Ah, Al, Bh, Bl, arow0, nb0, fkb, fs, tid, kk);
            compute_k16<TERMS>(cs, kk, wm, wn, lane, acc);
        }
        asm volatile("cp.async.commit_group;");   // empty group when !df
    }
    __syncthreads();

    // ---- stage accumulators through smem: es[MT][132] ----
    float* es = reinterpret_cast<float*>(smem);
    const int MI = (TERMS == 1) ? 4 : 2;
    const int WMS = (TERMS == 1) ? 64 : 32;
#pragma unroll
    for (int mi = 0; mi < MI; ++mi)
#pragma unroll
        for (int nj = 0; nj < 4; ++nj) {
            int r0 = wm * WMS + mi * 16 + (lane >> 2);
            int c0 = wn * 32 + nj * 8 + (lane & 3) * 2;
            es[r0 * 132 + c0]           = acc[mi][nj][0];
            es[r0 * 132 + c0 + 1]       = acc[mi][nj][1];
            es[(r0 + 8) * 132 + c0]     = acc[mi][nj][2];
            es[(r0 + 8) * 132 + c0 + 1] = acc[mi][nj][3];
        }
    __syncthreads();

    // thread -> (row, 1/(256/MT) slice of 128 cols)
    const int SPL  = 256 / MT;             // 2 (MT=128) or 4 (MT=64)
    const int CW   = 128 / SPL;            // 64 or 32 cols per thread
    const int row  = tid / SPL;
    const int part = tid % SPL;
    const int arow = arow0 + row;
    const bool valid = (arow < rowEnd);
    const float* er = es + row * 132 + part * CW;

    if (EPI == 0) {
        if (valid) {
            const float* xr = Xres + (size_t)arow * DD + nb0 + part * CW;
            const float* br = bias + nb0 + part * CW;
            float*  urf = HALF_U ? nullptr
                                 : (g_U + (size_t)arow * DD + nb0 + part * CW);
            __half* urh = HALF_U ? (g_Uh + (size_t)arow * DD + nb0 + part * CW)
                                 : nullptr;
#pragma unroll 4
            for (int j = 0; j < CW; j += 4) {
                float4 v  = *reinterpret_cast<const float4*>(er + j);
                float4 bb = *reinterpret_cast<const float4*>(br + j);
                float4 xv = *reinterpret_cast<const float4*>(xr + j);
                float h0 = v.x + bb.x, h1 = v.y + bb.y;
                float h2 = v.z + bb.z, h3 = v.w + bb.w;
                float4 o;
                o.x = h0 / (1.f + expf(-h0)) + xv.x;
                o.y = h1 / (1.f + expf(-h1)) + xv.y;
                o.z = h2 / (1.f + expf(-h2)) + xv.z;
                o.w = h3 / (1.f + expf(-h3)) + xv.w;
                if (HALF_U) {
                    uint2 pk = make_uint2(pack2h(o.x, o.y), pack2h(o.z, o.w));
                    *reinterpret_cast<uint2*>(urh + j) = pk;
                } else {
                    *reinterpret_cast<float4*>(urf + j) = o;
                }
            }
        }
    } else {
        float esum = 0.f;
        if (valid) {
            const float invtau = 1.0f / 0.11f;
            float* lr = Lout + (size_t)arow * Cn + nb0 + part * CW;
            int cbase = nb0 + part * CW;
#pragma unroll 4
            for (int j = 0; j < CW; ++j) {
                int c = cbase + j;
                if (c < Cn) {
                    float l = expf(32.f * er[j] - 32.f) * invtau;
                    lr[j] = l;
                    esum += expf(l);
                }
            }
        }
        // reduce the SPL threads of each row (adjacent lanes), one atomic/row
        esum += __shfl_xor_sync(0xffffffffu, esum, 1);
        if (SPL == 4) esum += __shfl_xor_sync(0xffffffffu, esum, 2);
        if (valid && part == 0) atomicAdd(&g_rowsum[arow], esum);
    }
}

// ---------------------------------------------------------------------------
// predicts = exp(logit) / rowsum   (softmax without max-subtraction; logits
// are bounded by 1/tau = 9.09 so exp cannot overflow)
__global__ void predicts_kernel(const float* __restrict__ L,
                                float* __restrict__ P, int Cn)
{
    size_t i = ((size_t)blockIdx.x * blockDim.x + threadIdx.x) * 4;
    if (i >= (size_t)BMAX * Cn) return;
    int row = (int)(i / Cn);
    float inv = 1.f / g_rowsum[row];
    float4 l = *reinterpret_cast<const float4*>(L + i);
    float4 o;
    o.x = expf(l.x) * inv;
    o.y = expf(l.y) * inv;
    o.z = expf(l.z) * inv;
    o.w = expf(l.w) * inv;
    *reinterpret_cast<float4*>(P + i) = o;
}

// ---------------------------------------------------------------------------
// normalize emb rows of g_U -> emb (fp32) + g_Ehi/g_Elo; sq computed here.
__global__ __launch_bounds__(256)
void norm_emb(float* __restrict__ emb, int M) {
    int row  = blockIdx.x * 8 + (threadIdx.x >> 5);
    int lane = threadIdx.x & 31;
    if (row >= M) return;
    const float4* u = reinterpret_cast<const float4*>(&g_U[(size_t)row * DD]);
    float4 v[6];
    float sq = 0.f;
#pragma unroll
    for (int i = 0; i < 6; ++i) {
        v[i] = u[lane + 32 * i];
        sq += v[i].x * v[i].x + v[i].y * v[i].y + v[i].z * v[i].z + v[i].w * v[i].w;
    }
#pragma unroll
    for (int o = 16; o; o >>= 1) sq += __shfl_xor_sync(0xffffffffu, sq, o);
    float inv = 1.f / fmaxf(sqrtf(sq), 1e-12f);
    float4* of = reinterpret_cast<float4*>(&emb[(size_t)row * DD]);
    uint2*  eh = reinterpret_cast<uint2*>(&g_Ehi[(size_t)row * DD]);
    uint2*  el = reinterpret_cast<uint2*>(&g_Elo[(size_t)row * DD]);
#pragma unroll
    for (int i = 0; i < 6; ++i) {
        float4 w = v[i];
        w.x *= inv; w.y *= inv; w.z *= inv; w.w *= inv;
        of[lane + 32 * i] = w;
        __nv_bfloat16 h0 = __float2bfloat16(w.x), h1 = __float2bfloat16(w.y);
        __nv_bfloat16 h2 = __float2bfloat16(w.z), h3 = __float2bfloat16(w.w);
        eh[lane + 32 * i] = make_uint2(pack2bf(w.x, w.y), pack2bf(w.z, w.w));
        el[lane + 32 * i] = make_uint2(
            pack2bf(w.x - __bfloat162float(h0), w.y - __bfloat162float(h1)),
            pack2bf(w.z - __bfloat162float(h2), w.w - __bfloat162float(h3)));
    }
}

// normalize support rows of g_Uh (fp16), scatter-add into g_proto[label]
__global__ __launch_bounds__(256)
void norm_proto(const int* __restrict__ lab, int N) {
    int row  = blockIdx.x * 8 + (threadIdx.x >> 5);
    int lane = threadIdx.x & 31;
    if (row >= N) return;
    const uint4* u = reinterpret_cast<const uint4*>(&g_Uh[(size_t)row * DD]);
    float vv[24];
    float sq = 0.f;
#pragma unroll
    for (int i = 0; i < 3; ++i) {
        uint4 q = u[lane + 32 * i];              // 8 halves
        const uint32_t w[4] = {q.x, q.y, q.z, q.w};
#pragma unroll
        for (int j = 0; j < 4; ++j) {
            float2 f = __half22float2(*reinterpret_cast<const __half2*>(&w[j]));
            vv[i * 8 + 2 * j]     = f.x;
            vv[i * 8 + 2 * j + 1] = f.y;
            sq += f.x * f.x + f.y * f.y;
        }
    }
#pragma unroll
    for (int o = 16; o; o >>= 1) sq += __shfl_xor_sync(0xffffffffu, sq, o);
    float inv = 1.f / fmaxf(sqrtf(sq), 1e-12f);
    int lb = lab[row];
    float* dst = &g_proto[(size_t)lb * DD];
#pragma unroll
    for (int i = 0; i < 3; ++i) {
        int col = (lane + 32 * i) * 8;
#pragma unroll
        for (int t = 0; t < 2; ++t) {
            float a = vv[i * 8 + 4 * t]     * inv;
            float b = vv[i * 8 + 4 * t + 1] * inv;
            float c = vv[i * 8 + 4 * t + 2] * inv;
            float d = vv[i * 8 + 4 * t + 3] * inv;
            asm volatile("red.global.add.v4.f32 [%0], {%1,%2,%3,%4};"
                         :: "l"(dst + col + 4 * t), "f"(a), "f"(b), "f"(c), "f"(d)
                         : "memory");
        }
    }
}

// prototype sums -> normalized bf16 hi/lo (rows >= Cn stay zero-init)
__global__ void proto_norm_kernel(int Cn) {
    int c   = blockIdx.x;
    int tid = threadIdx.x;
    if (c >= Cn) return;
    const float* row = &g_proto[(size_t)c * DD];
    float ss = 0.f;
    for (int i = tid; i < DD; i += 256) { float v = row[i]; ss += v * v; }
    __shared__ float red[8];
#pragma unroll
    for (int o = 16; o; o >>= 1) ss += __shfl_xor_sync(0xffffffffu, ss, o);
    if ((tid & 31) == 0) red[tid >> 5] = ss;
    __syncthreads();
    if (tid < 8) {
        ss = red[tid];
#pragma unroll
        for (int o = 4; o; o >>= 1) ss += __shfl_xor_sync(0xffu, ss, o);
        if (tid == 0) red[0] = ss;
    }
    __syncthreads();
    float inv = (g_cnt[c] > 0.f) ? 1.f / fmaxf(sqrtf(red[0]), 1e-12f) : 0.f;
    for (int i = tid; i < DD; i += 256) {
        float v = row[i] * inv;
        __nv_bfloat16 h = __float2bfloat16(v);
        g_Phi[(size_t)c * DD + i] = h;
        g_Plo[(size_t)c * DD + i] = __float2bfloat16(v - __bfloat162float(h));
    }
}

// ---------------------------------------------------------------------------
extern "C" void kernel_launch(void* const* d_in, const int* in_sizes, int n_in,
                              void* d_out, int out_size)
{
    const float* x   = (const float*)d_in[0];
    const float* sf  = (const float*)d_in[1];
    const int*   lab = (const int*)d_in[2];
    const float* W   = (const float*)d_in[3];
    const float* b   = (const float*)d_in[4];
    (void)n_in;

    const int D = in_sizes[4];               // 768
    const int B = in_sizes[0] / D;           // 8192
    const int N = in_sizes[2];               // 100000
    const long long C =
        ((long long)out_size - (long long)B * D) / (2LL * B);   // 1000

    float* predicts = (float*)d_out;
    float* logits   = predicts + (long long)B * C;
    float* emb      = logits + (long long)B * C;

    static __nv_bfloat16 *pAhi = nullptr, *pAlo = nullptr, *pWhi = nullptr, *pWlo = nullptr;
    static __nv_bfloat16 *pEhi = nullptr, *pElo = nullptr, *pPhi = nullptr, *pPlo = nullptr;
    static __nv_bfloat16 *pAh16 = nullptr, *pWh16 = nullptr;
    static bool init = false;
    if (!init) {
        cudaGetSymbolAddress((void**)&pAhi,  g_Ahi);
        cudaGetSymbolAddress((void**)&pAlo,  g_Alo);
        cudaGetSymbolAddress((void**)&pWhi,  g_Whi);
        cudaGetSymbolAddress((void**)&pWlo,  g_Wlo);
        cudaGetSymbolAddress((void**)&pEhi,  g_Ehi);
        cudaGetSymbolAddress((void**)&pElo,  g_Elo);
        cudaGetSymbolAddress((void**)&pPhi,  g_Phi);
        cudaGetSymbolAddress((void**)&pPlo,  g_Plo);
        cudaGetSymbolAddress((void**)&pAh16, g_Ah16);   // fp16 bits, bf16* type
        cudaGetSymbolAddress((void**)&pWh16, g_Wh16);
        cudaFuncSetAttribute((const void*)gemm_kernel<0, 3, false>,
                             cudaFuncAttributeMaxDynamicSharedMemorySize, Cfg<3>::SMEM);
        cudaFuncSetAttribute((const void*)gemm_kernel<0, 1, true>,
                             cudaFuncAttributeMaxDynamicSharedMemorySize, Cfg<1>::SMEM);
        cudaFuncSetAttribute((const void*)gemm_kernel<1, 3, false>,
                             cudaFuncAttributeMaxDynamicSharedMemorySize, Cfg<3>::SMEM);
        init = true;
    }

    zero_kernel<<<(CMAX * DD + 255) / 256, 256>>>();
    prep_w<<<(DD * DD + 255) / 256, 256>>>(W);
    {
        size_t tot = ((size_t)ROWS_PAD * DD) / 4;
        prep_x<<<(int)((tot + 255) / 256), 256>>>(x, sf, B, N);
    }
    // support adapter GEMM: fp16 1-term, fp16 U, 2 CTA/SM
    {
        dim3 g(DD / 128, (N + 127) / 128);
        gemm_kernel<0, 1, true><<<g, 256, Cfg<1>::SMEM>>>(
            pAh16, nullptr, pWh16, nullptr, sf, b, nullptr, N, DD);
    }
    // emb adapter GEMM: bf16 3-term, fp32 U, M-tile 64, 2 CTA/SM
    {
        dim3 g(DD / 128, B / 64);
        gemm_kernel<0, 3, false><<<g, 256, Cfg<3>::SMEM>>>(
            pAhi, pAlo, pWhi, pWlo, x, b, nullptr, B, DD);
    }
    count_kernel<<<200, 256>>>(lab, N);
    norm_emb<<<(B + 7) / 8, 256>>>(emb, B);
    norm_proto<<<(N + 7) / 8, 256>>>(lab, N);
    proto_norm_kernel<<<(int)C, 256>>>((int)C);
    // cosine logits GEMM: bf16 3-term, M-tile 64, 2 CTA/SM, fused row exp-sums
    {
        dim3 g(NPAD / 128, B / 64);
        gemm_kernel<1, 3, false><<<g, 256, Cfg<3>::SMEM>>>(
            pEhi, pElo, pPhi, pPlo, nullptr, nullptr, logits, B, (int)C);
    }
    predicts_kernel<<<(int)(((long long)B * C / 4 + 255) / 256), 256>>>(
        logits, predicts, (int)C);
}